// round 11
// baseline (speedup 1.0000x reference)
#include <cuda_runtime.h>
#include <cuda_bf16.h>
#include <math.h>

#define BB 64
#define CC 512
#define NN 1024
#define KK 8
#define DD 128
#define NSPLIT 8
#define N_ITERS 3

// ---------------- scratch (static device globals; no allocation) ----------------
__device__ float g_k[BB * NN * DD];
__device__ float g_v[BB * NN * DD];
__device__ float g_slots[BB * KK * DD];
__device__ float g_q[BB * KK * DD];
__device__ float g_upd[BB * NSPLIT * KK * DD];
__device__ float g_asum[BB * NSPLIT * KK];
__device__ float g_wihT[DD * 384];
__device__ float g_whhT[DD * 384];
__device__ int g_cnt[N_ITERS * BB];
__device__ __nv_bfloat16 g_Wph[DD * CC], g_Wpl[DD * CC];   // [d][c]
__device__ __nv_bfloat16 g_Wkh[DD * DD], g_Wkl[DD * DD];   // [d][j]
__device__ __nv_bfloat16 g_Wvh[DD * DD], g_Wvl[DD * DD];

__device__ __forceinline__ float sigf(float x) { return 1.0f / (1.0f + __expf(-x)); }
__device__ __forceinline__ float geluf(float x) { return 0.5f * x * (1.0f + erff(x * 0.70710678118654752f)); }

// ---------------- mma / ldmatrix / cp.async helpers ----------------
__device__ __forceinline__ unsigned smem_u32(const void* p) {
    unsigned a;
    asm("{ .reg .u64 tmp; cvta.to.shared.u64 tmp, %1; cvt.u32.u64 %0, tmp; }" : "=r"(a) : "l"(p));
    return a;
}
__device__ __forceinline__ void mma_bf16(float acc[4],
    unsigned a0, unsigned a1, unsigned a2, unsigned a3,
    unsigned b0, unsigned b1) {
    asm volatile(
        "mma.sync.aligned.m16n8k16.row.col.f32.bf16.bf16.f32 "
        "{%0,%1,%2,%3}, {%4,%5,%6,%7}, {%8,%9}, {%0,%1,%2,%3};"
        : "+f"(acc[0]), "+f"(acc[1]), "+f"(acc[2]), "+f"(acc[3])
        : "r"(a0), "r"(a1), "r"(a2), "r"(a3), "r"(b0), "r"(b1));
}
__device__ __forceinline__ void ldsm4(unsigned r[4], unsigned addr) {
    asm volatile("ldmatrix.sync.aligned.m8n8.x4.shared.b16 {%0,%1,%2,%3}, [%4];"
        : "=r"(r[0]), "=r"(r[1]), "=r"(r[2]), "=r"(r[3]) : "r"(addr));
}
#define CPA16(dst, src) asm volatile("cp.async.cg.shared.global [%0], [%1], 16;" :: "r"(dst), "l"(src))
#define CPA_COMMIT() asm volatile("cp.async.commit_group;" ::: "memory")
#define CPA_WAIT(n) asm volatile("cp.async.wait_group %0;" :: "n"(n) : "memory")

__device__ __forceinline__ void split2(float f0, float f1, unsigned& vh, unsigned& vl) {
    __nv_bfloat162 h = __floats2bfloat162_rn(f0, f1);
    float r0 = f0 - __bfloat162float(h.x);
    float r1 = f1 - __bfloat162float(h.y);
    __nv_bfloat162 l = __floats2bfloat162_rn(r0, r1);
    vh = *(unsigned*)&h; vl = *(unsigned*)&l;
}

// swizzled byte address within a tile: row r, 16B-granule g.
template<int S> __device__ __forceinline__ unsigned swaddr(int r, int g) {
    if (S == 64)  return (unsigned)(r * 64  + ((g ^ ((r >> 1) & 3)) << 4));
    if (S == 128) return (unsigned)(r * 128 + ((g ^ (r & 7)) << 4));
    return (unsigned)(r * 256 + ((g ^ (r & 7)) << 4));
}

// one k16 step for 32n x 64d warp tile, 3-mma bf16 split; SA/SB = tile row bytes.
template<int SA, int SB>
__device__ __forceinline__ void mma_k16t(float (*acc)[8][4],
    unsigned aH, unsigned aL, unsigned bH, unsigned bL,
    int nr, int d0, int lane, int kkA, int kkB) {
    int lr = lane & 15;
    int half = lane >> 4;
    int gA = half + (kkA >> 3);
    int gB = half + (kkB >> 3);
    unsigned bh[4][4], bl[4][4];
#pragma unroll
    for (int db = 0; db < 4; db++) {
        unsigned ro = swaddr<SB>(d0 + db * 16 + lr, gB);
        ldsm4(bh[db], bH + ro);
        ldsm4(bl[db], bL + ro);
    }
#pragma unroll
    for (int nb = 0; nb < 2; nb++) {
        unsigned ra = swaddr<SA>(nr + nb * 16 + lr, gA);
        unsigned ah[4], al[4];
        ldsm4(ah, aH + ra);
        ldsm4(al, aL + ra);
#pragma unroll
        for (int db = 0; db < 4; db++) {
#pragma unroll
            for (int g = 0; g < 2; g++) {
                float* a4 = acc[nb][db * 2 + g];
                mma_bf16(a4, ah[0], ah[1], ah[2], ah[3], bh[db][g], bh[db][g + 2]);
                mma_bf16(a4, ah[0], ah[1], ah[2], ah[3], bl[db][g], bl[db][g + 2]);
                mma_bf16(a4, al[0], al[1], al[2], al[3], bh[db][g], bh[db][g + 2]);
            }
        }
    }
}

// ---------------- kernel 0: fused prep (transpose+cnt | cvt_w | init+q) ----------------
#define SMEM_PREP (DD * DD * 4 + KK * (DD + 1) * 4)
__global__ __launch_bounds__(256) void k_prep(
    const float* __restrict__ W_ih, const float* __restrict__ W_hh,
    const float* __restrict__ Wp, const float* __restrict__ Wk, const float* __restrict__ Wv,
    const float* __restrict__ mu, const float* __restrict__ lsig,
    const float* __restrict__ noise,
    const float* __restrict__ Wq, const float* __restrict__ bq,
    const float* __restrict__ gsl, const float* __restrict__ bsl) {
    extern __shared__ float smf[];
    __shared__ float ta[32][33];
    __shared__ float tb[32][33];
    int blk = blockIdx.x;
    int t = threadIdx.x;
    int tx = t & 31, ty = t >> 5;

    if (blk < 48) {
        if (blk == 0 && t < N_ITERS * BB) g_cnt[t] = 0;
        int bx = blk % 12, by = blk / 12;
        int o0 = bx * 32, j0 = by * 32;
#pragma unroll
        for (int i = 0; i < 4; i++) {
            int o = o0 + ty + 8 * i;
            ta[ty + 8 * i][tx] = W_ih[(size_t)o * DD + j0 + tx];
            tb[ty + 8 * i][tx] = W_hh[(size_t)o * DD + j0 + tx];
        }
        __syncthreads();
#pragma unroll
        for (int i = 0; i < 4; i++) {
            int j = j0 + ty + 8 * i;
            g_wihT[(size_t)j * 384 + o0 + tx] = ta[tx][ty + 8 * i];
            g_whhT[(size_t)j * 384 + o0 + tx] = tb[tx][ty + 8 * i];
        }
    } else if (blk < 240) {
        int idx = blk - 48;
        int z = idx / 64, rem = idx % 64;
        int c0 = (rem % 16) * 32, d0 = (rem / 16) * 32;
        int Cdim = z == 0 ? CC : DD;
        if (c0 >= Cdim) return;
        const float* src = z == 0 ? Wp : (z == 1 ? Wk : Wv);
        __nv_bfloat16* dsth = z == 0 ? g_Wph : (z == 1 ? g_Wkh : g_Wvh);
        __nv_bfloat16* dstl = z == 0 ? g_Wpl : (z == 1 ? g_Wkl : g_Wvl);
#pragma unroll
        for (int i = 0; i < 4; i++)
            ta[ty + 8 * i][tx] = src[(size_t)(c0 + ty + 8 * i) * DD + d0 + tx];
        __syncthreads();
#pragma unroll
        for (int i = 0; i < 4; i++) {
            int d = d0 + ty + 8 * i;
            float f = ta[tx][ty + 8 * i];
            __nv_bfloat16 h = __float2bfloat16(f);
            __nv_bfloat16 l = __float2bfloat16(f - __bfloat162float(h));
            dsth[(size_t)d * Cdim + c0 + tx] = h;
            dstl[(size_t)d * Cdim + c0 + tx] = l;
        }
    } else {
        int b = blk - 240;
        float* Wqs = smf;
        float (*sl)[DD + 1] = (float (*)[DD + 1])(smf + DD * DD);
        const float SCALE = 0.08838834764831845f;
#pragma unroll
        for (int i = 0; i < 16; i++)
            ((float4*)Wqs)[t + i * 256] = ((const float4*)Wq)[t + i * 256];
        for (int i = t; i < KK * DD; i += 256) {
            float v = mu[i] + __expf(lsig[i]) * noise[(size_t)b * KK * DD + i];
            g_slots[(size_t)b * KK * DD + i] = v;
            sl[i >> 7][i & 127] = v;
        }
        __syncthreads();
        {
            int row = ty;
            float s = 0.f, s2 = 0.f, vr[4];
#pragma unroll
            for (int i = 0; i < 4; i++) {
                float val = sl[row][tx * 4 + i];
                vr[i] = val; s += val; s2 += val * val;
            }
#pragma unroll
            for (int off = 16; off; off >>= 1) {
                s += __shfl_xor_sync(0xffffffffu, s, off);
                s2 += __shfl_xor_sync(0xffffffffu, s2, off);
            }
            float m = s * (1.0f / 128.0f);
            float var = s2 * (1.0f / 128.0f) - m * m;
            float inv = rsqrtf(var + 1e-5f);
#pragma unroll
            for (int i = 0; i < 4; i++) {
                int d = tx * 4 + i;
                sl[row][d] = (vr[i] - m) * inv * gsl[d] + bsl[d];
            }
        }
        __syncthreads();
        int d = t & 127, rh = t >> 7;
        float acc[4] = {0.f, 0.f, 0.f, 0.f};
#pragma unroll 8
        for (int j = 0; j < DD; j++) {
            float w = Wqs[j * DD + d];
#pragma unroll
            for (int rr = 0; rr < 4; rr++) acc[rr] = fmaf(sl[rh * 4 + rr][j], w, acc[rr]);
        }
#pragma unroll
        for (int rr = 0; rr < 4; rr++)
            g_q[((size_t)b * KK + rh * 4 + rr) * DD + d] = (acc[rr] + bq[d]) * SCALE;
    }
}

// ---------------- kernel 1: proj + LN + k/v (x converted in-kernel) ----------------
#define XS_SZ 16896
#define SL_AH 16896
#define SL_AL 25088
#define SL_BH 33280
#define SL_BL 41472
#define SLOT 49664
#define AF_L 32768
#define BF_OFF 65536
#define BF_L 16384
#define SMEM_PROJ 99328

__device__ __forceinline__ void writeout(float (*acc)[8][4], float* out, const float* bias,
                                         int nr, int d0, int lane) {
#pragma unroll
    for (int nb = 0; nb < 2; nb++)
#pragma unroll
        for (int u = 0; u < 8; u++) {
            int row = nr + nb * 16 + (lane >> 2);
            int dc = d0 + u * 8 + (lane & 3) * 2;
            *(float2*)(out + (size_t)row * DD + dc) =
                make_float2(acc[nb][u][0] + bias[dc], acc[nb][u][1] + bias[dc + 1]);
            *(float2*)(out + (size_t)(row + 8) * DD + dc) =
                make_float2(acc[nb][u][2] + bias[dc], acc[nb][u][3] + bias[dc + 1]);
        }
}

__global__ __launch_bounds__(256, 2) void k_proj(
    const float* __restrict__ x,
    const float* __restrict__ bp,
    const float* __restrict__ gin, const float* __restrict__ bin,
    const float* __restrict__ bk, const float* __restrict__ bv) {
    extern __shared__ char sm[];
    __shared__ float bp_s[DD], gin_s[DD], bin_s[DD], bk_s[DD], bv_s[DD];
    __shared__ float mean_s[128], istd_s[128];
    __shared__ float ps[2][128], ps2[2][128];

    const int t = threadIdx.x, lane = t & 31, wid = t >> 5;
    const int warpX = wid >> 2, warpY = wid & 3;
    const int d0 = warpX * 64, nr = warpY * 32;
    const int b = blockIdx.y, n0 = blockIdx.x * 128;
    const unsigned smb = smem_u32(sm);

    if (t < DD) {
        bp_s[t] = bp[t]; gin_s[t] = gin[t]; bin_s[t] = bin[t];
        bk_s[t] = bk[t]; bv_s[t] = bv[t];
    }

    const float* xb = x + (size_t)b * CC * NN + n0;

    float acc[2][8][4];
#pragma unroll
    for (int nb = 0; nb < 2; nb++)
#pragma unroll
        for (int u = 0; u < 8; u++)
#pragma unroll
            for (int j = 0; j < 4; j++) acc[nb][u][j] = 0.f;

    auto stage1 = [&](int c, int sel) {
        unsigned base = smb + sel * SLOT;
        int c0 = c * 32;
#pragma unroll
        for (int it = 0; it < 4; it++) {
            int idx = t + it * 256;
            int row = idx >> 5, g = idx & 31;
            CPA16(base + row * 528 + g * 16, xb + (size_t)(c0 + row) * NN + g * 4);
        }
#pragma unroll
        for (int it = 0; it < 2; it++) {
            int idx = t + it * 256;
            int row = idx >> 2, g = idx & 3;
            unsigned so = swaddr<64>(row, g);
            size_t go = (size_t)row * CC + c0 + g * 8;
            CPA16(base + SL_BH + so, g_Wph + go);
            CPA16(base + SL_BL + so, g_Wpl + go);
        }
        CPA_COMMIT();
    };
    auto convert1 = [&](int sel) {
        char* sb = sm + sel * SLOT;
#pragma unroll
        for (int it = 0; it < 8; it++) {
            int idx = t + it * 256;
            int n = idx & 127, p = idx >> 7;
            float f0 = *(const float*)(sb + (2 * p) * 528 + n * 4);
            float f1 = *(const float*)(sb + (2 * p + 1) * 528 + n * 4);
            unsigned vh, vl; split2(f0, f1, vh, vl);
            unsigned off = swaddr<64>(n, p >> 2) + (p & 3) * 4;
            *(unsigned*)(sb + SL_AH + off) = vh;
            *(unsigned*)(sb + SL_AL + off) = vl;
        }
    };
    auto stageB = [&](const __nv_bfloat16* Wh, const __nv_bfloat16* Wl, int j0) {
#pragma unroll
        for (int it = 0; it < 4; it++) {
            int idx = t + it * 256;
            int row = idx >> 3, g = idx & 7;
            unsigned so = swaddr<128>(row, g);
            size_t go = (size_t)row * DD + j0 + g * 8;
            CPA16(smb + BF_OFF + so, Wh + go);
            CPA16(smb + BF_OFF + BF_L + so, Wl + go);
        }
        CPA_COMMIT();
    };

    // ---- phase 1 ----
    stage1(0, 0);
    stage1(1, 1);
#pragma unroll 1
    for (int c = 0; c < 16; c++) {
        CPA_WAIT(1);
        __syncthreads();
        int sel = c & 1;
        convert1(sel);
        __syncthreads();
        unsigned base = smb + sel * SLOT;
        mma_k16t<64, 64>(acc, base + SL_AH, base + SL_AL, base + SL_BH, base + SL_BL,
                         nr, d0, lane, 0, 0);
        mma_k16t<64, 64>(acc, base + SL_AH, base + SL_AL, base + SL_BH, base + SL_BL,
                         nr, d0, lane, 16, 16);
        __syncthreads();
        if (c + 2 < 16) stage1(c + 2, sel);
        else CPA_COMMIT();
    }
    stageB(g_Wkh, g_Wkl, 0);

    // ---- LN from accumulators ----
    {
        float rs[4] = {0.f, 0.f, 0.f, 0.f}, rs2[4] = {0.f, 0.f, 0.f, 0.f};
#pragma unroll
        for (int nb = 0; nb < 2; nb++)
#pragma unroll
            for (int u = 0; u < 8; u++) {
                int dc = d0 + u * 8 + (lane & 3) * 2;
                float v0 = acc[nb][u][0] + bp_s[dc];
                float v1 = acc[nb][u][1] + bp_s[dc + 1];
                float v2 = acc[nb][u][2] + bp_s[dc];
                float v3 = acc[nb][u][3] + bp_s[dc + 1];
                rs[nb * 2] += v0 + v1;       rs2[nb * 2] += v0 * v0 + v1 * v1;
                rs[nb * 2 + 1] += v2 + v3;   rs2[nb * 2 + 1] += v2 * v2 + v3 * v3;
            }
#pragma unroll
        for (int off = 1; off <= 2; off <<= 1)
#pragma unroll
            for (int i = 0; i < 4; i++) {
                rs[i] += __shfl_xor_sync(0xffffffffu, rs[i], off);
                rs2[i] += __shfl_xor_sync(0xffffffffu, rs2[i], off);
            }
        if ((lane & 3) == 0) {
#pragma unroll
            for (int i = 0; i < 4; i++) {
                int row = nr + (i >> 1) * 16 + (i & 1) * 8 + (lane >> 2);
                ps[warpX][row] = rs[i];
                ps2[warpX][row] = rs2[i];
            }
        }
    }
    __syncthreads();
    if (t < 128) {
        float s = ps[0][t] + ps[1][t];
        float s2 = ps2[0][t] + ps2[1][t];
        float m = s * (1.0f / 128.0f);
        float var = s2 * (1.0f / 128.0f) - m * m;
        mean_s[t] = m;
        istd_s[t] = rsqrtf(var + 1e-5f);
    }
    __syncthreads();

    // ---- write LN output as bf16 hi/lo into A-full ----
#pragma unroll
    for (int nb = 0; nb < 2; nb++)
#pragma unroll
        for (int u = 0; u < 8; u++) {
            int dc = d0 + u * 8 + (lane & 3) * 2;
            int r0 = nr + nb * 16 + (lane >> 2), r1 = r0 + 8;
            float m0 = mean_s[r0], i0 = istd_s[r0];
            float m1 = mean_s[r1], i1 = istd_s[r1];
            float f0 = (acc[nb][u][0] + bp_s[dc] - m0) * i0 * gin_s[dc] + bin_s[dc];
            float f1 = (acc[nb][u][1] + bp_s[dc + 1] - m0) * i0 * gin_s[dc + 1] + bin_s[dc + 1];
            float f2 = (acc[nb][u][2] + bp_s[dc] - m1) * i1 * gin_s[dc] + bin_s[dc];
            float f3 = (acc[nb][u][3] + bp_s[dc + 1] - m1) * i1 * gin_s[dc + 1] + bin_s[dc + 1];
            unsigned vh, vl;
            unsigned o0 = swaddr<256>(r0, dc >> 3) + (dc & 7) * 2;
            split2(f0, f1, vh, vl);
            *(unsigned*)(sm + o0) = vh;
            *(unsigned*)(sm + AF_L + o0) = vl;
            unsigned o1 = swaddr<256>(r1, dc >> 3) + (dc & 7) * 2;
            split2(f2, f3, vh, vl);
            *(unsigned*)(sm + o1) = vh;
            *(unsigned*)(sm + AF_L + o1) = vl;
        }
    __syncthreads();

    // ---- phases 2/3 ----
    unsigned aH = smb, aL = smb + AF_L, bH = smb + BF_OFF, bL = smb + BF_OFF + BF_L;
    float acc2[2][8][4];
#pragma unroll
    for (int nb = 0; nb < 2; nb++)
#pragma unroll
        for (int u = 0; u < 8; u++)
#pragma unroll
            for (int j = 0; j < 4; j++) acc2[nb][u][j] = 0.f;
    CPA_WAIT(0); __syncthreads();
#pragma unroll
    for (int kk = 0; kk < 64; kk += 16)
        mma_k16t<256, 128>(acc2, aH, aL, bH, bL, nr, d0, lane, kk, kk);
    __syncthreads();
    stageB(g_Wkh, g_Wkl, 64);
    CPA_WAIT(0); __syncthreads();
#pragma unroll
    for (int kk = 0; kk < 64; kk += 16)
        mma_k16t<256, 128>(acc2, aH, aL, bH, bL, nr, d0, lane, 64 + kk, kk);
    __syncthreads();
    stageB(g_Wvh, g_Wvl, 0);
    writeout(acc2, g_k + ((size_t)b * NN + n0) * DD, bk_s, nr, d0, lane);
#pragma unroll
    for (int nb = 0; nb < 2; nb++)
#pragma unroll
        for (int u = 0; u < 8; u++)
#pragma unroll
            for (int j = 0; j < 4; j++) acc2[nb][u][j] = 0.f;
    CPA_WAIT(0); __syncthreads();
#pragma unroll
    for (int kk = 0; kk < 64; kk += 16)
        mma_k16t<256, 128>(acc2, aH, aL, bH, bL, nr, d0, lane, kk, kk);
    __syncthreads();
    stageB(g_Wvh, g_Wvl, 64);
    CPA_WAIT(0); __syncthreads();
#pragma unroll
    for (int kk = 0; kk < 64; kk += 16)
        mma_k16t<256, 128>(acc2, aH, aL, bH, bL, nr, d0, lane, 64 + kk, kk);
    writeout(acc2, g_v + ((size_t)b * NN + n0) * DD, bv_s, nr, d0, lane);
}

// ---------------- kernel 2: fused attention + (last-block) update ----------------
// grid (NSPLIT, BB), 256 threads. Attention part identical to before; the block
// whose atomicAdd observes old==NSPLIT-1 runs the GRU/MLP/q update for its batch.
__global__ __launch_bounds__(256) void k_attn_update(
    const float* __restrict__ b_ih, const float* __restrict__ b_hh,
    const float* __restrict__ W1, const float* __restrict__ b1,
    const float* __restrict__ W2, const float* __restrict__ b2,
    const float* __restrict__ gm, const float* __restrict__ bm,
    const float* __restrict__ Wq, const float* __restrict__ bq,
    const float* __restrict__ gsl, const float* __restrict__ bsl,
    float* __restrict__ attn_out, float* __restrict__ slots_out,
    int it, int last) {
    __shared__ float buf[9280];
    __shared__ int winner_s;
    float (*updp)[KK * DD] = (float (*)[KK * DD])buf;     // [8][1024]
    float (*asums)[KK] = (float (*)[KK])(buf + 8192);     // [8][8]
    float (*atile)[KK][16] = (float (*)[KK][16])(buf + 8256);  // [8][8][16]

    int b = blockIdx.y, split = blockIdx.x;
    int t = threadIdx.x, lane = t & 31, w = t >> 5;
    int n0 = split * (NN / NSPLIT);
    int nb = n0 + w * 16;

    // ================= attention =================
    {
        const float* qp = g_q + (size_t)b * KK * DD + lane * 4;
        float qreg[KK][4];
#pragma unroll
        for (int s = 0; s < KK; s++) {
            float4 qv = *(const float4*)(qp + s * DD);
            qreg[s][0] = qv.x; qreg[s][1] = qv.y; qreg[s][2] = qv.z; qreg[s][3] = qv.w;
        }
        float upd[KK][4];
        float asum[KK];
#pragma unroll
        for (int s = 0; s < KK; s++) {
            asum[s] = 0.f;
#pragma unroll
            for (int j = 0; j < 4; j++) upd[s][j] = 0.f;
        }

        const float* kb = g_k + ((size_t)b * NN + nb) * DD + lane * 4;
        const float* vb = g_v + ((size_t)b * NN + nb) * DD + lane * 4;
        float4 kc = *(const float4*)kb;
        float4 vc = *(const float4*)vb;

#pragma unroll 4
        for (int i = 0; i < 16; i++) {
            float4 kn = kc, vn = vc;
            if (i < 15) {
                kn = *(const float4*)(kb + (i + 1) * DD);
                vn = *(const float4*)(vb + (i + 1) * DD);
            }
            float lg[KK];
#pragma unroll
            for (int s = 0; s < KK; s++)
                lg[s] = qreg[s][0] * kc.x + qreg[s][1] * kc.y + qreg[s][2] * kc.z + qreg[s][3] * kc.w;
#pragma unroll
            for (int off = 16; off; off >>= 1)
#pragma unroll
                for (int s = 0; s < KK; s++) lg[s] += __shfl_xor_sync(0xffffffffu, lg[s], off);
            float mx = lg[0];
#pragma unroll
            for (int s = 1; s < KK; s++) mx = fmaxf(mx, lg[s]);
            float ssum = 0.f;
#pragma unroll
            for (int s = 0; s < KK; s++) { lg[s] = __expf(lg[s] - mx); ssum += lg[s]; }
            float inv = 1.0f / ssum;
#pragma unroll
            for (int s = 0; s < KK; s++) {
                lg[s] *= inv;
                asum[s] += lg[s];
                upd[s][0] = fmaf(lg[s], vc.x, upd[s][0]);
                upd[s][1] = fmaf(lg[s], vc.y, upd[s][1]);
                upd[s][2] = fmaf(lg[s], vc.z, upd[s][2]);
                upd[s][3] = fmaf(lg[s], vc.w, upd[s][3]);
            }
            if (last && lane < 8) {
                float av = lane == 0 ? lg[0] : lane == 1 ? lg[1] : lane == 2 ? lg[2] :
                           lane == 3 ? lg[3] : lane == 4 ? lg[4] : lane == 5 ? lg[5] :
                           lane == 6 ? lg[6] : lg[7];
                atile[w][lane][i] = av;
            }
            kc = kn; vc = vn;
        }
#pragma unroll
        for (int s = 0; s < KK; s++)
            *(float4*)&updp[w][s * DD + lane * 4] =
                make_float4(upd[s][0], upd[s][1], upd[s][2], upd[s][3]);
        if (lane == 0) {
#pragma unroll
            for (int s = 0; s < KK; s++) asums[w][s] = asum[s];
        }
        __syncthreads();
        for (int idx = t; idx < KK * DD; idx += 256) {
            float s = 0.f;
#pragma unroll
            for (int ww = 0; ww < 8; ww++) s += updp[ww][idx];
            g_upd[((size_t)b * NSPLIT + split) * KK * DD + idx] = s;
        }
        if (t < KK) {
            float s = 0.f;
#pragma unroll
            for (int ww = 0; ww < 8; ww++) s += asums[ww][t];
            g_asum[((size_t)b * NSPLIT + split) * KK + t] = s;
        }
        if (last) {
            for (int idx = t; idx < KK * (NN / NSPLIT); idx += 256) {
                int s = idx >> 7, n = idx & 127;
                attn_out[((size_t)b * KK + s) * NN + n0 + n] = atile[n >> 4][s][n & 15];
            }
        }
    }

    // ================= last-block-wins handoff =================
    __threadfence();
    __syncthreads();
    if (t == 0) {
        int old = atomicAdd(&g_cnt[it * BB + b], 1);
        winner_s = (old == NSPLIT - 1) ? 1 : 0;
    }
    __syncthreads();
    if (!winner_s) return;

    // ================= update (256 threads, winner block) =================
    float* us = buf;                 // 1024
    float* hs = buf + 1024;          // 1024
    float* gxs = buf + 2048;         // 3072
    float* ghs = buf + 5120;         // 3072
    float* astot = buf + 8192;       // 8
    float* ns = us;
    float* lns = hs;
    float* h1s = gxs;
    float* fs = hs;
    float* lnq = ghs;
    int wid = w;

    if (t < KK) {
        float s = 0.f;
        for (int sp = 0; sp < NSPLIT; sp++) s += g_asum[((size_t)b * NSPLIT + sp) * KK + t];
        astot[t] = s + 1e-8f;
    }
#pragma unroll
    for (int i2 = t; i2 < KK * DD; i2 += 256) hs[i2] = g_slots[(size_t)b * KK * DD + i2];
    __syncthreads();
#pragma unroll
    for (int i2 = t; i2 < KK * DD; i2 += 256) {
        float s = 0.f;
#pragma unroll
        for (int sp = 0; sp < NSPLIT; sp++)
            s += g_upd[((size_t)b * NSPLIT + sp) * KK * DD + i2];
        us[i2] = s / astot[i2 >> 7];
    }
    __syncthreads();

    // GRU gates (8-chain ILP preserved)
    for (int o = t; o < 384; o += 256) {
        float accx[KK], acch[KK];
#pragma unroll
        for (int r = 0; r < KK; r++) { accx[r] = b_ih[o]; acch[r] = b_hh[o]; }
        const float* wi = g_wihT + o;
        const float* wh = g_whhT + o;
#pragma unroll 8
        for (int j = 0; j < DD; j++) {
            float wa = wi[(size_t)j * 384];
            float wb = wh[(size_t)j * 384];
#pragma unroll
            for (int r = 0; r < KK; r++) {
                accx[r] = fmaf(us[r * DD + j], wa, accx[r]);
                acch[r] = fmaf(hs[r * DD + j], wb, acch[r]);
            }
        }
#pragma unroll
        for (int r = 0; r < KK; r++) { gxs[r * 384 + o] = accx[r]; ghs[r * 384 + o] = acch[r]; }
    }
    __syncthreads();

    for (int idx = t; idx < KK * DD; idx += 256) {
        int r = idx >> 7, d = idx & 127;
        float xr = gxs[r * 384 + d],       hr = ghs[r * 384 + d];
        float xz = gxs[r * 384 + 128 + d], hz = ghs[r * 384 + 128 + d];
        float xn = gxs[r * 384 + 256 + d], hn = ghs[r * 384 + 256 + d];
        float rg = sigf(xr + hr);
        float zg = sigf(xz + hz);
        float ng = tanhf(xn + rg * hn);
        ns[idx] = (1.0f - zg) * ng + zg * hs[idx];
    }
    __syncthreads();

    {   // LN(ns): 8 warps, one row each
        int row = wid;
        float s = 0.f, s2 = 0.f, vr[4];
#pragma unroll
        for (int i = 0; i < 4; i++) {
            float val = ns[row * DD + lane * 4 + i];
            vr[i] = val; s += val; s2 += val * val;
        }
#pragma unroll
        for (int off = 16; off; off >>= 1) {
            s += __shfl_xor_sync(0xffffffffu, s, off);
            s2 += __shfl_xor_sync(0xffffffffu, s2, off);
        }
        float m = s * (1.0f / 128.0f);
        float var = s2 * (1.0f / 128.0f) - m * m;
        float inv = rsqrtf(var + 1e-5f);
#pragma unroll
        for (int i = 0; i < 4; i++) {
            int d = lane * 4 + i;
            lns[row * DD + d] = (vr[i] - m) * inv * gm[d] + bm[d];
        }
    }
    __syncthreads();

    {   // h1 = gelu(lns @ W1 + b1): 256 threads, 8 chains
        int o = t;
        float acc[KK];
#pragma unroll
        for (int r = 0; r < KK; r++) acc[r] = b1[o];
#pragma unroll 8
        for (int j = 0; j < DD; j++) {
            float w2 = W1[(size_t)j * 256 + o];
#pragma unroll
            for (int r = 0; r < KK; r++) acc[r] = fmaf(lns[r * DD + j], w2, acc[r]);
        }
#pragma unroll
        for (int r = 0; r < KK; r++) h1s[r * 256 + o] = geluf(acc[r]);
    }
    __syncthreads();

    {   // out = ns + h1 @ W2 + b2: 4 rows per thread-group
        int d = t & 127;
        int grp = t >> 7;   // 0..1, rows grp*4..grp*4+3
        float acc[4] = {0.f, 0.f, 0.f, 0.f};
#pragma unroll 8
        for (int j = 0; j < 256; j++) {
            float w2 = W2[(size_t)j * DD + d];
#pragma unroll
            for (int i = 0; i < 4; i++) acc[i] = fmaf(h1s[(grp * 4 + i) * 256 + j], w2, acc[i]);
        }
#pragma unroll
        for (int i = 0; i < 4; i++) {
            int r = grp * 4 + i;
            float val = ns[r * DD + d] + acc[i] + b2[d];
            g_slots[(size_t)b * KK * DD + r * DD + d] = val;
            fs[r * DD + d] = val;
            if (last) slots_out[(size_t)b * KK * DD + r * DD + d] = val;
        }
    }
    __syncthreads();

    if (!last) {
        const float SCALE = 0.08838834764831845f;
        {   // LN for q
            int row = wid;
            float s = 0.f, s2 = 0.f, vr[4];
#pragma unroll
            for (int i = 0; i < 4; i++) {
                float val = fs[row * DD + lane * 4 + i];
                vr[i] = val; s += val; s2 += val * val;
            }
#pragma unroll
            for (int off = 16; off; off >>= 1) {
                s += __shfl_xor_sync(0xffffffffu, s, off);
                s2 += __shfl_xor_sync(0xffffffffu, s2, off);
            }
            float m = s * (1.0f / 128.0f);
            float var = s2 * (1.0f / 128.0f) - m * m;
            float inv = rsqrtf(var + 1e-5f);
#pragma unroll
            for (int i = 0; i < 4; i++) {
                int d = lane * 4 + i;
                lnq[row * DD + d] = (vr[i] - m) * inv * gsl[d] + bsl[d];
            }
        }
        __syncthreads();
        int d = t & 127, grp = t >> 7;
        float a4[4] = {0.f, 0.f, 0.f, 0.f};
#pragma unroll 8
        for (int j = 0; j < DD; j++) {
            float w2 = Wq[(size_t)j * DD + d];
#pragma unroll
            for (int r = 0; r < 4; r++) a4[r] = fmaf(lnq[(grp * 4 + r) * DD + j], w2, a4[r]);
        }
#pragma unroll
        for (int r = 0; r < 4; r++)
            g_q[((size_t)b * KK + grp * 4 + r) * DD + d] = (a4[r] + bq[d]) * SCALE;
    }
}

// ---------------- launcher ----------------
extern "C" void kernel_launch(void* const* d_in, const int* in_sizes, int n_in,
                              void* d_out, int out_size) {
    const float* x       = (const float*)d_in[0];
    const float* noise   = (const float*)d_in[1];
    const float* slot_mu = (const float*)d_in[2];
    const float* slot_ls = (const float*)d_in[3];
    const float* Wp   = (const float*)d_in[4];
    const float* bp   = (const float*)d_in[5];
    const float* gin  = (const float*)d_in[6];
    const float* bin  = (const float*)d_in[7];
    const float* Wq   = (const float*)d_in[8];
    const float* bq   = (const float*)d_in[9];
    const float* Wk   = (const float*)d_in[10];
    const float* bk   = (const float*)d_in[11];
    const float* Wv   = (const float*)d_in[12];
    const float* bv   = (const float*)d_in[13];
    const float* W_ih = (const float*)d_in[14];
    const float* W_hh = (const float*)d_in[15];
    const float* b_ih = (const float*)d_in[16];
    const float* b_hh = (const float*)d_in[17];
    const float* W1   = (const float*)d_in[18];
    const float* b1   = (const float*)d_in[19];
    const float* W2   = (const float*)d_in[20];
    const float* b2   = (const float*)d_in[21];
    const float* gsl  = (const float*)d_in[22];
    const float* bsl  = (const float*)d_in[23];
    const float* gm   = (const float*)d_in[24];
    const float* bm   = (const float*)d_in[25];

    float* out_slots = (float*)d_out;
    float* out_attn  = out_slots + BB * KK * DD;

    cudaFuncSetAttribute(k_proj, cudaFuncAttributeMaxDynamicSharedMemorySize, SMEM_PROJ);
    cudaFuncSetAttribute(k_prep, cudaFuncAttributeMaxDynamicSharedMemorySize, SMEM_PREP);

    // launches: prep(0), proj(1), attn_update x3 (2,3,4) -> ncu slot 3 = 2nd fused kernel
    k_prep<<<304, 256, SMEM_PREP>>>(W_ih, W_hh, Wp, Wk, Wv,
                                    slot_mu, slot_ls, noise, Wq, bq, gsl, bsl);
    k_proj<<<dim3(NN / 128, BB), 256, SMEM_PROJ>>>(x, bp, gin, bin, bk, bv);

    for (int it = 0; it < N_ITERS; it++) {
        int last = (it == N_ITERS - 1);
        k_attn_update<<<dim3(NSPLIT, BB), 256>>>(b_ih, b_hh, W1, b1, W2, b2, gm, bm,
                                                 Wq, bq, gsl, bsl,
                                                 out_attn, out_slots, it, last);
    }
}

// round 12
// speedup vs baseline: 1.0460x; 1.0460x over previous
#include <cuda_runtime.h>
#include <cuda_bf16.h>
#include <math.h>

#define BB 64
#define CC 512
#define NN 1024
#define KK 8
#define DD 128
#define NSPLIT 8
#define N_ITERS 3

// ---------------- scratch (static device globals; no allocation) ----------------
__device__ float g_k[BB * NN * DD];
__device__ float g_v[BB * NN * DD];
__device__ float g_slots[BB * KK * DD];
__device__ float g_q[BB * KK * DD];
__device__ float g_upd[BB * NSPLIT * KK * DD];
__device__ float g_asum[BB * NSPLIT * KK];
__device__ float g_wihT[DD * 384];
__device__ float g_whhT[DD * 384];
__device__ __nv_bfloat16 g_Wph[DD * CC], g_Wpl[DD * CC];   // [d][c]
__device__ __nv_bfloat16 g_Wkh[DD * DD], g_Wkl[DD * DD];   // [d][j]
__device__ __nv_bfloat16 g_Wvh[DD * DD], g_Wvl[DD * DD];

__device__ __forceinline__ float sigf(float x) { return 1.0f / (1.0f + __expf(-x)); }
__device__ __forceinline__ float geluf(float x) { return 0.5f * x * (1.0f + erff(x * 0.70710678118654752f)); }

// ---------------- mma / ldmatrix / cp.async helpers ----------------
__device__ __forceinline__ unsigned smem_u32(const void* p) {
    unsigned a;
    asm("{ .reg .u64 tmp; cvta.to.shared.u64 tmp, %1; cvt.u32.u64 %0, tmp; }" : "=r"(a) : "l"(p));
    return a;
}
__device__ __forceinline__ void mma_bf16(float acc[4],
    unsigned a0, unsigned a1, unsigned a2, unsigned a3,
    unsigned b0, unsigned b1) {
    asm volatile(
        "mma.sync.aligned.m16n8k16.row.col.f32.bf16.bf16.f32 "
        "{%0,%1,%2,%3}, {%4,%5,%6,%7}, {%8,%9}, {%0,%1,%2,%3};"
        : "+f"(acc[0]), "+f"(acc[1]), "+f"(acc[2]), "+f"(acc[3])
        : "r"(a0), "r"(a1), "r"(a2), "r"(a3), "r"(b0), "r"(b1));
}
__device__ __forceinline__ void ldsm4(unsigned r[4], unsigned addr) {
    asm volatile("ldmatrix.sync.aligned.m8n8.x4.shared.b16 {%0,%1,%2,%3}, [%4];"
        : "=r"(r[0]), "=r"(r[1]), "=r"(r[2]), "=r"(r[3]) : "r"(addr));
}
#define CPA16(dst, src) asm volatile("cp.async.cg.shared.global [%0], [%1], 16;" :: "r"(dst), "l"(src))
#define CPA_COMMIT() asm volatile("cp.async.commit_group;" ::: "memory")
#define CPA_WAIT(n) asm volatile("cp.async.wait_group %0;" :: "n"(n) : "memory")

__device__ __forceinline__ void split2(float f0, float f1, unsigned& vh, unsigned& vl) {
    __nv_bfloat162 h = __floats2bfloat162_rn(f0, f1);
    float r0 = f0 - __bfloat162float(h.x);
    float r1 = f1 - __bfloat162float(h.y);
    __nv_bfloat162 l = __floats2bfloat162_rn(r0, r1);
    vh = *(unsigned*)&h; vl = *(unsigned*)&l;
}

// swizzled byte address within a tile: row r, 16B-granule g.
template<int S> __device__ __forceinline__ unsigned swaddr(int r, int g) {
    if (S == 64)  return (unsigned)(r * 64  + ((g ^ ((r >> 1) & 3)) << 4));
    if (S == 128) return (unsigned)(r * 128 + ((g ^ (r & 7)) << 4));
    return (unsigned)(r * 256 + ((g ^ (r & 7)) << 4));
}

// one k16 step for 32n x 64d warp tile, 3-mma bf16 split; SA/SB = tile row bytes.
template<int SA, int SB>
__device__ __forceinline__ void mma_k16t(float (*acc)[8][4],
    unsigned aH, unsigned aL, unsigned bH, unsigned bL,
    int nr, int d0, int lane, int kkA, int kkB) {
    int lr = lane & 15;
    int half = lane >> 4;
    int gA = half + (kkA >> 3);
    int gB = half + (kkB >> 3);
    unsigned bh[4][4], bl[4][4];
#pragma unroll
    for (int db = 0; db < 4; db++) {
        unsigned ro = swaddr<SB>(d0 + db * 16 + lr, gB);
        ldsm4(bh[db], bH + ro);
        ldsm4(bl[db], bL + ro);
    }
#pragma unroll
    for (int nb = 0; nb < 2; nb++) {
        unsigned ra = swaddr<SA>(nr + nb * 16 + lr, gA);
        unsigned ah[4], al[4];
        ldsm4(ah, aH + ra);
        ldsm4(al, aL + ra);
#pragma unroll
        for (int db = 0; db < 4; db++) {
#pragma unroll
            for (int g = 0; g < 2; g++) {
                float* a4 = acc[nb][db * 2 + g];
                mma_bf16(a4, ah[0], ah[1], ah[2], ah[3], bh[db][g], bh[db][g + 2]);
                mma_bf16(a4, ah[0], ah[1], ah[2], ah[3], bl[db][g], bl[db][g + 2]);
                mma_bf16(a4, al[0], al[1], al[2], al[3], bh[db][g], bh[db][g + 2]);
            }
        }
    }
}

// ---------------- kernel 0a: GRU weight transpose ----------------
__global__ __launch_bounds__(256) void k_prep_t(const float* __restrict__ W_ih,
                                                const float* __restrict__ W_hh) {
    __shared__ float ta[32][33];
    __shared__ float tb[32][33];
    int tx = threadIdx.x & 31, ty = threadIdx.x >> 5;
    int o0 = (blockIdx.x % 12) * 32, j0 = (blockIdx.x / 12) * 32;
#pragma unroll
    for (int i = 0; i < 4; i++) {
        int o = o0 + ty + 8 * i;
        ta[ty + 8 * i][tx] = W_ih[(size_t)o * DD + j0 + tx];
        tb[ty + 8 * i][tx] = W_hh[(size_t)o * DD + j0 + tx];
    }
    __syncthreads();
#pragma unroll
    for (int i = 0; i < 4; i++) {
        int j = j0 + ty + 8 * i;
        g_wihT[(size_t)j * 384 + o0 + tx] = ta[tx][ty + 8 * i];
        g_whhT[(size_t)j * 384 + o0 + tx] = tb[tx][ty + 8 * i];
    }
}

// ---------------- kernel 0b: convert+transpose proj weights ----------------
__global__ __launch_bounds__(256) void k_prep_w(const float* __restrict__ Wp,
                                                const float* __restrict__ Wk,
                                                const float* __restrict__ Wv) {
    __shared__ float ta[32][33];
    int idx = blockIdx.x;
    int z = idx / 64, rem = idx % 64;
    int c0 = (rem % 16) * 32, d0 = (rem / 16) * 32;
    int Cdim = z == 0 ? CC : DD;
    if (c0 >= Cdim) return;
    const float* src = z == 0 ? Wp : (z == 1 ? Wk : Wv);
    __nv_bfloat16* dsth = z == 0 ? g_Wph : (z == 1 ? g_Wkh : g_Wvh);
    __nv_bfloat16* dstl = z == 0 ? g_Wpl : (z == 1 ? g_Wkl : g_Wvl);
    int tx = threadIdx.x & 31, ty = threadIdx.x >> 5;
#pragma unroll
    for (int i = 0; i < 4; i++)
        ta[ty + 8 * i][tx] = src[(size_t)(c0 + ty + 8 * i) * DD + d0 + tx];
    __syncthreads();
#pragma unroll
    for (int i = 0; i < 4; i++) {
        int d = d0 + ty + 8 * i;
        float f = ta[tx][ty + 8 * i];
        __nv_bfloat16 h = __float2bfloat16(f);
        __nv_bfloat16 l = __float2bfloat16(f - __bfloat162float(h));
        dsth[(size_t)d * Cdim + c0 + tx] = h;
        dstl[(size_t)d * Cdim + c0 + tx] = l;
    }
}

// ---------------- kernel 0c: slots init + LN + first q ----------------
#define SMEM_QS (DD * DD * 4 + KK * (DD + 1) * 4)
__global__ __launch_bounds__(256) void k_prep_q(
    const float* __restrict__ mu, const float* __restrict__ lsig,
    const float* __restrict__ noise,
    const float* __restrict__ Wq, const float* __restrict__ bq,
    const float* __restrict__ gsl, const float* __restrict__ bsl) {
    extern __shared__ float smf[];
    float* Wqs = smf;
    float (*sl)[DD + 1] = (float (*)[DD + 1])(smf + DD * DD);
    const float SCALE = 0.08838834764831845f;
    int b = blockIdx.x, t = threadIdx.x, lane = t & 31, wid = t >> 5;
#pragma unroll
    for (int i = 0; i < 16; i++)
        ((float4*)Wqs)[t + i * 256] = ((const float4*)Wq)[t + i * 256];
    for (int i = t; i < KK * DD; i += 256) {
        float v = mu[i] + __expf(lsig[i]) * noise[(size_t)b * KK * DD + i];
        g_slots[(size_t)b * KK * DD + i] = v;
        sl[i >> 7][i & 127] = v;
    }
    __syncthreads();
    {
        int row = wid;
        float s = 0.f, s2 = 0.f, vr[4];
#pragma unroll
        for (int i = 0; i < 4; i++) {
            float val = sl[row][lane * 4 + i];
            vr[i] = val; s += val; s2 += val * val;
        }
#pragma unroll
        for (int off = 16; off; off >>= 1) {
            s += __shfl_xor_sync(0xffffffffu, s, off);
            s2 += __shfl_xor_sync(0xffffffffu, s2, off);
        }
        float m = s * (1.0f / 128.0f);
        float var = s2 * (1.0f / 128.0f) - m * m;
        float inv = rsqrtf(var + 1e-5f);
#pragma unroll
        for (int i = 0; i < 4; i++) {
            int d = lane * 4 + i;
            sl[row][d] = (vr[i] - m) * inv * gsl[d] + bsl[d];
        }
    }
    __syncthreads();
    int d = t & 127, rh = t >> 7;
    float acc[4] = {0.f, 0.f, 0.f, 0.f};
#pragma unroll 8
    for (int j = 0; j < DD; j++) {
        float w = Wqs[j * DD + d];
#pragma unroll
        for (int rr = 0; rr < 4; rr++) acc[rr] = fmaf(sl[rh * 4 + rr][j], w, acc[rr]);
    }
#pragma unroll
    for (int rr = 0; rr < 4; rr++)
        g_q[((size_t)b * KK + rh * 4 + rr) * DD + d] = (acc[rr] + bq[d]) * SCALE;
}

// ---------------- kernel 1: proj + LN + k/v (x converted in-kernel) ----------------
// ring slot (x2): XS fp32 [32c][132f] 16896B | AH 8K | AL 8K | BH 8K | BL 8K = 49664B
// phases 2/3 alias: A-full hi [0,32K), lo [32K,64K); BF at 65536 = 2 halves of 16K
// (each half: BH 8K + BL 8K, k32 tiles swz64), double-buffered pipeline.
#define XS_SZ 16896
#define SL_AH 16896
#define SL_AL 25088
#define SL_BH 33280
#define SL_BL 41472
#define SLOT 49664
#define AF_L 32768
#define BF_OFF 65536
#define BF_HALF 16384
#define SMEM_PROJ 99328

__device__ __forceinline__ void writeout(float (*acc)[8][4], float* out, const float* bias,
                                         int nr, int d0, int lane) {
#pragma unroll
    for (int nb = 0; nb < 2; nb++)
#pragma unroll
        for (int u = 0; u < 8; u++) {
            int row = nr + nb * 16 + (lane >> 2);
            int dc = d0 + u * 8 + (lane & 3) * 2;
            *(float2*)(out + (size_t)row * DD + dc) =
                make_float2(acc[nb][u][0] + bias[dc], acc[nb][u][1] + bias[dc + 1]);
            *(float2*)(out + (size_t)(row + 8) * DD + dc) =
                make_float2(acc[nb][u][2] + bias[dc], acc[nb][u][3] + bias[dc + 1]);
        }
}

__global__ __launch_bounds__(256, 2) void k_proj(
    const float* __restrict__ x,
    const float* __restrict__ bp,
    const float* __restrict__ gin, const float* __restrict__ bin,
    const float* __restrict__ bk, const float* __restrict__ bv) {
    extern __shared__ char sm[];
    __shared__ float bp_s[DD], gin_s[DD], bin_s[DD], bk_s[DD], bv_s[DD];
    __shared__ float mean_s[128], istd_s[128];
    __shared__ float ps[2][128], ps2[2][128];

    const int t = threadIdx.x, lane = t & 31, wid = t >> 5;
    const int warpX = wid >> 2, warpY = wid & 3;
    const int d0 = warpX * 64, nr = warpY * 32;
    const int b = blockIdx.y, n0 = blockIdx.x * 128;
    const unsigned smb = smem_u32(sm);

    if (t < DD) {
        bp_s[t] = bp[t]; gin_s[t] = gin[t]; bin_s[t] = bin[t];
        bk_s[t] = bk[t]; bv_s[t] = bv[t];
    }

    const float* xb = x + (size_t)b * CC * NN + n0;

    float acc[2][8][4];
#pragma unroll
    for (int nb = 0; nb < 2; nb++)
#pragma unroll
        for (int u = 0; u < 8; u++)
#pragma unroll
            for (int j = 0; j < 4; j++) acc[nb][u][j] = 0.f;

    auto stage1 = [&](int c, int sel) {
        unsigned base = smb + sel * SLOT;
        int c0 = c * 32;
#pragma unroll
        for (int it = 0; it < 4; it++) {
            int idx = t + it * 256;
            int row = idx >> 5, g = idx & 31;
            CPA16(base + row * 528 + g * 16, xb + (size_t)(c0 + row) * NN + g * 4);
        }
#pragma unroll
        for (int it = 0; it < 2; it++) {
            int idx = t + it * 256;
            int row = idx >> 2, g = idx & 3;
            unsigned so = swaddr<64>(row, g);
            size_t go = (size_t)row * CC + c0 + g * 8;
            CPA16(base + SL_BH + so, g_Wph + go);
            CPA16(base + SL_BL + so, g_Wpl + go);
        }
        CPA_COMMIT();
    };
    auto convert1 = [&](int sel) {
        char* sb = sm + sel * SLOT;
#pragma unroll
        for (int it = 0; it < 8; it++) {
            int idx = t + it * 256;
            int n = idx & 127, p = idx >> 7;
            float f0 = *(const float*)(sb + (2 * p) * 528 + n * 4);
            float f1 = *(const float*)(sb + (2 * p + 1) * 528 + n * 4);
            unsigned vh, vl; split2(f0, f1, vh, vl);
            unsigned off = swaddr<64>(n, p >> 2) + (p & 3) * 4;
            *(unsigned*)(sb + SL_AH + off) = vh;
            *(unsigned*)(sb + SL_AL + off) = vl;
        }
    };
    // stage one k32 weight chunk (hi+lo) into BF half
    auto stageB32 = [&](const __nv_bfloat16* Wh, const __nv_bfloat16* Wl, int j0, int half) {
        unsigned base = smb + BF_OFF + half * BF_HALF;
#pragma unroll
        for (int it = 0; it < 2; it++) {
            int idx = t + it * 256;               // 512 = 128 rows x 4 granules
            int row = idx >> 2, g = idx & 3;
            unsigned so = swaddr<64>(row, g);
            size_t go = (size_t)row * DD + j0 + g * 8;
            CPA16(base + so, Wh + go);
            CPA16(base + 8192 + so, Wl + go);
        }
        CPA_COMMIT();
    };

    // ---- phase 1 ----
    stage1(0, 0);
    stage1(1, 1);
#pragma unroll 1
    for (int c = 0; c < 16; c++) {
        CPA_WAIT(1);
        __syncthreads();
        int sel = c & 1;
        convert1(sel);
        __syncthreads();
        unsigned base = smb + sel * SLOT;
        mma_k16t<64, 64>(acc, base + SL_AH, base + SL_AL, base + SL_BH, base + SL_BL,
                         nr, d0, lane, 0, 0);
        mma_k16t<64, 64>(acc, base + SL_AH, base + SL_AL, base + SL_BH, base + SL_BL,
                         nr, d0, lane, 16, 16);
        __syncthreads();
        if (c + 2 < 16) stage1(c + 2, sel);
        else CPA_COMMIT();
    }
    // prefetch first two phase-2 weight chunks (overlaps LN epilogue)
    stageB32(g_Wkh, g_Wkl, 0, 0);
    stageB32(g_Wkh, g_Wkl, 32, 1);

    // ---- LN from accumulators ----
    {
        float rs[4] = {0.f, 0.f, 0.f, 0.f}, rs2[4] = {0.f, 0.f, 0.f, 0.f};
#pragma unroll
        for (int nb = 0; nb < 2; nb++)
#pragma unroll
            for (int u = 0; u < 8; u++) {
                int dc = d0 + u * 8 + (lane & 3) * 2;
                float v0 = acc[nb][u][0] + bp_s[dc];
                float v1 = acc[nb][u][1] + bp_s[dc + 1];
                float v2 = acc[nb][u][2] + bp_s[dc];
                float v3 = acc[nb][u][3] + bp_s[dc + 1];
                rs[nb * 2] += v0 + v1;       rs2[nb * 2] += v0 * v0 + v1 * v1;
                rs[nb * 2 + 1] += v2 + v3;   rs2[nb * 2 + 1] += v2 * v2 + v3 * v3;
            }
#pragma unroll
        for (int off = 1; off <= 2; off <<= 1)
#pragma unroll
            for (int i = 0; i < 4; i++) {
                rs[i] += __shfl_xor_sync(0xffffffffu, rs[i], off);
                rs2[i] += __shfl_xor_sync(0xffffffffu, rs2[i], off);
            }
        if ((lane & 3) == 0) {
#pragma unroll
            for (int i = 0; i < 4; i++) {
                int row = nr + (i >> 1) * 16 + (i & 1) * 8 + (lane >> 2);
                ps[warpX][row] = rs[i];
                ps2[warpX][row] = rs2[i];
            }
        }
    }
    __syncthreads();
    if (t < 128) {
        float s = ps[0][t] + ps[1][t];
        float s2 = ps2[0][t] + ps2[1][t];
        float m = s * (1.0f / 128.0f);
        float var = s2 * (1.0f / 128.0f) - m * m;
        mean_s[t] = m;
        istd_s[t] = rsqrtf(var + 1e-5f);
    }
    __syncthreads();

    // ---- write LN output as bf16 hi/lo into A-full ----
#pragma unroll
    for (int nb = 0; nb < 2; nb++)
#pragma unroll
        for (int u = 0; u < 8; u++) {
            int dc = d0 + u * 8 + (lane & 3) * 2;
            int r0 = nr + nb * 16 + (lane >> 2), r1 = r0 + 8;
            float m0 = mean_s[r0], i0 = istd_s[r0];
            float m1 = mean_s[r1], i1 = istd_s[r1];
            float f0 = (acc[nb][u][0] + bp_s[dc] - m0) * i0 * gin_s[dc] + bin_s[dc];
            float f1 = (acc[nb][u][1] + bp_s[dc + 1] - m0) * i0 * gin_s[dc + 1] + bin_s[dc + 1];
            float f2 = (acc[nb][u][2] + bp_s[dc] - m1) * i1 * gin_s[dc] + bin_s[dc];
            float f3 = (acc[nb][u][3] + bp_s[dc + 1] - m1) * i1 * gin_s[dc + 1] + bin_s[dc + 1];
            unsigned vh, vl;
            unsigned o0 = swaddr<256>(r0, dc >> 3) + (dc & 7) * 2;
            split2(f0, f1, vh, vl);
            *(unsigned*)(sm + o0) = vh;
            *(unsigned*)(sm + AF_L + o0) = vl;
            unsigned o1 = swaddr<256>(r1, dc >> 3) + (dc & 7) * 2;
            split2(f2, f3, vh, vl);
            *(unsigned*)(sm + o1) = vh;
            *(unsigned*)(sm + AF_L + o1) = vl;
        }
    __syncthreads();

    // ---- phases 2/3: pipelined k32 weight chunks (j=0..3 -> k, 4..7 -> v) ----
    unsigned aH = smb, aL = smb + AF_L;
    float acc2[2][8][4];
#pragma unroll
    for (int nb = 0; nb < 2; nb++)
#pragma unroll
        for (int u = 0; u < 8; u++)
#pragma unroll
            for (int j = 0; j < 4; j++) acc2[nb][u][j] = 0.f;
#pragma unroll 1
    for (int j = 0; j < 8; j++) {
        CPA_WAIT(1);
        __syncthreads();
        int half = j & 1;
        unsigned bH = smb + BF_OFF + half * BF_HALF;
        unsigned bL = bH + 8192;
        int ka = (j & 3) * 32;
        mma_k16t<256, 64>(acc2, aH, aL, bH, bL, nr, d0, lane, ka, 0);
        mma_k16t<256, 64>(acc2, aH, aL, bH, bL, nr, d0, lane, ka + 16, 16);
        __syncthreads();
        int nx = j + 2;
        if (nx < 8) {
            if (nx < 4) stageB32(g_Wkh, g_Wkl, (nx & 3) * 32, half);
            else        stageB32(g_Wvh, g_Wvl, (nx & 3) * 32, half);
        } else CPA_COMMIT();
        if (j == 3) {
            writeout(acc2, g_k + ((size_t)b * NN + n0) * DD, bk_s, nr, d0, lane);
#pragma unroll
            for (int nb = 0; nb < 2; nb++)
#pragma unroll
                for (int u = 0; u < 8; u++)
#pragma unroll
                    for (int jj = 0; jj < 4; jj++) acc2[nb][u][jj] = 0.f;
        }
    }
    writeout(acc2, g_v + ((size_t)b * NN + n0) * DD, bv_s, nr, d0, lane);
}

// ---------------- kernel 2: attention ----------------
__global__ __launch_bounds__(256) void k_attn(float* __restrict__ attn_out, int write_attn) {
    __shared__ float updp[8][KK * DD];
    __shared__ float asums[8][KK];
    __shared__ float atile[8][KK][16];

    int b = blockIdx.y, split = blockIdx.x;
    int t = threadIdx.x, lane = t & 31, w = t >> 5;
    int n0 = split * (NN / NSPLIT);
    int nb = n0 + w * 16;

    const float* qp = g_q + (size_t)b * KK * DD + lane * 4;
    float qreg[KK][4];
#pragma unroll
    for (int s = 0; s < KK; s++) {
        float4 qv = *(const float4*)(qp + s * DD);
        qreg[s][0] = qv.x; qreg[s][1] = qv.y; qreg[s][2] = qv.z; qreg[s][3] = qv.w;
    }
    float upd[KK][4];
    float asum[KK];
#pragma unroll
    for (int s = 0; s < KK; s++) {
        asum[s] = 0.f;
#pragma unroll
        for (int j = 0; j < 4; j++) upd[s][j] = 0.f;
    }

    const float* kb = g_k + ((size_t)b * NN + nb) * DD + lane * 4;
    const float* vb = g_v + ((size_t)b * NN + nb) * DD + lane * 4;
    float4 kc = *(const float4*)kb;
    float4 vc = *(const float4*)vb;

#pragma unroll 4
    for (int i = 0; i < 16; i++) {
        float4 kn = kc, vn = vc;
        if (i < 15) {
            kn = *(const float4*)(kb + (i + 1) * DD);
            vn = *(const float4*)(vb + (i + 1) * DD);
        }
        float lg[KK];
#pragma unroll
        for (int s = 0; s < KK; s++)
            lg[s] = qreg[s][0] * kc.x + qreg[s][1] * kc.y + qreg[s][2] * kc.z + qreg[s][3] * kc.w;
#pragma unroll
        for (int off = 16; off; off >>= 1)
#pragma unroll
            for (int s = 0; s < KK; s++) lg[s] += __shfl_xor_sync(0xffffffffu, lg[s], off);
        float mx = lg[0];
#pragma unroll
        for (int s = 1; s < KK; s++) mx = fmaxf(mx, lg[s]);
        float ssum = 0.f;
#pragma unroll
        for (int s = 0; s < KK; s++) { lg[s] = __expf(lg[s] - mx); ssum += lg[s]; }
        float inv = 1.0f / ssum;
#pragma unroll
        for (int s = 0; s < KK; s++) {
            lg[s] *= inv;
            asum[s] += lg[s];
            upd[s][0] = fmaf(lg[s], vc.x, upd[s][0]);
            upd[s][1] = fmaf(lg[s], vc.y, upd[s][1]);
            upd[s][2] = fmaf(lg[s], vc.z, upd[s][2]);
            upd[s][3] = fmaf(lg[s], vc.w, upd[s][3]);
        }
        if (write_attn && lane < 8) {
            float av = lane == 0 ? lg[0] : lane == 1 ? lg[1] : lane == 2 ? lg[2] :
                       lane == 3 ? lg[3] : lane == 4 ? lg[4] : lane == 5 ? lg[5] :
                       lane == 6 ? lg[6] : lg[7];
            atile[w][lane][i] = av;
        }
        kc = kn; vc = vn;
    }
#pragma unroll
    for (int s = 0; s < KK; s++)
        *(float4*)&updp[w][s * DD + lane * 4] =
            make_float4(upd[s][0], upd[s][1], upd[s][2], upd[s][3]);
    if (lane == 0) {
#pragma unroll
        for (int s = 0; s < KK; s++) asums[w][s] = asum[s];
    }
    __syncthreads();
    for (int idx = t; idx < KK * DD; idx += 256) {
        float s = 0.f;
#pragma unroll
        for (int ww = 0; ww < 8; ww++) s += updp[ww][idx];
        g_upd[((size_t)b * NSPLIT + split) * KK * DD + idx] = s;
    }
    if (t < KK) {
        float s = 0.f;
#pragma unroll
        for (int ww = 0; ww < 8; ww++) s += asums[ww][t];
        g_asum[((size_t)b * NSPLIT + split) * KK + t] = s;
    }
    if (write_attn) {
        for (int idx = t; idx < KK * (NN / NSPLIT); idx += 256) {
            int s = idx >> 7, n = idx & 127;
            attn_out[((size_t)b * KK + s) * NN + n0 + n] = atile[n >> 4][s][n & 15];
        }
    }
}

// ---------------- kernel 3: updates + GRU + MLP + next-iter q ----------------
__global__ __launch_bounds__(512) void k_update(
    const float* __restrict__ b_ih, const float* __restrict__ b_hh,
    const float* __restrict__ W1, const float* __restrict__ b1,
    const float* __restrict__ W2, const float* __restrict__ b2,
    const float* __restrict__ gm, const float* __restrict__ bm,
    const float* __restrict__ Wq, const float* __restrict__ bq,
    const float* __restrict__ gsl, const float* __restrict__ bsl,
    float* __restrict__ slots_out, int last) {
    __shared__ float us[KK * DD];
    __shared__ float hs[KK * DD];
    __shared__ float gxs[KK * 384];
    __shared__ float ghs[KK * 384];
    __shared__ float astot[KK];
    float* ns = us;
    float* lns = hs;
    float* h1s = gxs;
    float* fs = hs;
    float* lnq = ghs;

    int b = blockIdx.x;
    int t = threadIdx.x;
    int wid = t >> 5, lane = t & 31;

    if (t < KK) {
        float s = 0.f;
        for (int sp = 0; sp < NSPLIT; sp++) s += g_asum[((size_t)b * NSPLIT + sp) * KK + t];
        astot[t] = s + 1e-8f;
    }
    for (int i = t; i < KK * DD; i += 512) hs[i] = g_slots[(size_t)b * KK * DD + i];
    __syncthreads();
    for (int i = t; i < KK * DD; i += 512) {
        float s = 0.f;
        for (int sp = 0; sp < NSPLIT; sp++)
            s += g_upd[((size_t)b * NSPLIT + sp) * KK * DD + i];
        us[i] = s / astot[i >> 7];
    }
    __syncthreads();

    if (t < 384) {
        int o = t;
        float accx[KK], acch[KK];
#pragma unroll
        for (int r = 0; r < KK; r++) { accx[r] = b_ih[o]; acch[r] = b_hh[o]; }
        const float* wi = g_wihT + o;
        const float* wh = g_whhT + o;
#pragma unroll 8
        for (int j = 0; j < DD; j++) {
            float wa = wi[(size_t)j * 384];
            float wb = wh[(size_t)j * 384];
#pragma unroll
            for (int r = 0; r < KK; r++) {
                accx[r] = fmaf(us[r * DD + j], wa, accx[r]);
                acch[r] = fmaf(hs[r * DD + j], wb, acch[r]);
            }
        }
#pragma unroll
        for (int r = 0; r < KK; r++) { gxs[r * 384 + o] = accx[r]; ghs[r * 384 + o] = acch[r]; }
    }
    __syncthreads();

    for (int idx = t; idx < KK * DD; idx += 512) {
        int r = idx >> 7, d = idx & 127;
        float xr = gxs[r * 384 + d],       hr = ghs[r * 384 + d];
        float xz = gxs[r * 384 + 128 + d], hz = ghs[r * 384 + 128 + d];
        float xn = gxs[r * 384 + 256 + d], hn = ghs[r * 384 + 256 + d];
        float rg = sigf(xr + hr);
        float zg = sigf(xz + hz);
        float ng = tanhf(xn + rg * hn);
        ns[idx] = (1.0f - zg) * ng + zg * hs[idx];
    }
    __syncthreads();

    if (wid < KK) {
        int row = wid;
        float s = 0.f, s2 = 0.f, vr[4];
#pragma unroll
        for (int i = 0; i < 4; i++) {
            float val = ns[row * DD + lane * 4 + i];
            vr[i] = val; s += val; s2 += val * val;
        }
#pragma unroll
        for (int off = 16; off; off >>= 1) {
            s += __shfl_xor_sync(0xffffffffu, s, off);
            s2 += __shfl_xor_sync(0xffffffffu, s2, off);
        }
        float m = s * (1.0f / 128.0f);
        float var = s2 * (1.0f / 128.0f) - m * m;
        float inv = rsqrtf(var + 1e-5f);
#pragma unroll
        for (int i = 0; i < 4; i++) {
            int d = lane * 4 + i;
            lns[row * DD + d] = (vr[i] - m) * inv * gm[d] + bm[d];
        }
    }
    __syncthreads();

    if (t < 256) {
        int o = t;
        float acc[KK];
#pragma unroll
        for (int r = 0; r < KK; r++) acc[r] = b1[o];
#pragma unroll 8
        for (int j = 0; j < DD; j++) {
            float w = W1[(size_t)j * 256 + o];
#pragma unroll
            for (int r = 0; r < KK; r++) acc[r] = fmaf(lns[r * DD + j], w, acc[r]);
        }
#pragma unroll
        for (int r = 0; r < KK; r++) h1s[r * 256 + o] = geluf(acc[r]);
    }
    __syncthreads();

    {
        int d = t & 127;
        int rg2 = t >> 7;
        float acc[2] = {0.f, 0.f};
#pragma unroll 8
        for (int j = 0; j < 256; j++) {
            float w = W2[(size_t)j * DD + d];
#pragma unroll
            for (int i = 0; i < 2; i++) acc[i] = fmaf(h1s[(rg2 * 2 + i) * 256 + j], w, acc[i]);
        }
#pragma unroll
        for (int i = 0; i < 2; i++) {
            int r = rg2 * 2 + i;
            float val = ns[r * DD + d] + acc[i] + b2[d];
            g_slots[(size_t)b * KK * DD + r * DD + d] = val;
            fs[r * DD + d] = val;
            if (last) slots_out[(size_t)b * KK * DD + r * DD + d] = val;
        }
    }
    __syncthreads();

    if (!last) {
        const float SCALE = 0.08838834764831845f;
        if (wid < KK) {
            int row = wid;
            float s = 0.f, s2 = 0.f, vr[4];
#pragma unroll
            for (int i = 0; i < 4; i++) {
                float val = fs[row * DD + lane * 4 + i];
                vr[i] = val; s += val; s2 += val * val;
            }
#pragma unroll
            for (int off = 16; off; off >>= 1) {
                s += __shfl_xor_sync(0xffffffffu, s, off);
                s2 += __shfl_xor_sync(0xffffffffu, s2, off);
            }
            float m = s * (1.0f / 128.0f);
            float var = s2 * (1.0f / 128.0f) - m * m;
            float inv = rsqrtf(var + 1e-5f);
#pragma unroll
            for (int i = 0; i < 4; i++) {
                int d = lane * 4 + i;
                lnq[row * DD + d] = (vr[i] - m) * inv * gsl[d] + bsl[d];
            }
        }
        __syncthreads();
        int d = t & 127, grp = t >> 7;
        float a0 = 0.f, a1 = 0.f;
#pragma unroll 8
        for (int j = 0; j < DD; j++) {
            float w = Wq[(size_t)j * DD + d];
            a0 = fmaf(lnq[(grp * 2) * DD + j], w, a0);
            a1 = fmaf(lnq[(grp * 2 + 1) * DD + j], w, a1);
        }
        g_q[((size_t)b * KK + grp * 2) * DD + d] = (a0 + bq[d]) * SCALE;
        g_q[((size_t)b * KK + grp * 2 + 1) * DD + d] = (a1 + bq[d]) * SCALE;
    }
}

// ---------------- launcher ----------------
extern "C" void kernel_launch(void* const* d_in, const int* in_sizes, int n_in,
                              void* d_out, int out_size) {
    const float* x       = (const float*)d_in[0];
    const float* noise   = (const float*)d_in[1];
    const float* slot_mu = (const float*)d_in[2];
    const float* slot_ls = (const float*)d_in[3];
    const float* Wp   = (const float*)d_in[4];
    const float* bp   = (const float*)d_in[5];
    const float* gin  = (const float*)d_in[6];
    const float* bin  = (const float*)d_in[7];
    const float* Wq   = (const float*)d_in[8];
    const float* bq   = (const float*)d_in[9];
    const float* Wk   = (const float*)d_in[10];
    const float* bk   = (const float*)d_in[11];
    const float* Wv   = (const float*)d_in[12];
    const float* bv   = (const float*)d_in[13];
    const float* W_ih = (const float*)d_in[14];
    const float* W_hh = (const float*)d_in[15];
    const float* b_ih = (const float*)d_in[16];
    const float* b_hh = (const float*)d_in[17];
    const float* W1   = (const float*)d_in[18];
    const float* b1   = (const float*)d_in[19];
    const float* W2   = (const float*)d_in[20];
    const float* b2   = (const float*)d_in[21];
    const float* gsl  = (const float*)d_in[22];
    const float* bsl  = (const float*)d_in[23];
    const float* gm   = (const float*)d_in[24];
    const float* bm   = (const float*)d_in[25];

    float* out_slots = (float*)d_out;
    float* out_attn  = out_slots + BB * KK * DD;

    cudaFuncSetAttribute(k_proj, cudaFuncAttributeMaxDynamicSharedMemorySize, SMEM_PROJ);
    cudaFuncSetAttribute(k_prep_q, cudaFuncAttributeMaxDynamicSharedMemorySize, SMEM_QS);

    // launch index 3 = k_proj (the slot ncu captures)
    k_prep_t<<<48, 256>>>(W_ih, W_hh);
    k_prep_w<<<192, 256>>>(Wp, Wk, Wv);
    k_prep_q<<<BB, 256, SMEM_QS>>>(slot_mu, slot_ls, noise, Wq, bq, gsl, bsl);
    k_proj<<<dim3(NN / 128, BB), 256, SMEM_PROJ>>>(x, bp, gin, bin, bk, bv);

    for (int it = 0; it < N_ITERS; it++) {
        int last = (it == N_ITERS - 1);
        k_attn<<<dim3(NSPLIT, BB), 256>>>(out_attn, last);
        k_update<<<BB, 512>>>(b_ih, b_hh, W1, b1, W2, b2, gm, bm,
                              Wq, bq, gsl, bsl, out_slots, last);
    }
}

// round 14
// speedup vs baseline: 1.0486x; 1.0025x over previous
#include <cuda_runtime.h>
#include <cuda_bf16.h>
#include <math.h>

#define BB 64
#define CC 512
#define NN 1024
#define KK 8
#define DD 128
#define NSPLIT 8
#define N_ITERS 3

// ---------------- scratch (static device globals; no allocation) ----------------
__device__ float g_k[BB * NN * DD];
__device__ float g_v[BB * NN * DD];
__device__ float g_slots[BB * KK * DD];
__device__ float g_q[BB * KK * DD];
__device__ float g_upd[BB * NSPLIT * KK * DD];
__device__ float g_asum[BB * NSPLIT * KK];
__device__ float g_wihT[DD * 384];
__device__ float g_whhT[DD * 384];
__device__ __nv_bfloat16 g_Wph[DD * CC], g_Wpl[DD * CC];   // [d][c]
__device__ __nv_bfloat16 g_Wkh[DD * DD], g_Wkl[DD * DD];   // [d][j]
__device__ __nv_bfloat16 g_Wvh[DD * DD], g_Wvl[DD * DD];

__device__ __forceinline__ float sigf(float x) { return 1.0f / (1.0f + __expf(-x)); }
__device__ __forceinline__ float geluf(float x) { return 0.5f * x * (1.0f + erff(x * 0.70710678118654752f)); }

// ---------------- mma / ldmatrix / cp.async helpers ----------------
__device__ __forceinline__ unsigned smem_u32(const void* p) {
    unsigned a;
    asm("{ .reg .u64 tmp; cvta.to.shared.u64 tmp, %1; cvt.u32.u64 %0, tmp; }" : "=r"(a) : "l"(p));
    return a;
}
__device__ __forceinline__ void mma_bf16(float acc[4],
    unsigned a0, unsigned a1, unsigned a2, unsigned a3,
    unsigned b0, unsigned b1) {
    asm volatile(
        "mma.sync.aligned.m16n8k16.row.col.f32.bf16.bf16.f32 "
        "{%0,%1,%2,%3}, {%4,%5,%6,%7}, {%8,%9}, {%0,%1,%2,%3};"
        : "+f"(acc[0]), "+f"(acc[1]), "+f"(acc[2]), "+f"(acc[3])
        : "r"(a0), "r"(a1), "r"(a2), "r"(a3), "r"(b0), "r"(b1));
}
__device__ __forceinline__ void ldsm4(unsigned r[4], unsigned addr) {
    asm volatile("ldmatrix.sync.aligned.m8n8.x4.shared.b16 {%0,%1,%2,%3}, [%4];"
        : "=r"(r[0]), "=r"(r[1]), "=r"(r[2]), "=r"(r[3]) : "r"(addr));
}
#define CPA16(dst, src) asm volatile("cp.async.cg.shared.global [%0], [%1], 16;" :: "r"(dst), "l"(src))
#define CPA_COMMIT() asm volatile("cp.async.commit_group;" ::: "memory")
#define CPA_WAIT(n) asm volatile("cp.async.wait_group %0;" :: "n"(n) : "memory")

// L2 residency-controlled accesses (createpolicy + cache_hint: width-agnostic)
__device__ __forceinline__ unsigned long long mk_policy() {
    unsigned long long pol;
    asm("createpolicy.fractional.L2::evict_last.b64 %0, 1.0;" : "=l"(pol));
    return pol;
}
__device__ __forceinline__ float4 ldg_el4(const float* p, unsigned long long pol) {
    float4 v;
    asm volatile("ld.global.nc.L2::cache_hint.v4.f32 {%0,%1,%2,%3}, [%4], %5;"
        : "=f"(v.x), "=f"(v.y), "=f"(v.z), "=f"(v.w) : "l"(p), "l"(pol));
    return v;
}
__device__ __forceinline__ void stg_el2(float* p, float a, float b, unsigned long long pol) {
    asm volatile("st.global.L2::cache_hint.v2.f32 [%0], {%1,%2}, %3;"
        :: "l"(p), "f"(a), "f"(b), "l"(pol));
}

__device__ __forceinline__ void split2(float f0, float f1, unsigned& vh, unsigned& vl) {
    __nv_bfloat162 h = __floats2bfloat162_rn(f0, f1);
    float r0 = f0 - __bfloat162float(h.x);
    float r1 = f1 - __bfloat162float(h.y);
    __nv_bfloat162 l = __floats2bfloat162_rn(r0, r1);
    vh = *(unsigned*)&h; vl = *(unsigned*)&l;
}

// swizzled byte address within a tile: row r, 16B-granule g.
template<int S> __device__ __forceinline__ unsigned swaddr(int r, int g) {
    if (S == 64)  return (unsigned)(r * 64  + ((g ^ ((r >> 1) & 3)) << 4));
    if (S == 128) return (unsigned)(r * 128 + ((g ^ (r & 7)) << 4));
    return (unsigned)(r * 256 + ((g ^ (r & 7)) << 4));
}

// one k16 step for 32n x 64d warp tile, 3-mma bf16 split; SA/SB = tile row bytes.
template<int SA, int SB>
__device__ __forceinline__ void mma_k16t(float (*acc)[8][4],
    unsigned aH, unsigned aL, unsigned bH, unsigned bL,
    int nr, int d0, int lane, int kkA, int kkB) {
    int lr = lane & 15;
    int half = lane >> 4;
    int gA = half + (kkA >> 3);
    int gB = half + (kkB >> 3);
    unsigned bh[4][4], bl[4][4];
#pragma unroll
    for (int db = 0; db < 4; db++) {
        unsigned ro = swaddr<SB>(d0 + db * 16 + lr, gB);
        ldsm4(bh[db], bH + ro);
        ldsm4(bl[db], bL + ro);
    }
#pragma unroll
    for (int nb = 0; nb < 2; nb++) {
        unsigned ra = swaddr<SA>(nr + nb * 16 + lr, gA);
        unsigned ah[4], al[4];
        ldsm4(ah, aH + ra);
        ldsm4(al, aL + ra);
#pragma unroll
        for (int db = 0; db < 4; db++) {
#pragma unroll
            for (int g = 0; g < 2; g++) {
                float* a4 = acc[nb][db * 2 + g];
                mma_bf16(a4, ah[0], ah[1], ah[2], ah[3], bh[db][g], bh[db][g + 2]);
                mma_bf16(a4, ah[0], ah[1], ah[2], ah[3], bl[db][g], bl[db][g + 2]);
                mma_bf16(a4, al[0], al[1], al[2], al[3], bh[db][g], bh[db][g + 2]);
            }
        }
    }
}

// ---------------- kernel 0a: GRU weight transpose ----------------
__global__ __launch_bounds__(256) void k_prep_t(const float* __restrict__ W_ih,
                                                const float* __restrict__ W_hh) {
    __shared__ float ta[32][33];
    __shared__ float tb[32][33];
    int tx = threadIdx.x & 31, ty = threadIdx.x >> 5;
    int o0 = (blockIdx.x % 12) * 32, j0 = (blockIdx.x / 12) * 32;
#pragma unroll
    for (int i = 0; i < 4; i++) {
        int o = o0 + ty + 8 * i;
        ta[ty + 8 * i][tx] = W_ih[(size_t)o * DD + j0 + tx];
        tb[ty + 8 * i][tx] = W_hh[(size_t)o * DD + j0 + tx];
    }
    __syncthreads();
#pragma unroll
    for (int i = 0; i < 4; i++) {
        int j = j0 + ty + 8 * i;
        g_wihT[(size_t)j * 384 + o0 + tx] = ta[tx][ty + 8 * i];
        g_whhT[(size_t)j * 384 + o0 + tx] = tb[tx][ty + 8 * i];
    }
}

// ---------------- kernel 0b: convert+transpose proj weights ----------------
__global__ __launch_bounds__(256) void k_prep_w(const float* __restrict__ Wp,
                                                const float* __restrict__ Wk,
                                                const float* __restrict__ Wv) {
    __shared__ float ta[32][33];
    int idx = blockIdx.x;
    int z = idx / 64, rem = idx % 64;
    int c0 = (rem % 16) * 32, d0 = (rem / 16) * 32;
    int Cdim = z == 0 ? CC : DD;
    if (c0 >= Cdim) return;
    const float* src = z == 0 ? Wp : (z == 1 ? Wk : Wv);
    __nv_bfloat16* dsth = z == 0 ? g_Wph : (z == 1 ? g_Wkh : g_Wvh);
    __nv_bfloat16* dstl = z == 0 ? g_Wpl : (z == 1 ? g_Wkl : g_Wvl);
    int tx = threadIdx.x & 31, ty = threadIdx.x >> 5;
#pragma unroll
    for (int i = 0; i < 4; i++)
        ta[ty + 8 * i][tx] = src[(size_t)(c0 + ty + 8 * i) * DD + d0 + tx];
    __syncthreads();
#pragma unroll
    for (int i = 0; i < 4; i++) {
        int d = d0 + ty + 8 * i;
        float f = ta[tx][ty + 8 * i];
        __nv_bfloat16 h = __float2bfloat16(f);
        __nv_bfloat16 l = __float2bfloat16(f - __bfloat162float(h));
        dsth[(size_t)d * Cdim + c0 + tx] = h;
        dstl[(size_t)d * Cdim + c0 + tx] = l;
    }
}

// ---------------- kernel 0c: slots init + LN + first q ----------------
#define SMEM_QS (DD * DD * 4 + KK * (DD + 1) * 4)
__global__ __launch_bounds__(256) void k_prep_q(
    const float* __restrict__ mu, const float* __restrict__ lsig,
    const float* __restrict__ noise,
    const float* __restrict__ Wq, const float* __restrict__ bq,
    const float* __restrict__ gsl, const float* __restrict__ bsl) {
    extern __shared__ float smf[];
    float* Wqs = smf;
    float (*sl)[DD + 1] = (float (*)[DD + 1])(smf + DD * DD);
    const float SCALE = 0.08838834764831845f;
    int b = blockIdx.x, t = threadIdx.x, lane = t & 31, wid = t >> 5;
#pragma unroll
    for (int i = 0; i < 16; i++)
        ((float4*)Wqs)[t + i * 256] = ((const float4*)Wq)[t + i * 256];
    for (int i = t; i < KK * DD; i += 256) {
        float v = mu[i] + __expf(lsig[i]) * noise[(size_t)b * KK * DD + i];
        g_slots[(size_t)b * KK * DD + i] = v;
        sl[i >> 7][i & 127] = v;
    }
    __syncthreads();
    {
        int row = wid;
        float s = 0.f, s2 = 0.f, vr[4];
#pragma unroll
        for (int i = 0; i < 4; i++) {
            float val = sl[row][lane * 4 + i];
            vr[i] = val; s += val; s2 += val * val;
        }
#pragma unroll
        for (int off = 16; off; off >>= 1) {
            s += __shfl_xor_sync(0xffffffffu, s, off);
            s2 += __shfl_xor_sync(0xffffffffu, s2, off);
        }
        float m = s * (1.0f / 128.0f);
        float var = s2 * (1.0f / 128.0f) - m * m;
        float inv = rsqrtf(var + 1e-5f);
#pragma unroll
        for (int i = 0; i < 4; i++) {
            int d = lane * 4 + i;
            sl[row][d] = (vr[i] - m) * inv * gsl[d] + bsl[d];
        }
    }
    __syncthreads();
    int d = t & 127, rh = t >> 7;
    float acc[4] = {0.f, 0.f, 0.f, 0.f};
#pragma unroll 8
    for (int j = 0; j < DD; j++) {
        float w = Wqs[j * DD + d];
#pragma unroll
        for (int rr = 0; rr < 4; rr++) acc[rr] = fmaf(sl[rh * 4 + rr][j], w, acc[rr]);
    }
#pragma unroll
    for (int rr = 0; rr < 4; rr++)
        g_q[((size_t)b * KK + rh * 4 + rr) * DD + d] = (acc[rr] + bq[d]) * SCALE;
}

// ---------------- kernel 1: proj + LN + k/v (x converted in-kernel) ----------------
#define XS_SZ 16896
#define SL_AH 16896
#define SL_AL 25088
#define SL_BH 33280
#define SL_BL 41472
#define SLOT 49664
#define AF_L 32768
#define BF_OFF 65536
#define BF_L 16384
#define SMEM_PROJ 99328

__device__ __forceinline__ void writeout(float (*acc)[8][4], float* out, const float* bias,
                                         int nr, int d0, int lane, unsigned long long pol) {
#pragma unroll
    for (int nb = 0; nb < 2; nb++)
#pragma unroll
        for (int u = 0; u < 8; u++) {
            int row = nr + nb * 16 + (lane >> 2);
            int dc = d0 + u * 8 + (lane & 3) * 2;
            stg_el2(out + (size_t)row * DD + dc,
                    acc[nb][u][0] + bias[dc], acc[nb][u][1] + bias[dc + 1], pol);
            stg_el2(out + (size_t)(row + 8) * DD + dc,
                    acc[nb][u][2] + bias[dc], acc[nb][u][3] + bias[dc + 1], pol);
        }
}

__global__ __launch_bounds__(256, 2) void k_proj(
    const float* __restrict__ x,
    const float* __restrict__ bp,
    const float* __restrict__ gin, const float* __restrict__ bin,
    const float* __restrict__ bk, const float* __restrict__ bv) {
    extern __shared__ char sm[];
    __shared__ float bp_s[DD], gin_s[DD], bin_s[DD], bk_s[DD], bv_s[DD];
    __shared__ float mean_s[128], istd_s[128];
    __shared__ float ps[2][128], ps2[2][128];

    const int t = threadIdx.x, lane = t & 31, wid = t >> 5;
    const int warpX = wid >> 2, warpY = wid & 3;
    const int d0 = warpX * 64, nr = warpY * 32;
    const int b = blockIdx.y, n0 = blockIdx.x * 128;
    const unsigned smb = smem_u32(sm);
    const unsigned long long pol = mk_policy();

    if (t < DD) {
        bp_s[t] = bp[t]; gin_s[t] = gin[t]; bin_s[t] = bin[t];
        bk_s[t] = bk[t]; bv_s[t] = bv[t];
    }

    const float* xb = x + (size_t)b * CC * NN + n0;

    float acc[2][8][4];
#pragma unroll
    for (int nb = 0; nb < 2; nb++)
#pragma unroll
        for (int u = 0; u < 8; u++)
#pragma unroll
            for (int j = 0; j < 4; j++) acc[nb][u][j] = 0.f;

    auto stage1 = [&](int c, int sel) {
        unsigned base = smb + sel * SLOT;
        int c0 = c * 32;
#pragma unroll
        for (int it = 0; it < 4; it++) {
            int idx = t + it * 256;
            int row = idx >> 5, g = idx & 31;
            CPA16(base + row * 528 + g * 16, xb + (size_t)(c0 + row) * NN + g * 4);
        }
#pragma unroll
        for (int it = 0; it < 2; it++) {
            int idx = t + it * 256;
            int row = idx >> 2, g = idx & 3;
            unsigned so = swaddr<64>(row, g);
            size_t go = (size_t)row * CC + c0 + g * 8;
            CPA16(base + SL_BH + so, g_Wph + go);
            CPA16(base + SL_BL + so, g_Wpl + go);
        }
        CPA_COMMIT();
    };
    auto convert1 = [&](int sel) {
        char* sb = sm + sel * SLOT;
#pragma unroll
        for (int it = 0; it < 8; it++) {
            int idx = t + it * 256;
            int n = idx & 127, p = idx >> 7;
            float f0 = *(const float*)(sb + (2 * p) * 528 + n * 4);
            float f1 = *(const float*)(sb + (2 * p + 1) * 528 + n * 4);
            unsigned vh, vl; split2(f0, f1, vh, vl);
            unsigned off = swaddr<64>(n, p >> 2) + (p & 3) * 4;
            *(unsigned*)(sb + SL_AH + off) = vh;
            *(unsigned*)(sb + SL_AL + off) = vl;
        }
    };
    auto stageB = [&](const __nv_bfloat16* Wh, const __nv_bfloat16* Wl, int j0) {
#pragma unroll
        for (int it = 0; it < 4; it++) {
            int idx = t + it * 256;
            int row = idx >> 3, g = idx & 7;
            unsigned so = swaddr<128>(row, g);
            size_t go = (size_t)row * DD + j0 + g * 8;
            CPA16(smb + BF_OFF + so, Wh + go);
            CPA16(smb + BF_OFF + BF_L + so, Wl + go);
        }
        CPA_COMMIT();
    };

    // ---- phase 1 ----
    stage1(0, 0);
    stage1(1, 1);
#pragma unroll 1
    for (int c = 0; c < 16; c++) {
        CPA_WAIT(1);
        __syncthreads();
        int sel = c & 1;
        convert1(sel);
        __syncthreads();
        unsigned base = smb + sel * SLOT;
        mma_k16t<64, 64>(acc, base + SL_AH, base + SL_AL, base + SL_BH, base + SL_BL,
                         nr, d0, lane, 0, 0);
        mma_k16t<64, 64>(acc, base + SL_AH, base + SL_AL, base + SL_BH, base + SL_BL,
                         nr, d0, lane, 16, 16);
        __syncthreads();
        if (c + 2 < 16) stage1(c + 2, sel);
        else CPA_COMMIT();
    }
    stageB(g_Wkh, g_Wkl, 0);

    // ---- LN from accumulators ----
    {
        float rs[4] = {0.f, 0.f, 0.f, 0.f}, rs2[4] = {0.f, 0.f, 0.f, 0.f};
#pragma unroll
        for (int nb = 0; nb < 2; nb++)
#pragma unroll
            for (int u = 0; u < 8; u++) {
                int dc = d0 + u * 8 + (lane & 3) * 2;
                float v0 = acc[nb][u][0] + bp_s[dc];
                float v1 = acc[nb][u][1] + bp_s[dc + 1];
                float v2 = acc[nb][u][2] + bp_s[dc];
                float v3 = acc[nb][u][3] + bp_s[dc + 1];
                rs[nb * 2] += v0 + v1;       rs2[nb * 2] += v0 * v0 + v1 * v1;
                rs[nb * 2 + 1] += v2 + v3;   rs2[nb * 2 + 1] += v2 * v2 + v3 * v3;
            }
#pragma unroll
        for (int off = 1; off <= 2; off <<= 1)
#pragma unroll
            for (int i = 0; i < 4; i++) {
                rs[i] += __shfl_xor_sync(0xffffffffu, rs[i], off);
                rs2[i] += __shfl_xor_sync(0xffffffffu, rs2[i], off);
            }
        if ((lane & 3) == 0) {
#pragma unroll
            for (int i = 0; i < 4; i++) {
                int row = nr + (i >> 1) * 16 + (i & 1) * 8 + (lane >> 2);
                ps[warpX][row] = rs[i];
                ps2[warpX][row] = rs2[i];
            }
        }
    }
    __syncthreads();
    if (t < 128) {
        float s = ps[0][t] + ps[1][t];
        float s2 = ps2[0][t] + ps2[1][t];
        float m = s * (1.0f / 128.0f);
        float var = s2 * (1.0f / 128.0f) - m * m;
        mean_s[t] = m;
        istd_s[t] = rsqrtf(var + 1e-5f);
    }
    __syncthreads();

    // ---- write LN output as bf16 hi/lo into A-full ----
#pragma unroll
    for (int nb = 0; nb < 2; nb++)
#pragma unroll
        for (int u = 0; u < 8; u++) {
            int dc = d0 + u * 8 + (lane & 3) * 2;
            int r0 = nr + nb * 16 + (lane >> 2), r1 = r0 + 8;
            float m0 = mean_s[r0], i0 = istd_s[r0];
            float m1 = mean_s[r1], i1 = istd_s[r1];
            float f0 = (acc[nb][u][0] + bp_s[dc] - m0) * i0 * gin_s[dc] + bin_s[dc];
            float f1 = (acc[nb][u][1] + bp_s[dc + 1] - m0) * i0 * gin_s[dc + 1] + bin_s[dc + 1];
            float f2 = (acc[nb][u][2] + bp_s[dc] - m1) * i1 * gin_s[dc] + bin_s[dc];
            float f3 = (acc[nb][u][3] + bp_s[dc + 1] - m1) * i1 * gin_s[dc + 1] + bin_s[dc + 1];
            unsigned vh, vl;
            unsigned o0 = swaddr<256>(r0, dc >> 3) + (dc & 7) * 2;
            split2(f0, f1, vh, vl);
            *(unsigned*)(sm + o0) = vh;
            *(unsigned*)(sm + AF_L + o0) = vl;
            unsigned o1 = swaddr<256>(r1, dc >> 3) + (dc & 7) * 2;
            split2(f2, f3, vh, vl);
            *(unsigned*)(sm + o1) = vh;
            *(unsigned*)(sm + AF_L + o1) = vl;
        }
    __syncthreads();

    // ---- phases 2/3 ----
    unsigned aH = smb, aL = smb + AF_L, bH = smb + BF_OFF, bL = smb + BF_OFF + BF_L;
    float acc2[2][8][4];
#pragma unroll
    for (int nb = 0; nb < 2; nb++)
#pragma unroll
        for (int u = 0; u < 8; u++)
#pragma unroll
            for (int j = 0; j < 4; j++) acc2[nb][u][j] = 0.f;
    CPA_WAIT(0); __syncthreads();
#pragma unroll
    for (int kk = 0; kk < 64; kk += 16)
        mma_k16t<256, 128>(acc2, aH, aL, bH, bL, nr, d0, lane, kk, kk);
    __syncthreads();
    stageB(g_Wkh, g_Wkl, 64);
    CPA_WAIT(0); __syncthreads();
#pragma unroll
    for (int kk = 0; kk < 64; kk += 16)
        mma_k16t<256, 128>(acc2, aH, aL, bH, bL, nr, d0, lane, 64 + kk, kk);
    __syncthreads();
    stageB(g_Wvh, g_Wvl, 0);
    writeout(acc2, g_k + ((size_t)b * NN + n0) * DD, bk_s, nr, d0, lane, pol);
#pragma unroll
    for (int nb = 0; nb < 2; nb++)
#pragma unroll
        for (int u = 0; u < 8; u++)
#pragma unroll
            for (int j = 0; j < 4; j++) acc2[nb][u][j] = 0.f;
    CPA_WAIT(0); __syncthreads();
#pragma unroll
    for (int kk = 0; kk < 64; kk += 16)
        mma_k16t<256, 128>(acc2, aH, aL, bH, bL, nr, d0, lane, kk, kk);
    __syncthreads();
    stageB(g_Wvh, g_Wvl, 64);
    CPA_WAIT(0); __syncthreads();
#pragma unroll
    for (int kk = 0; kk < 64; kk += 16)
        mma_k16t<256, 128>(acc2, aH, aL, bH, bL, nr, d0, lane, 64 + kk, kk);
    writeout(acc2, g_v + ((size_t)b * NN + n0) * DD, bv_s, nr, d0, lane, pol);
}

// ---------------- kernel 2: attention (k/v loads pinned to L2) ----------------
__global__ __launch_bounds__(256) void k_attn(float* __restrict__ attn_out, int write_attn) {
    __shared__ float updp[8][KK * DD];
    __shared__ float asums[8][KK];
    __shared__ float atile[8][KK][16];

    int b = blockIdx.y, split = blockIdx.x;
    int t = threadIdx.x, lane = t & 31, w = t >> 5;
    int n0 = split * (NN / NSPLIT);
    int nb = n0 + w * 16;
    const unsigned long long pol = mk_policy();

    const float* qp = g_q + (size_t)b * KK * DD + lane * 4;
    float qreg[KK][4];
#pragma unroll
    for (int s = 0; s < KK; s++) {
        float4 qv = *(const float4*)(qp + s * DD);
        qreg[s][0] = qv.x; qreg[s][1] = qv.y; qreg[s][2] = qv.z; qreg[s][3] = qv.w;
    }
    float upd[KK][4];
    float asum[KK];
#pragma unroll
    for (int s = 0; s < KK; s++) {
        asum[s] = 0.f;
#pragma unroll
        for (int j = 0; j < 4; j++) upd[s][j] = 0.f;
    }

    const float* kb = g_k + ((size_t)b * NN + nb) * DD + lane * 4;
    const float* vb = g_v + ((size_t)b * NN + nb) * DD + lane * 4;
    float4 kc = ldg_el4(kb, pol);
    float4 vc = ldg_el4(vb, pol);

#pragma unroll 4
    for (int i = 0; i < 16; i++) {
        float4 kn = kc, vn = vc;
        if (i < 15) {
            kn = ldg_el4(kb + (i + 1) * DD, pol);
            vn = ldg_el4(vb + (i + 1) * DD, pol);
        }
        float lg[KK];
#pragma unroll
        for (int s = 0; s < KK; s++)
            lg[s] = qreg[s][0] * kc.x + qreg[s][1] * kc.y + qreg[s][2] * kc.z + qreg[s][3] * kc.w;
#pragma unroll
        for (int off = 16; off; off >>= 1)
#pragma unroll
            for (int s = 0; s < KK; s++) lg[s] += __shfl_xor_sync(0xffffffffu, lg[s], off);
        float mx = lg[0];
#pragma unroll
        for (int s = 1; s < KK; s++) mx = fmaxf(mx, lg[s]);
        float ssum = 0.f;
#pragma unroll
        for (int s = 0; s < KK; s++) { lg[s] = __expf(lg[s] - mx); ssum += lg[s]; }
        float inv = 1.0f / ssum;
#pragma unroll
        for (int s = 0; s < KK; s++) {
            lg[s] *= inv;
            asum[s] += lg[s];
            upd[s][0] = fmaf(lg[s], vc.x, upd[s][0]);
            upd[s][1] = fmaf(lg[s], vc.y, upd[s][1]);
            upd[s][2] = fmaf(lg[s], vc.z, upd[s][2]);
            upd[s][3] = fmaf(lg[s], vc.w, upd[s][3]);
        }
        if (write_attn && lane < 8) {
            float av = lane == 0 ? lg[0] : lane == 1 ? lg[1] : lane == 2 ? lg[2] :
                       lane == 3 ? lg[3] : lane == 4 ? lg[4] : lane == 5 ? lg[5] :
                       lane == 6 ? lg[6] : lg[7];
            atile[w][lane][i] = av;
        }
        kc = kn; vc = vn;
    }
#pragma unroll
    for (int s = 0; s < KK; s++)
        *(float4*)&updp[w][s * DD + lane * 4] =
            make_float4(upd[s][0], upd[s][1], upd[s][2], upd[s][3]);
    if (lane == 0) {
#pragma unroll
        for (int s = 0; s < KK; s++) asums[w][s] = asum[s];
    }
    __syncthreads();
    for (int idx = t; idx < KK * DD; idx += 256) {
        float s = 0.f;
#pragma unroll
        for (int ww = 0; ww < 8; ww++) s += updp[ww][idx];
        g_upd[((size_t)b * NSPLIT + split) * KK * DD + idx] = s;
    }
    if (t < KK) {
        float s = 0.f;
#pragma unroll
        for (int ww = 0; ww < 8; ww++) s += asums[ww][t];
        g_asum[((size_t)b * NSPLIT + split) * KK + t] = s;
    }
    if (write_attn) {
        for (int idx = t; idx < KK * (NN / NSPLIT); idx += 256) {
            int s = idx >> 7, n = idx & 127;
            attn_out[((size_t)b * KK + s) * NN + n0 + n] = atile[n >> 4][s][n & 15];
        }
    }
}

// ---------------- kernel 3: updates + GRU + MLP + next-iter q ----------------
__global__ __launch_bounds__(512) void k_update(
    const float* __restrict__ b_ih, const float* __restrict__ b_hh,
    const float* __restrict__ W1, const float* __restrict__ b1,
    const float* __restrict__ W2, const float* __restrict__ b2,
    const float* __restrict__ gm, const float* __restrict__ bm,
    const float* __restrict__ Wq, const float* __restrict__ bq,
    const float* __restrict__ gsl, const float* __restrict__ bsl,
    float* __restrict__ slots_out, int last) {
    __shared__ float us[KK * DD];
    __shared__ float hs[KK * DD];
    __shared__ float gxs[KK * 384];
    __shared__ float ghs[KK * 384];
    __shared__ float astot[KK];
    float* ns = us;
    float* lns = hs;
    float* h1s = gxs;
    float* fs = hs;
    float* lnq = ghs;

    int b = blockIdx.x;
    int t = threadIdx.x;
    int wid = t >> 5, lane = t & 31;

    if (t < KK) {
        float s = 0.f;
        for (int sp = 0; sp < NSPLIT; sp++) s += g_asum[((size_t)b * NSPLIT + sp) * KK + t];
        astot[t] = s + 1e-8f;
    }
    for (int i = t; i < KK * DD; i += 512) hs[i] = g_slots[(size_t)b * KK * DD + i];
    __syncthreads();
    for (int i = t; i < KK * DD; i += 512) {
        float s = 0.f;
        for (int sp = 0; sp < NSPLIT; sp++)
            s += g_upd[((size_t)b * NSPLIT + sp) * KK * DD + i];
        us[i] = s / astot[i >> 7];
    }
    __syncthreads();

    if (t < 384) {
        int o = t;
        float accx[KK], acch[KK];
#pragma unroll
        for (int r = 0; r < KK; r++) { accx[r] = b_ih[o]; acch[r] = b_hh[o]; }
        const float* wi = g_wihT + o;
        const float* wh = g_whhT + o;
#pragma unroll 8
        for (int j = 0; j < DD; j++) {
            float wa = wi[(size_t)j * 384];
            float wb = wh[(size_t)j * 384];
#pragma unroll
            for (int r = 0; r < KK; r++) {
                accx[r] = fmaf(us[r * DD + j], wa, accx[r]);
                acch[r] = fmaf(hs[r * DD + j], wb, acch[r]);
            }
        }
#pragma unroll
        for (int r = 0; r < KK; r++) { gxs[r * 384 + o] = accx[r]; ghs[r * 384 + o] = acch[r]; }
    }
    __syncthreads();

    for (int idx = t; idx < KK * DD; idx += 512) {
        int r = idx >> 7, d = idx & 127;
        float xr = gxs[r * 384 + d],       hr = ghs[r * 384 + d];
        float xz = gxs[r * 384 + 128 + d], hz = ghs[r * 384 + 128 + d];
        float xn = gxs[r * 384 + 256 + d], hn = ghs[r * 384 + 256 + d];
        float rg = sigf(xr + hr);
        float zg = sigf(xz + hz);
        float ng = tanhf(xn + rg * hn);
        ns[idx] = (1.0f - zg) * ng + zg * hs[idx];
    }
    __syncthreads();

    if (wid < KK) {
        int row = wid;
        float s = 0.f, s2 = 0.f, vr[4];
#pragma unroll
        for (int i = 0; i < 4; i++) {
            float val = ns[row * DD + lane * 4 + i];
            vr[i] = val; s += val; s2 += val * val;
        }
#pragma unroll
        for (int off = 16; off; off >>= 1) {
            s += __shfl_xor_sync(0xffffffffu, s, off);
            s2 += __shfl_xor_sync(0xffffffffu, s2, off);
        }
        float m = s * (1.0f / 128.0f);
        float var = s2 * (1.0f / 128.0f) - m * m;
        float inv = rsqrtf(var + 1e-5f);
#pragma unroll
        for (int i = 0; i < 4; i++) {
            int d = lane * 4 + i;
            lns[row * DD + d] = (vr[i] - m) * inv * gm[d] + bm[d];
        }
    }
    __syncthreads();

    if (t < 256) {
        int o = t;
        float acc[KK];
#pragma unroll
        for (int r = 0; r < KK; r++) acc[r] = b1[o];
#pragma unroll 8
        for (int j = 0; j < DD; j++) {
            float w = W1[(size_t)j * 256 + o];
#pragma unroll
            for (int r = 0; r < KK; r++) acc[r] = fmaf(lns[r * DD + j], w, acc[r]);
        }
#pragma unroll
        for (int r = 0; r < KK; r++) h1s[r * 256 + o] = geluf(acc[r]);
    }
    __syncthreads();

    {
        int d = t & 127;
        int rg2 = t >> 7;
        float acc[2] = {0.f, 0.f};
#pragma unroll 8
        for (int j = 0; j < 256; j++) {
            float w = W2[(size_t)j * DD + d];
#pragma unroll
            for (int i = 0; i < 2; i++) acc[i] = fmaf(h1s[(rg2 * 2 + i) * 256 + j], w, acc[i]);
        }
#pragma unroll
        for (int i = 0; i < 2; i++) {
            int r = rg2 * 2 + i;
            float val = ns[r * DD + d] + acc[i] + b2[d];
            g_slots[(size_t)b * KK * DD + r * DD + d] = val;
            fs[r * DD + d] = val;
            if (last) slots_out[(size_t)b * KK * DD + r * DD + d] = val;
        }
    }
    __syncthreads();

    if (!last) {
        const float SCALE = 0.08838834764831845f;
        if (wid < KK) {
            int row = wid;
            float s = 0.f, s2 = 0.f, vr[4];
#pragma unroll
            for (int i = 0; i < 4; i++) {
                float val = fs[row * DD + lane * 4 + i];
                vr[i] = val; s += val; s2 += val * val;
            }
#pragma unroll
            for (int off = 16; off; off >>= 1) {
                s += __shfl_xor_sync(0xffffffffu, s, off);
                s2 += __shfl_xor_sync(0xffffffffu, s2, off);
            }
            float m = s * (1.0f / 128.0f);
            float var = s2 * (1.0f / 128.0f) - m * m;
            float inv = rsqrtf(var + 1e-5f);
#pragma unroll
            for (int i = 0; i < 4; i++) {
                int d = lane * 4 + i;
                lnq[row * DD + d] = (vr[i] - m) * inv * gsl[d] + bsl[d];
            }
        }
        __syncthreads();
        int d = t & 127, grp = t >> 7;
        float a0 = 0.f, a1 = 0.f;
#pragma unroll 8
        for (int j = 0; j < DD; j++) {
            float w = Wq[(size_t)j * DD + d];
            a0 = fmaf(lnq[(grp * 2) * DD + j], w, a0);
            a1 = fmaf(lnq[(grp * 2 + 1) * DD + j], w, a1);
        }
        g_q[((size_t)b * KK + grp * 2) * DD + d] = (a0 + bq[d]) * SCALE;
        g_q[((size_t)b * KK + grp * 2 + 1) * DD + d] = (a1 + bq[d]) * SCALE;
    }
}

// ---------------- launcher ----------------
extern "C" void kernel_launch(void* const* d_in, const int* in_sizes, int n_in,
                              void* d_out, int out_size) {
    const float* x       = (const float*)d_in[0];
    const float* noise   = (const float*)d_in[1];
    const float* slot_mu = (const float*)d_in[2];
    const float* slot_ls = (const float*)d_in[3];
    const float* Wp   = (const float*)d_in[4];
    const float* bp   = (const float*)d_in[5];
    const float* gin  = (const float*)d_in[6];
    const float* bin  = (const float*)d_in[7];
    const float* Wq   = (const float*)d_in[8];
    const float* bq   = (const float*)d_in[9];
    const float* Wk   = (const float*)d_in[10];
    const float* bk   = (const float*)d_in[11];
    const float* Wv   = (const float*)d_in[12];
    const float* bv   = (const float*)d_in[13];
    const float* W_ih = (const float*)d_in[14];
    const float* W_hh = (const float*)d_in[15];
    const float* b_ih = (const float*)d_in[16];
    const float* b_hh = (const float*)d_in[17];
    const float* W1   = (const float*)d_in[18];
    const float* b1   = (const float*)d_in[19];
    const float* W2   = (const float*)d_in[20];
    const float* b2   = (const float*)d_in[21];
    const float* gsl  = (const float*)d_in[22];
    const float* bsl  = (const float*)d_in[23];
    const float* gm   = (const float*)d_in[24];
    const float* bm   = (const float*)d_in[25];

    float* out_slots = (float*)d_out;
    float* out_attn  = out_slots + BB * KK * DD;

    cudaFuncSetAttribute(k_proj, cudaFuncAttributeMaxDynamicSharedMemorySize, SMEM_PROJ);
    cudaFuncSetAttribute(k_prep_q, cudaFuncAttributeMaxDynamicSharedMemorySize, SMEM_QS);

    // launch index 3 = k_proj (the slot ncu captures)
    k_prep_t<<<48, 256>>>(W_ih, W_hh);
    k_prep_w<<<192, 256>>>(Wp, Wk, Wv);
    k_prep_q<<<BB, 256, SMEM_QS>>>(slot_mu, slot_ls, noise, Wq, bq, gsl, bsl);
    k_proj<<<dim3(NN / 128, BB), 256, SMEM_PROJ>>>(x, bp, gin, bin, bk, bv);

    for (int it = 0; it < N_ITERS; it++) {
        int last = (it == N_ITERS - 1);
        k_attn<<<dim3(NSPLIT, BB), 256>>>(out_attn, last);
        k_update<<<BB, 512>>>(b_ih, b_hh, W1, b1, W2, b2, gm, bm,
                              Wq, bq, gsl, bsl, out_slots, last);
    }
}

// round 15
// speedup vs baseline: 1.0698x; 1.0203x over previous
#include <cuda_runtime.h>
#include <cuda_bf16.h>
#include <math.h>

#define BB 64
#define CC 512
#define NN 1024
#define KK 8
#define DD 128
#define NSPLIT 8
#define N_ITERS 3

// ---------------- scratch (static device globals; no allocation) ----------------
__device__ float g_k[BB * NN * DD];
__device__ float g_v[BB * NN * DD];
__device__ float g_slots[BB * KK * DD];
__device__ float g_q[BB * KK * DD];
__device__ float g_upd[BB * NSPLIT * KK * DD];
__device__ float g_asum[BB * NSPLIT * KK];
__device__ float g_wihT[DD * 384];
__device__ float g_whhT[DD * 384];
__device__ __nv_bfloat16 g_Wph[DD * CC], g_Wpl[DD * CC];   // [d][c]
__device__ __nv_bfloat16 g_Wkh[DD * DD], g_Wkl[DD * DD];   // [d][j]
__device__ __nv_bfloat16 g_Wvh[DD * DD], g_Wvl[DD * DD];

__device__ __forceinline__ float sigf(float x) { return 1.0f / (1.0f + __expf(-x)); }
__device__ __forceinline__ float geluf(float x) { return 0.5f * x * (1.0f + erff(x * 0.70710678118654752f)); }

// ---------------- mma / ldmatrix / cp.async helpers ----------------
__device__ __forceinline__ unsigned smem_u32(const void* p) {
    unsigned a;
    asm("{ .reg .u64 tmp; cvta.to.shared.u64 tmp, %1; cvt.u32.u64 %0, tmp; }" : "=r"(a) : "l"(p));
    return a;
}
__device__ __forceinline__ void mma_bf16(float acc[4],
    unsigned a0, unsigned a1, unsigned a2, unsigned a3,
    unsigned b0, unsigned b1) {
    asm volatile(
        "mma.sync.aligned.m16n8k16.row.col.f32.bf16.bf16.f32 "
        "{%0,%1,%2,%3}, {%4,%5,%6,%7}, {%8,%9}, {%0,%1,%2,%3};"
        : "+f"(acc[0]), "+f"(acc[1]), "+f"(acc[2]), "+f"(acc[3])
        : "r"(a0), "r"(a1), "r"(a2), "r"(a3), "r"(b0), "r"(b1));
}
__device__ __forceinline__ void ldsm4(unsigned r[4], unsigned addr) {
    asm volatile("ldmatrix.sync.aligned.m8n8.x4.shared.b16 {%0,%1,%2,%3}, [%4];"
        : "=r"(r[0]), "=r"(r[1]), "=r"(r[2]), "=r"(r[3]) : "r"(addr));
}
#define CPA16(dst, src) asm volatile("cp.async.cg.shared.global [%0], [%1], 16;" :: "r"(dst), "l"(src))
#define CPA_COMMIT() asm volatile("cp.async.commit_group;" ::: "memory")
#define CPA_WAIT(n) asm volatile("cp.async.wait_group %0;" :: "n"(n) : "memory")

// streaming (evict_first) k/v loads: don't pollute L2, keep update weights resident
__device__ __forceinline__ unsigned long long mk_policy_ef() {
    unsigned long long pol;
    asm("createpolicy.fractional.L2::evict_first.b64 %0, 1.0;" : "=l"(pol));
    return pol;
}
__device__ __forceinline__ float4 ldg_ef4(const float* p, unsigned long long pol) {
    float4 v;
    asm volatile("ld.global.nc.L2::cache_hint.v4.f32 {%0,%1,%2,%3}, [%4], %5;"
        : "=f"(v.x), "=f"(v.y), "=f"(v.z), "=f"(v.w) : "l"(p), "l"(pol));
    return v;
}

__device__ __forceinline__ void split2(float f0, float f1, unsigned& vh, unsigned& vl) {
    __nv_bfloat162 h = __floats2bfloat162_rn(f0, f1);
    float r0 = f0 - __bfloat162float(h.x);
    float r1 = f1 - __bfloat162float(h.y);
    __nv_bfloat162 l = __floats2bfloat162_rn(r0, r1);
    vh = *(unsigned*)&h; vl = *(unsigned*)&l;
}

// swizzled byte address within a tile: row r, 16B-granule g.
template<int S> __device__ __forceinline__ unsigned swaddr(int r, int g) {
    if (S == 64)  return (unsigned)(r * 64  + ((g ^ ((r >> 1) & 3)) << 4));
    if (S == 128) return (unsigned)(r * 128 + ((g ^ (r & 7)) << 4));
    return (unsigned)(r * 256 + ((g ^ (r & 7)) << 4));
}

// one k16 step for 32n x 64d warp tile, 3-mma bf16 split; SA/SB = tile row bytes.
template<int SA, int SB>
__device__ __forceinline__ void mma_k16t(float (*acc)[8][4],
    unsigned aH, unsigned aL, unsigned bH, unsigned bL,
    int nr, int d0, int lane, int kkA, int kkB) {
    int lr = lane & 15;
    int half = lane >> 4;
    int gA = half + (kkA >> 3);
    int gB = half + (kkB >> 3);
    unsigned bh[4][4], bl[4][4];
#pragma unroll
    for (int db = 0; db < 4; db++) {
        unsigned ro = swaddr<SB>(d0 + db * 16 + lr, gB);
        ldsm4(bh[db], bH + ro);
        ldsm4(bl[db], bL + ro);
    }
#pragma unroll
    for (int nb = 0; nb < 2; nb++) {
        unsigned ra = swaddr<SA>(nr + nb * 16 + lr, gA);
        unsigned ah[4], al[4];
        ldsm4(ah, aH + ra);
        ldsm4(al, aL + ra);
#pragma unroll
        for (int db = 0; db < 4; db++) {
#pragma unroll
            for (int g = 0; g < 2; g++) {
                float* a4 = acc[nb][db * 2 + g];
                mma_bf16(a4, ah[0], ah[1], ah[2], ah[3], bh[db][g], bh[db][g + 2]);
                mma_bf16(a4, ah[0], ah[1], ah[2], ah[3], bl[db][g], bl[db][g + 2]);
                mma_bf16(a4, al[0], al[1], al[2], al[3], bh[db][g], bh[db][g + 2]);
            }
        }
    }
}

// ---------------- kernel 0: fused prep (transpose | cvt_w | init+q) ----------------
#define SMEM_PREP (DD * DD * 4 + KK * (DD + 1) * 4)
__global__ __launch_bounds__(256) void k_prep(
    const float* __restrict__ W_ih, const float* __restrict__ W_hh,
    const float* __restrict__ Wp, const float* __restrict__ Wk, const float* __restrict__ Wv,
    const float* __restrict__ mu, const float* __restrict__ lsig,
    const float* __restrict__ noise,
    const float* __restrict__ Wq, const float* __restrict__ bq,
    const float* __restrict__ gsl, const float* __restrict__ bsl) {
    extern __shared__ float smf[];
    __shared__ float ta[32][33];
    __shared__ float tb[32][33];
    int blk = blockIdx.x;
    int t = threadIdx.x;
    int tx = t & 31, ty = t >> 5;

    if (blk < 48) {
        int bx = blk % 12, by = blk / 12;
        int o0 = bx * 32, j0 = by * 32;
#pragma unroll
        for (int i = 0; i < 4; i++) {
            int o = o0 + ty + 8 * i;
            ta[ty + 8 * i][tx] = W_ih[(size_t)o * DD + j0 + tx];
            tb[ty + 8 * i][tx] = W_hh[(size_t)o * DD + j0 + tx];
        }
        __syncthreads();
#pragma unroll
        for (int i = 0; i < 4; i++) {
            int j = j0 + ty + 8 * i;
            g_wihT[(size_t)j * 384 + o0 + tx] = ta[tx][ty + 8 * i];
            g_whhT[(size_t)j * 384 + o0 + tx] = tb[tx][ty + 8 * i];
        }
    } else if (blk < 240) {
        int idx = blk - 48;
        int z = idx / 64, rem = idx % 64;
        int c0 = (rem % 16) * 32, d0 = (rem / 16) * 32;
        int Cdim = z == 0 ? CC : DD;
        if (c0 >= Cdim) return;
        const float* src = z == 0 ? Wp : (z == 1 ? Wk : Wv);
        __nv_bfloat16* dsth = z == 0 ? g_Wph : (z == 1 ? g_Wkh : g_Wvh);
        __nv_bfloat16* dstl = z == 0 ? g_Wpl : (z == 1 ? g_Wkl : g_Wvl);
#pragma unroll
        for (int i = 0; i < 4; i++)
            ta[ty + 8 * i][tx] = src[(size_t)(c0 + ty + 8 * i) * DD + d0 + tx];
        __syncthreads();
#pragma unroll
        for (int i = 0; i < 4; i++) {
            int d = d0 + ty + 8 * i;
            float f = ta[tx][ty + 8 * i];
            __nv_bfloat16 h = __float2bfloat16(f);
            __nv_bfloat16 l = __float2bfloat16(f - __bfloat162float(h));
            dsth[(size_t)d * Cdim + c0 + tx] = h;
            dstl[(size_t)d * Cdim + c0 + tx] = l;
        }
    } else {
        int b = blk - 240;
        float* Wqs = smf;
        float (*sl)[DD + 1] = (float (*)[DD + 1])(smf + DD * DD);
        const float SCALE = 0.08838834764831845f;
#pragma unroll
        for (int i = 0; i < 16; i++)
            ((float4*)Wqs)[t + i * 256] = ((const float4*)Wq)[t + i * 256];
        for (int i = t; i < KK * DD; i += 256) {
            float v = mu[i] + __expf(lsig[i]) * noise[(size_t)b * KK * DD + i];
            g_slots[(size_t)b * KK * DD + i] = v;
            sl[i >> 7][i & 127] = v;
        }
        __syncthreads();
        {
            int row = ty;
            float s = 0.f, s2 = 0.f, vr[4];
#pragma unroll
            for (int i = 0; i < 4; i++) {
                float val = sl[row][tx * 4 + i];
                vr[i] = val; s += val; s2 += val * val;
            }
#pragma unroll
            for (int off = 16; off; off >>= 1) {
                s += __shfl_xor_sync(0xffffffffu, s, off);
                s2 += __shfl_xor_sync(0xffffffffu, s2, off);
            }
            float m = s * (1.0f / 128.0f);
            float var = s2 * (1.0f / 128.0f) - m * m;
            float inv = rsqrtf(var + 1e-5f);
#pragma unroll
            for (int i = 0; i < 4; i++) {
                int d = tx * 4 + i;
                sl[row][d] = (vr[i] - m) * inv * gsl[d] + bsl[d];
            }
        }
        __syncthreads();
        int d = t & 127, rh = t >> 7;
        float acc[4] = {0.f, 0.f, 0.f, 0.f};
#pragma unroll 8
        for (int j = 0; j < DD; j++) {
            float w = Wqs[j * DD + d];
#pragma unroll
            for (int rr = 0; rr < 4; rr++) acc[rr] = fmaf(sl[rh * 4 + rr][j], w, acc[rr]);
        }
#pragma unroll
        for (int rr = 0; rr < 4; rr++)
            g_q[((size_t)b * KK + rh * 4 + rr) * DD + d] = (acc[rr] + bq[d]) * SCALE;
    }
}

// ---------------- kernel 1: proj + LN + k/v (x converted in-kernel) ----------------
#define XS_SZ 16896
#define SL_AH 16896
#define SL_AL 25088
#define SL_BH 33280
#define SL_BL 41472
#define SLOT 49664
#define AF_L 32768
#define BF_OFF 65536
#define BF_L 16384
#define SMEM_PROJ 99328

__device__ __forceinline__ void writeout(float (*acc)[8][4], float* out, const float* bias,
                                         int nr, int d0, int lane) {
#pragma unroll
    for (int nb = 0; nb < 2; nb++)
#pragma unroll
        for (int u = 0; u < 8; u++) {
            int row = nr + nb * 16 + (lane >> 2);
            int dc = d0 + u * 8 + (lane & 3) * 2;
            *(float2*)(out + (size_t)row * DD + dc) =
                make_float2(acc[nb][u][0] + bias[dc], acc[nb][u][1] + bias[dc + 1]);
            *(float2*)(out + (size_t)(row + 8) * DD + dc) =
                make_float2(acc[nb][u][2] + bias[dc], acc[nb][u][3] + bias[dc + 1]);
        }
}

__global__ __launch_bounds__(256, 2) void k_proj(
    const float* __restrict__ x,
    const float* __restrict__ bp,
    const float* __restrict__ gin, const float* __restrict__ bin,
    const float* __restrict__ bk, const float* __restrict__ bv) {
    extern __shared__ char sm[];
    __shared__ float bp_s[DD], gin_s[DD], bin_s[DD], bk_s[DD], bv_s[DD];
    __shared__ float mean_s[128], istd_s[128];
    __shared__ float ps[2][128], ps2[2][128];

    const int t = threadIdx.x, lane = t & 31, wid = t >> 5;
    const int warpX = wid >> 2, warpY = wid & 3;
    const int d0 = warpX * 64, nr = warpY * 32;
    const int b = blockIdx.y, n0 = blockIdx.x * 128;
    const unsigned smb = smem_u32(sm);

    if (t < DD) {
        bp_s[t] = bp[t]; gin_s[t] = gin[t]; bin_s[t] = bin[t];
        bk_s[t] = bk[t]; bv_s[t] = bv[t];
    }

    const float* xb = x + (size_t)b * CC * NN + n0;

    float acc[2][8][4];
#pragma unroll
    for (int nb = 0; nb < 2; nb++)
#pragma unroll
        for (int u = 0; u < 8; u++)
#pragma unroll
            for (int j = 0; j < 4; j++) acc[nb][u][j] = 0.f;

    auto stage1 = [&](int c, int sel) {
        unsigned base = smb + sel * SLOT;
        int c0 = c * 32;
#pragma unroll
        for (int it = 0; it < 4; it++) {
            int idx = t + it * 256;
            int row = idx >> 5, g = idx & 31;
            CPA16(base + row * 528 + g * 16, xb + (size_t)(c0 + row) * NN + g * 4);
        }
#pragma unroll
        for (int it = 0; it < 2; it++) {
            int idx = t + it * 256;
            int row = idx >> 2, g = idx & 3;
            unsigned so = swaddr<64>(row, g);
            size_t go = (size_t)row * CC + c0 + g * 8;
            CPA16(base + SL_BH + so, g_Wph + go);
            CPA16(base + SL_BL + so, g_Wpl + go);
        }
        CPA_COMMIT();
    };
    auto convert1 = [&](int sel) {
        char* sb = sm + sel * SLOT;
#pragma unroll
        for (int it = 0; it < 8; it++) {
            int idx = t + it * 256;
            int n = idx & 127, p = idx >> 7;
            float f0 = *(const float*)(sb + (2 * p) * 528 + n * 4);
            float f1 = *(const float*)(sb + (2 * p + 1) * 528 + n * 4);
            unsigned vh, vl; split2(f0, f1, vh, vl);
            unsigned off = swaddr<64>(n, p >> 2) + (p & 3) * 4;
            *(unsigned*)(sb + SL_AH + off) = vh;
            *(unsigned*)(sb + SL_AL + off) = vl;
        }
    };
    auto stageB = [&](const __nv_bfloat16* Wh, const __nv_bfloat16* Wl, int j0) {
#pragma unroll
        for (int it = 0; it < 4; it++) {
            int idx = t + it * 256;
            int row = idx >> 3, g = idx & 7;
            unsigned so = swaddr<128>(row, g);
            size_t go = (size_t)row * DD + j0 + g * 8;
            CPA16(smb + BF_OFF + so, Wh + go);
            CPA16(smb + BF_OFF + BF_L + so, Wl + go);
        }
        CPA_COMMIT();
    };

    // ---- phase 1 ----
    stage1(0, 0);
    stage1(1, 1);
#pragma unroll 1
    for (int c = 0; c < 16; c++) {
        CPA_WAIT(1);
        __syncthreads();
        int sel = c & 1;
        convert1(sel);
        __syncthreads();
        unsigned base = smb + sel * SLOT;
        mma_k16t<64, 64>(acc, base + SL_AH, base + SL_AL, base + SL_BH, base + SL_BL,
                         nr, d0, lane, 0, 0);
        mma_k16t<64, 64>(acc, base + SL_AH, base + SL_AL, base + SL_BH, base + SL_BL,
                         nr, d0, lane, 16, 16);
        __syncthreads();
        if (c + 2 < 16) stage1(c + 2, sel);
        else CPA_COMMIT();
    }
    stageB(g_Wkh, g_Wkl, 0);

    // ---- LN from accumulators ----
    {
        float rs[4] = {0.f, 0.f, 0.f, 0.f}, rs2[4] = {0.f, 0.f, 0.f, 0.f};
#pragma unroll
        for (int nb = 0; nb < 2; nb++)
#pragma unroll
            for (int u = 0; u < 8; u++) {
                int dc = d0 + u * 8 + (lane & 3) * 2;
                float v0 = acc[nb][u][0] + bp_s[dc];
                float v1 = acc[nb][u][1] + bp_s[dc + 1];
                float v2 = acc[nb][u][2] + bp_s[dc];
                float v3 = acc[nb][u][3] + bp_s[dc + 1];
                rs[nb * 2] += v0 + v1;       rs2[nb * 2] += v0 * v0 + v1 * v1;
                rs[nb * 2 + 1] += v2 + v3;   rs2[nb * 2 + 1] += v2 * v2 + v3 * v3;
            }
#pragma unroll
        for (int off = 1; off <= 2; off <<= 1)
#pragma unroll
            for (int i = 0; i < 4; i++) {
                rs[i] += __shfl_xor_sync(0xffffffffu, rs[i], off);
                rs2[i] += __shfl_xor_sync(0xffffffffu, rs2[i], off);
            }
        if ((lane & 3) == 0) {
#pragma unroll
            for (int i = 0; i < 4; i++) {
                int row = nr + (i >> 1) * 16 + (i & 1) * 8 + (lane >> 2);
                ps[warpX][row] = rs[i];
                ps2[warpX][row] = rs2[i];
            }
        }
    }
    __syncthreads();
    if (t < 128) {
        float s = ps[0][t] + ps[1][t];
        float s2 = ps2[0][t] + ps2[1][t];
        float m = s * (1.0f / 128.0f);
        float var = s2 * (1.0f / 128.0f) - m * m;
        mean_s[t] = m;
        istd_s[t] = rsqrtf(var + 1e-5f);
    }
    __syncthreads();

    // ---- write LN output as bf16 hi/lo into A-full ----
#pragma unroll
    for (int nb = 0; nb < 2; nb++)
#pragma unroll
        for (int u = 0; u < 8; u++) {
            int dc = d0 + u * 8 + (lane & 3) * 2;
            int r0 = nr + nb * 16 + (lane >> 2), r1 = r0 + 8;
            float m0 = mean_s[r0], i0 = istd_s[r0];
            float m1 = mean_s[r1], i1 = istd_s[r1];
            float f0 = (acc[nb][u][0] + bp_s[dc] - m0) * i0 * gin_s[dc] + bin_s[dc];
            float f1 = (acc[nb][u][1] + bp_s[dc + 1] - m0) * i0 * gin_s[dc + 1] + bin_s[dc + 1];
            float f2 = (acc[nb][u][2] + bp_s[dc] - m1) * i1 * gin_s[dc] + bin_s[dc];
            float f3 = (acc[nb][u][3] + bp_s[dc + 1] - m1) * i1 * gin_s[dc + 1] + bin_s[dc + 1];
            unsigned vh, vl;
            unsigned o0 = swaddr<256>(r0, dc >> 3) + (dc & 7) * 2;
            split2(f0, f1, vh, vl);
            *(unsigned*)(sm + o0) = vh;
            *(unsigned*)(sm + AF_L + o0) = vl;
            unsigned o1 = swaddr<256>(r1, dc >> 3) + (dc & 7) * 2;
            split2(f2, f3, vh, vl);
            *(unsigned*)(sm + o1) = vh;
            *(unsigned*)(sm + AF_L + o1) = vl;
        }
    __syncthreads();

    // ---- phases 2/3 ----
    unsigned aH = smb, aL = smb + AF_L, bH = smb + BF_OFF, bL = smb + BF_OFF + BF_L;
    float acc2[2][8][4];
#pragma unroll
    for (int nb = 0; nb < 2; nb++)
#pragma unroll
        for (int u = 0; u < 8; u++)
#pragma unroll
            for (int j = 0; j < 4; j++) acc2[nb][u][j] = 0.f;
    CPA_WAIT(0); __syncthreads();
#pragma unroll
    for (int kk = 0; kk < 64; kk += 16)
        mma_k16t<256, 128>(acc2, aH, aL, bH, bL, nr, d0, lane, kk, kk);
    __syncthreads();
    stageB(g_Wkh, g_Wkl, 64);
    CPA_WAIT(0); __syncthreads();
#pragma unroll
    for (int kk = 0; kk < 64; kk += 16)
        mma_k16t<256, 128>(acc2, aH, aL, bH, bL, nr, d0, lane, 64 + kk, kk);
    __syncthreads();
    stageB(g_Wvh, g_Wvl, 0);
    writeout(acc2, g_k + ((size_t)b * NN + n0) * DD, bk_s, nr, d0, lane);
#pragma unroll
    for (int nb = 0; nb < 2; nb++)
#pragma unroll
        for (int u = 0; u < 8; u++)
#pragma unroll
            for (int j = 0; j < 4; j++) acc2[nb][u][j] = 0.f;
    CPA_WAIT(0); __syncthreads();
#pragma unroll
    for (int kk = 0; kk < 64; kk += 16)
        mma_k16t<256, 128>(acc2, aH, aL, bH, bL, nr, d0, lane, kk, kk);
    __syncthreads();
    stageB(g_Wvh, g_Wvl, 64);
    CPA_WAIT(0); __syncthreads();
#pragma unroll
    for (int kk = 0; kk < 64; kk += 16)
        mma_k16t<256, 128>(acc2, aH, aL, bH, bL, nr, d0, lane, 64 + kk, kk);
    writeout(acc2, g_v + ((size_t)b * NN + n0) * DD, bv_s, nr, d0, lane);
}

// ---------------- kernel 2: attention (k/v streamed with evict_first) ----------------
__global__ __launch_bounds__(256) void k_attn(float* __restrict__ attn_out, int write_attn) {
    __shared__ float updp[8][KK * DD];
    __shared__ float asums[8][KK];
    __shared__ float atile[8][KK][16];

    int b = blockIdx.y, split = blockIdx.x;
    int t = threadIdx.x, lane = t & 31, w = t >> 5;
    int n0 = split * (NN / NSPLIT);
    int nb = n0 + w * 16;
    const unsigned long long pol = mk_policy_ef();

    const float* qp = g_q + (size_t)b * KK * DD + lane * 4;
    float qreg[KK][4];
#pragma unroll
    for (int s = 0; s < KK; s++) {
        float4 qv = *(const float4*)(qp + s * DD);
        qreg[s][0] = qv.x; qreg[s][1] = qv.y; qreg[s][2] = qv.z; qreg[s][3] = qv.w;
    }
    float upd[KK][4];
    float asum[KK];
#pragma unroll
    for (int s = 0; s < KK; s++) {
        asum[s] = 0.f;
#pragma unroll
        for (int j = 0; j < 4; j++) upd[s][j] = 0.f;
    }

    const float* kb = g_k + ((size_t)b * NN + nb) * DD + lane * 4;
    const float* vb = g_v + ((size_t)b * NN + nb) * DD + lane * 4;
    float4 kc = ldg_ef4(kb, pol);
    float4 vc = ldg_ef4(vb, pol);

#pragma unroll 4
    for (int i = 0; i < 16; i++) {
        float4 kn = kc, vn = vc;
        if (i < 15) {
            kn = ldg_ef4(kb + (i + 1) * DD, pol);
            vn = ldg_ef4(vb + (i + 1) * DD, pol);
        }
        float lg[KK];
#pragma unroll
        for (int s = 0; s < KK; s++)
            lg[s] = qreg[s][0] * kc.x + qreg[s][1] * kc.y + qreg[s][2] * kc.z + qreg[s][3] * kc.w;
#pragma unroll
        for (int off = 16; off; off >>= 1)
#pragma unroll
            for (int s = 0; s < KK; s++) lg[s] += __shfl_xor_sync(0xffffffffu, lg[s], off);
        float mx = lg[0];
#pragma unroll
        for (int s = 1; s < KK; s++) mx = fmaxf(mx, lg[s]);
        float ssum = 0.f;
#pragma unroll
        for (int s = 0; s < KK; s++) { lg[s] = __expf(lg[s] - mx); ssum += lg[s]; }
        float inv = 1.0f / ssum;
#pragma unroll
        for (int s = 0; s < KK; s++) {
            lg[s] *= inv;
            asum[s] += lg[s];
            upd[s][0] = fmaf(lg[s], vc.x, upd[s][0]);
            upd[s][1] = fmaf(lg[s], vc.y, upd[s][1]);
            upd[s][2] = fmaf(lg[s], vc.z, upd[s][2]);
            upd[s][3] = fmaf(lg[s], vc.w, upd[s][3]);
        }
        if (write_attn && lane < 8) {
            float av = lane == 0 ? lg[0] : lane == 1 ? lg[1] : lane == 2 ? lg[2] :
                       lane == 3 ? lg[3] : lane == 4 ? lg[4] : lane == 5 ? lg[5] :
                       lane == 6 ? lg[6] : lg[7];
            atile[w][lane][i] = av;
        }
        kc = kn; vc = vn;
    }
#pragma unroll
    for (int s = 0; s < KK; s++)
        *(float4*)&updp[w][s * DD + lane * 4] =
            make_float4(upd[s][0], upd[s][1], upd[s][2], upd[s][3]);
    if (lane == 0) {
#pragma unroll
        for (int s = 0; s < KK; s++) asums[w][s] = asum[s];
    }
    __syncthreads();
    for (int idx = t; idx < KK * DD; idx += 256) {
        float s = 0.f;
#pragma unroll
        for (int ww = 0; ww < 8; ww++) s += updp[ww][idx];
        g_upd[((size_t)b * NSPLIT + split) * KK * DD + idx] = s;
    }
    if (t < KK) {
        float s = 0.f;
#pragma unroll
        for (int ww = 0; ww < 8; ww++) s += asums[ww][t];
        g_asum[((size_t)b * NSPLIT + split) * KK + t] = s;
    }
    if (write_attn) {
        for (int idx = t; idx < KK * (NN / NSPLIT); idx += 256) {
            int s = idx >> 7, n = idx & 127;
            attn_out[((size_t)b * KK + s) * NN + n0 + n] = atile[n >> 4][s][n & 15];
        }
    }
}

// ---------------- kernel 3: updates + GRU + MLP + next-iter q ----------------
__global__ __launch_bounds__(512) void k_update(
    const float* __restrict__ b_ih, const float* __restrict__ b_hh,
    const float* __restrict__ W1, const float* __restrict__ b1,
    const float* __restrict__ W2, const float* __restrict__ b2,
    const float* __restrict__ gm, const float* __restrict__ bm,
    const float* __restrict__ Wq, const float* __restrict__ bq,
    const float* __restrict__ gsl, const float* __restrict__ bsl,
    float* __restrict__ slots_out, int last) {
    __shared__ float us[KK * DD];
    __shared__ float hs[KK * DD];
    __shared__ float gxs[KK * 384];
    __shared__ float ghs[KK * 384];
    __shared__ float astot[KK];
    float* ns = us;
    float* lns = hs;
    float* h1s = gxs;
    float* fs = hs;
    float* lnq = ghs;

    int b = blockIdx.x;
    int t = threadIdx.x;
    int wid = t >> 5, lane = t & 31;

    if (t < KK) {
        float s = 0.f;
        for (int sp = 0; sp < NSPLIT; sp++) s += g_asum[((size_t)b * NSPLIT + sp) * KK + t];
        astot[t] = s + 1e-8f;
    }
    for (int i = t; i < KK * DD; i += 512) hs[i] = g_slots[(size_t)b * KK * DD + i];
    __syncthreads();
    for (int i = t; i < KK * DD; i += 512) {
        float s = 0.f;
        for (int sp = 0; sp < NSPLIT; sp++)
            s += g_upd[((size_t)b * NSPLIT + sp) * KK * DD + i];
        us[i] = s / astot[i >> 7];
    }
    __syncthreads();

    if (t < 384) {
        int o = t;
        float accx[KK], acch[KK];
#pragma unroll
        for (int r = 0; r < KK; r++) { accx[r] = b_ih[o]; acch[r] = b_hh[o]; }
        const float* wi = g_wihT + o;
        const float* wh = g_whhT + o;
#pragma unroll 8
        for (int j = 0; j < DD; j++) {
            float wa = wi[(size_t)j * 384];
            float wb = wh[(size_t)j * 384];
#pragma unroll
            for (int r = 0; r < KK; r++) {
                accx[r] = fmaf(us[r * DD + j], wa, accx[r]);
                acch[r] = fmaf(hs[r * DD + j], wb, acch[r]);
            }
        }
#pragma unroll
        for (int r = 0; r < KK; r++) { gxs[r * 384 + o] = accx[r]; ghs[r * 384 + o] = acch[r]; }
    }
    __syncthreads();

    for (int idx = t; idx < KK * DD; idx += 512) {
        int r = idx >> 7, d = idx & 127;
        float xr = gxs[r * 384 + d],       hr = ghs[r * 384 + d];
        float xz = gxs[r * 384 + 128 + d], hz = ghs[r * 384 + 128 + d];
        float xn = gxs[r * 384 + 256 + d], hn = ghs[r * 384 + 256 + d];
        float rg = sigf(xr + hr);
        float zg = sigf(xz + hz);
        float ng = tanhf(xn + rg * hn);
        ns[idx] = (1.0f - zg) * ng + zg * hs[idx];
    }
    __syncthreads();

    if (wid < KK) {
        int row = wid;
        float s = 0.f, s2 = 0.f, vr[4];
#pragma unroll
        for (int i = 0; i < 4; i++) {
            float val = ns[row * DD + lane * 4 + i];
            vr[i] = val; s += val; s2 += val * val;
        }
#pragma unroll
        for (int off = 16; off; off >>= 1) {
            s += __shfl_xor_sync(0xffffffffu, s, off);
            s2 += __shfl_xor_sync(0xffffffffu, s2, off);
        }
        float m = s * (1.0f / 128.0f);
        float var = s2 * (1.0f / 128.0f) - m * m;
        float inv = rsqrtf(var + 1e-5f);
#pragma unroll
        for (int i = 0; i < 4; i++) {
            int d = lane * 4 + i;
            lns[row * DD + d] = (vr[i] - m) * inv * gm[d] + bm[d];
        }
    }
    __syncthreads();

    if (t < 256) {
        int o = t;
        float acc[KK];
#pragma unroll
        for (int r = 0; r < KK; r++) acc[r] = b1[o];
#pragma unroll 8
        for (int j = 0; j < DD; j++) {
            float w = W1[(size_t)j * 256 + o];
#pragma unroll
            for (int r = 0; r < KK; r++) acc[r] = fmaf(lns[r * DD + j], w, acc[r]);
        }
#pragma unroll
        for (int r = 0; r < KK; r++) h1s[r * 256 + o] = geluf(acc[r]);
    }
    __syncthreads();

    {
        int d = t & 127;
        int rg2 = t >> 7;
        float acc[2] = {0.f, 0.f};
#pragma unroll 8
        for (int j = 0; j < 256; j++) {
            float w = W2[(size_t)j * DD + d];
#pragma unroll
            for (int i = 0; i < 2; i++) acc[i] = fmaf(h1s[(rg2 * 2 + i) * 256 + j], w, acc[i]);
        }
#pragma unroll
        for (int i = 0; i < 2; i++) {
            int r = rg2 * 2 + i;
            float val = ns[r * DD + d] + acc[i] + b2[d];
            g_slots[(size_t)b * KK * DD + r * DD + d] = val;
            fs[r * DD + d] = val;
            if (last) slots_out[(size_t)b * KK * DD + r * DD + d] = val;
        }
    }
    __syncthreads();

    if (!last) {
        const float SCALE = 0.08838834764831845f;
        if (wid < KK) {
            int row = wid;
            float s = 0.f, s2 = 0.f, vr[4];
#pragma unroll
            for (int i = 0; i < 4; i++) {
                float val = fs[row * DD + lane * 4 + i];
                vr[i] = val; s += val; s2 += val * val;
            }
#pragma unroll
            for (int off = 16; off; off >>= 1) {
                s += __shfl_xor_sync(0xffffffffu, s, off);
                s2 += __shfl_xor_sync(0xffffffffu, s2, off);
            }
            float m = s * (1.0f / 128.0f);
            float var = s2 * (1.0f / 128.0f) - m * m;
            float inv = rsqrtf(var + 1e-5f);
#pragma unroll
            for (int i = 0; i < 4; i++) {
                int d = lane * 4 + i;
                lnq[row * DD + d] = (vr[i] - m) * inv * gsl[d] + bsl[d];
            }
        }
        __syncthreads();
        int d = t & 127, grp = t >> 7;
        float a0 = 0.f, a1 = 0.f;
#pragma unroll 8
        for (int j = 0; j < DD; j++) {
            float w = Wq[(size_t)j * DD + d];
            a0 = fmaf(lnq[(grp * 2) * DD + j], w, a0);
            a1 = fmaf(lnq[(grp * 2 + 1) * DD + j], w, a1);
        }
        g_q[((size_t)b * KK + grp * 2) * DD + d] = (a0 + bq[d]) * SCALE;
        g_q[((size_t)b * KK + grp * 2 + 1) * DD + d] = (a1 + bq[d]) * SCALE;
    }
}

// ---------------- launcher ----------------
extern "C" void kernel_launch(void* const* d_in, const int* in_sizes, int n_in,
                              void* d_out, int out_size) {
    const float* x       = (const float*)d_in[0];
    const float* noise   = (const float*)d_in[1];
    const float* slot_mu = (const float*)d_in[2];
    const float* slot_ls = (const float*)d_in[3];
    const float* Wp   = (const float*)d_in[4];
    const float* bp   = (const float*)d_in[5];
    const float* gin  = (const float*)d_in[6];
    const float* bin  = (const float*)d_in[7];
    const float* Wq   = (const float*)d_in[8];
    const float* bq   = (const float*)d_in[9];
    const float* Wk   = (const float*)d_in[10];
    const float* bk   = (const float*)d_in[11];
    const float* Wv   = (const float*)d_in[12];
    const float* bv   = (const float*)d_in[13];
    const float* W_ih = (const float*)d_in[14];
    const float* W_hh = (const float*)d_in[15];
    const float* b_ih = (const float*)d_in[16];
    const float* b_hh = (const float*)d_in[17];
    const float* W1   = (const float*)d_in[18];
    const float* b1   = (const float*)d_in[19];
    const float* W2   = (const float*)d_in[20];
    const float* b2   = (const float*)d_in[21];
    const float* gsl  = (const float*)d_in[22];
    const float* bsl  = (const float*)d_in[23];
    const float* gm   = (const float*)d_in[24];
    const float* bm   = (const float*)d_in[25];

    float* out_slots = (float*)d_out;
    float* out_attn  = out_slots + BB * KK * DD;

    cudaFuncSetAttribute(k_proj, cudaFuncAttributeMaxDynamicSharedMemorySize, SMEM_PROJ);
    cudaFuncSetAttribute(k_prep, cudaFuncAttributeMaxDynamicSharedMemorySize, SMEM_PREP);

    // launches: prep(0), proj(1), attn(2), update(3) -> ncu slot 3 = first k_update
    k_prep<<<304, 256, SMEM_PREP>>>(W_ih, W_hh, Wp, Wk, Wv,
                                    slot_mu, slot_ls, noise, Wq, bq, gsl, bsl);
    k_proj<<<dim3(NN / 128, BB), 256, SMEM_PROJ>>>(x, bp, gin, bin, bk, bv);

    for (int it = 0; it < N_ITERS; it++) {
        int last = (it == N_ITERS - 1);
        k_attn<<<dim3(NSPLIT, BB), 256>>>(out_attn, last);
        k_update<<<BB, 512>>>(b_ih, b_hh, W1, b1, W2, b2, gm, bm,
                              Wq, bq, gsl, bsl, out_slots, last);
    }
}

// round 16
// speedup vs baseline: 1.1627x; 1.0868x over previous
#include <cuda_runtime.h>
#include <cuda_bf16.h>
#include <math.h>

#define BB 64
#define CC 512
#define NN 1024
#define KK 8
#define DD 128
#define NSPLIT 8
#define N_ITERS 3

// ---------------- scratch (static device globals; no allocation) ----------------
__device__ float g_k[BB * NN * DD];
__device__ float g_v[BB * NN * DD];
__device__ float g_slots[BB * KK * DD];
__device__ float g_q[BB * KK * DD];
__device__ float g_upd[BB * NSPLIT * KK * DD];
__device__ float g_asum[BB * NSPLIT * KK];
__device__ float g_wihT[DD * 384];
__device__ float g_whhT[DD * 384];
__device__ __nv_bfloat16 g_Wph[DD * CC], g_Wpl[DD * CC];   // [d][c]
__device__ __nv_bfloat16 g_Wkh[DD * DD], g_Wkl[DD * DD];   // [d][j]
__device__ __nv_bfloat16 g_Wvh[DD * DD], g_Wvl[DD * DD];

__device__ __forceinline__ float sigf(float x) { return 1.0f / (1.0f + __expf(-x)); }
__device__ __forceinline__ float geluf(float x) { return 0.5f * x * (1.0f + erff(x * 0.70710678118654752f)); }

// ---------------- mma / ldmatrix / cp.async helpers ----------------
__device__ __forceinline__ unsigned smem_u32(const void* p) {
    unsigned a;
    asm("{ .reg .u64 tmp; cvta.to.shared.u64 tmp, %1; cvt.u32.u64 %0, tmp; }" : "=r"(a) : "l"(p));
    return a;
}
__device__ __forceinline__ void mma_bf16(float acc[4],
    unsigned a0, unsigned a1, unsigned a2, unsigned a3,
    unsigned b0, unsigned b1) {
    asm volatile(
        "mma.sync.aligned.m16n8k16.row.col.f32.bf16.bf16.f32 "
        "{%0,%1,%2,%3}, {%4,%5,%6,%7}, {%8,%9}, {%0,%1,%2,%3};"
        : "+f"(acc[0]), "+f"(acc[1]), "+f"(acc[2]), "+f"(acc[3])
        : "r"(a0), "r"(a1), "r"(a2), "r"(a3), "r"(b0), "r"(b1));
}
__device__ __forceinline__ void ldsm4(unsigned r[4], unsigned addr) {
    asm volatile("ldmatrix.sync.aligned.m8n8.x4.shared.b16 {%0,%1,%2,%3}, [%4];"
        : "=r"(r[0]), "=r"(r[1]), "=r"(r[2]), "=r"(r[3]) : "r"(addr));
}
#define CPA16(dst, src) asm volatile("cp.async.cg.shared.global [%0], [%1], 16;" :: "r"(dst), "l"(src))
#define CPA_COMMIT() asm volatile("cp.async.commit_group;" ::: "memory")
#define CPA_WAIT(n) asm volatile("cp.async.wait_group %0;" :: "n"(n) : "memory")

// streaming (evict_first) k/v loads: don't pollute L2, keep update weights resident
__device__ __forceinline__ unsigned long long mk_policy_ef() {
    unsigned long long pol;
    asm("createpolicy.fractional.L2::evict_first.b64 %0, 1.0;" : "=l"(pol));
    return pol;
}
__device__ __forceinline__ float4 ldg_ef4(const float* p, unsigned long long pol) {
    float4 v;
    asm volatile("ld.global.nc.L2::cache_hint.v4.f32 {%0,%1,%2,%3}, [%4], %5;"
        : "=f"(v.x), "=f"(v.y), "=f"(v.z), "=f"(v.w) : "l"(p), "l"(pol));
    return v;
}

__device__ __forceinline__ void split2(float f0, float f1, unsigned& vh, unsigned& vl) {
    __nv_bfloat162 h = __floats2bfloat162_rn(f0, f1);
    float r0 = f0 - __bfloat162float(h.x);
    float r1 = f1 - __bfloat162float(h.y);
    __nv_bfloat162 l = __floats2bfloat162_rn(r0, r1);
    vh = *(unsigned*)&h; vl = *(unsigned*)&l;
}

// swizzled byte address within a tile: row r, 16B-granule g.
template<int S> __device__ __forceinline__ unsigned swaddr(int r, int g) {
    if (S == 64)  return (unsigned)(r * 64  + ((g ^ ((r >> 1) & 3)) << 4));
    if (S == 128) return (unsigned)(r * 128 + ((g ^ (r & 7)) << 4));
    return (unsigned)(r * 256 + ((g ^ (r & 7)) << 4));
}

// one k16 step for 32n x 64d warp tile, 3-mma bf16 split; SA/SB = tile row bytes.
template<int SA, int SB>
__device__ __forceinline__ void mma_k16t(float (*acc)[8][4],
    unsigned aH, unsigned aL, unsigned bH, unsigned bL,
    int nr, int d0, int lane, int kkA, int kkB) {
    int lr = lane & 15;
    int half = lane >> 4;
    int gA = half + (kkA >> 3);
    int gB = half + (kkB >> 3);
    unsigned bh[4][4], bl[4][4];
#pragma unroll
    for (int db = 0; db < 4; db++) {
        unsigned ro = swaddr<SB>(d0 + db * 16 + lr, gB);
        ldsm4(bh[db], bH + ro);
        ldsm4(bl[db], bL + ro);
    }
#pragma unroll
    for (int nb = 0; nb < 2; nb++) {
        unsigned ra = swaddr<SA>(nr + nb * 16 + lr, gA);
        unsigned ah[4], al[4];
        ldsm4(ah, aH + ra);
        ldsm4(al, aL + ra);
#pragma unroll
        for (int db = 0; db < 4; db++) {
#pragma unroll
            for (int g = 0; g < 2; g++) {
                float* a4 = acc[nb][db * 2 + g];
                mma_bf16(a4, ah[0], ah[1], ah[2], ah[3], bh[db][g], bh[db][g + 2]);
                mma_bf16(a4, ah[0], ah[1], ah[2], ah[3], bl[db][g], bl[db][g + 2]);
                mma_bf16(a4, al[0], al[1], al[2], al[3], bh[db][g], bh[db][g + 2]);
            }
        }
    }
}

// ---------------- kernel 0: fused prep (transpose | cvt_w | init+q) ----------------
#define SMEM_PREP (DD * DD * 4 + KK * (DD + 1) * 4)
__global__ __launch_bounds__(256) void k_prep(
    const float* __restrict__ W_ih, const float* __restrict__ W_hh,
    const float* __restrict__ Wp, const float* __restrict__ Wk, const float* __restrict__ Wv,
    const float* __restrict__ mu, const float* __restrict__ lsig,
    const float* __restrict__ noise,
    const float* __restrict__ Wq, const float* __restrict__ bq,
    const float* __restrict__ gsl, const float* __restrict__ bsl) {
    extern __shared__ float smf[];
    __shared__ float ta[32][33];
    __shared__ float tb[32][33];
    int blk = blockIdx.x;
    int t = threadIdx.x;
    int tx = t & 31, ty = t >> 5;

    if (blk < 48) {
        int bx = blk % 12, by = blk / 12;
        int o0 = bx * 32, j0 = by * 32;
#pragma unroll
        for (int i = 0; i < 4; i++) {
            int o = o0 + ty + 8 * i;
            ta[ty + 8 * i][tx] = W_ih[(size_t)o * DD + j0 + tx];
            tb[ty + 8 * i][tx] = W_hh[(size_t)o * DD + j0 + tx];
        }
        __syncthreads();
#pragma unroll
        for (int i = 0; i < 4; i++) {
            int j = j0 + ty + 8 * i;
            g_wihT[(size_t)j * 384 + o0 + tx] = ta[tx][ty + 8 * i];
            g_whhT[(size_t)j * 384 + o0 + tx] = tb[tx][ty + 8 * i];
        }
    } else if (blk < 240) {
        int idx = blk - 48;
        int z = idx / 64, rem = idx % 64;
        int c0 = (rem % 16) * 32, d0 = (rem / 16) * 32;
        int Cdim = z == 0 ? CC : DD;
        if (c0 >= Cdim) return;
        const float* src = z == 0 ? Wp : (z == 1 ? Wk : Wv);
        __nv_bfloat16* dsth = z == 0 ? g_Wph : (z == 1 ? g_Wkh : g_Wvh);
        __nv_bfloat16* dstl = z == 0 ? g_Wpl : (z == 1 ? g_Wkl : g_Wvl);
#pragma unroll
        for (int i = 0; i < 4; i++)
            ta[ty + 8 * i][tx] = src[(size_t)(c0 + ty + 8 * i) * DD + d0 + tx];
        __syncthreads();
#pragma unroll
        for (int i = 0; i < 4; i++) {
            int d = d0 + ty + 8 * i;
            float f = ta[tx][ty + 8 * i];
            __nv_bfloat16 h = __float2bfloat16(f);
            __nv_bfloat16 l = __float2bfloat16(f - __bfloat162float(h));
            dsth[(size_t)d * Cdim + c0 + tx] = h;
            dstl[(size_t)d * Cdim + c0 + tx] = l;
        }
    } else {
        int b = blk - 240;
        float* Wqs = smf;
        float (*sl)[DD + 1] = (float (*)[DD + 1])(smf + DD * DD);
        const float SCALE = 0.08838834764831845f;
#pragma unroll
        for (int i = 0; i < 16; i++)
            ((float4*)Wqs)[t + i * 256] = ((const float4*)Wq)[t + i * 256];
        for (int i = t; i < KK * DD; i += 256) {
            float v = mu[i] + __expf(lsig[i]) * noise[(size_t)b * KK * DD + i];
            g_slots[(size_t)b * KK * DD + i] = v;
            sl[i >> 7][i & 127] = v;
        }
        __syncthreads();
        {
            int row = ty;
            float s = 0.f, s2 = 0.f, vr[4];
#pragma unroll
            for (int i = 0; i < 4; i++) {
                float val = sl[row][tx * 4 + i];
                vr[i] = val; s += val; s2 += val * val;
            }
#pragma unroll
            for (int off = 16; off; off >>= 1) {
                s += __shfl_xor_sync(0xffffffffu, s, off);
                s2 += __shfl_xor_sync(0xffffffffu, s2, off);
            }
            float m = s * (1.0f / 128.0f);
            float var = s2 * (1.0f / 128.0f) - m * m;
            float inv = rsqrtf(var + 1e-5f);
#pragma unroll
            for (int i = 0; i < 4; i++) {
                int d = tx * 4 + i;
                sl[row][d] = (vr[i] - m) * inv * gsl[d] + bsl[d];
            }
        }
        __syncthreads();
        int d = t & 127, rh = t >> 7;
        float acc[4] = {0.f, 0.f, 0.f, 0.f};
#pragma unroll 8
        for (int j = 0; j < DD; j++) {
            float w = Wqs[j * DD + d];
#pragma unroll
            for (int rr = 0; rr < 4; rr++) acc[rr] = fmaf(sl[rh * 4 + rr][j], w, acc[rr]);
        }
#pragma unroll
        for (int rr = 0; rr < 4; rr++)
            g_q[((size_t)b * KK + rh * 4 + rr) * DD + d] = (acc[rr] + bq[d]) * SCALE;
    }
}

// ---------------- kernel 1: proj + LN + k/v (x converted in-kernel) ----------------
#define XS_SZ 16896
#define SL_AH 16896
#define SL_AL 25088
#define SL_BH 33280
#define SL_BL 41472
#define SLOT 49664
#define AF_L 32768
#define BF_OFF 65536
#define BF_L 16384
#define SMEM_PROJ 99328

__device__ __forceinline__ void writeout(float (*acc)[8][4], float* out, const float* bias,
                                         int nr, int d0, int lane) {
#pragma unroll
    for (int nb = 0; nb < 2; nb++)
#pragma unroll
        for (int u = 0; u < 8; u++) {
            int row = nr + nb * 16 + (lane >> 2);
            int dc = d0 + u * 8 + (lane & 3) * 2;
            *(float2*)(out + (size_t)row * DD + dc) =
                make_float2(acc[nb][u][0] + bias[dc], acc[nb][u][1] + bias[dc + 1]);
            *(float2*)(out + (size_t)(row + 8) * DD + dc) =
                make_float2(acc[nb][u][2] + bias[dc], acc[nb][u][3] + bias[dc + 1]);
        }
}

__global__ __launch_bounds__(256, 2) void k_proj(
    const float* __restrict__ x,
    const float* __restrict__ bp,
    const float* __restrict__ gin, const float* __restrict__ bin,
    const float* __restrict__ bk, const float* __restrict__ bv) {
    extern __shared__ char sm[];
    __shared__ float bp_s[DD], gin_s[DD], bin_s[DD], bk_s[DD], bv_s[DD];
    __shared__ float mean_s[128], istd_s[128];
    __shared__ float ps[2][128], ps2[2][128];

    const int t = threadIdx.x, lane = t & 31, wid = t >> 5;
    const int warpX = wid >> 2, warpY = wid & 3;
    const int d0 = warpX * 64, nr = warpY * 32;
    const int b = blockIdx.y, n0 = blockIdx.x * 128;
    const unsigned smb = smem_u32(sm);

    if (t < DD) {
        bp_s[t] = bp[t]; gin_s[t] = gin[t]; bin_s[t] = bin[t];
        bk_s[t] = bk[t]; bv_s[t] = bv[t];
    }

    const float* xb = x + (size_t)b * CC * NN + n0;

    float acc[2][8][4];
#pragma unroll
    for (int nb = 0; nb < 2; nb++)
#pragma unroll
        for (int u = 0; u < 8; u++)
#pragma unroll
            for (int j = 0; j < 4; j++) acc[nb][u][j] = 0.f;

    auto stage1 = [&](int c, int sel) {
        unsigned base = smb + sel * SLOT;
        int c0 = c * 32;
#pragma unroll
        for (int it = 0; it < 4; it++) {
            int idx = t + it * 256;
            int row = idx >> 5, g = idx & 31;
            CPA16(base + row * 528 + g * 16, xb + (size_t)(c0 + row) * NN + g * 4);
        }
#pragma unroll
        for (int it = 0; it < 2; it++) {
            int idx = t + it * 256;
            int row = idx >> 2, g = idx & 3;
            unsigned so = swaddr<64>(row, g);
            size_t go = (size_t)row * CC + c0 + g * 8;
            CPA16(base + SL_BH + so, g_Wph + go);
            CPA16(base + SL_BL + so, g_Wpl + go);
        }
        CPA_COMMIT();
    };
    auto convert1 = [&](int sel) {
        char* sb = sm + sel * SLOT;
#pragma unroll
        for (int it = 0; it < 8; it++) {
            int idx = t + it * 256;
            int n = idx & 127, p = idx >> 7;
            float f0 = *(const float*)(sb + (2 * p) * 528 + n * 4);
            float f1 = *(const float*)(sb + (2 * p + 1) * 528 + n * 4);
            unsigned vh, vl; split2(f0, f1, vh, vl);
            unsigned off = swaddr<64>(n, p >> 2) + (p & 3) * 4;
            *(unsigned*)(sb + SL_AH + off) = vh;
            *(unsigned*)(sb + SL_AL + off) = vl;
        }
    };
    auto stageB = [&](const __nv_bfloat16* Wh, const __nv_bfloat16* Wl, int j0) {
#pragma unroll
        for (int it = 0; it < 4; it++) {
            int idx = t + it * 256;
            int row = idx >> 3, g = idx & 7;
            unsigned so = swaddr<128>(row, g);
            size_t go = (size_t)row * DD + j0 + g * 8;
            CPA16(smb + BF_OFF + so, Wh + go);
            CPA16(smb + BF_OFF + BF_L + so, Wl + go);
        }
        CPA_COMMIT();
    };

    // ---- phase 1 ----
    stage1(0, 0);
    stage1(1, 1);
#pragma unroll 1
    for (int c = 0; c < 16; c++) {
        CPA_WAIT(1);
        __syncthreads();
        int sel = c & 1;
        convert1(sel);
        __syncthreads();
        unsigned base = smb + sel * SLOT;
        mma_k16t<64, 64>(acc, base + SL_AH, base + SL_AL, base + SL_BH, base + SL_BL,
                         nr, d0, lane, 0, 0);
        mma_k16t<64, 64>(acc, base + SL_AH, base + SL_AL, base + SL_BH, base + SL_BL,
                         nr, d0, lane, 16, 16);
        __syncthreads();
        if (c + 2 < 16) stage1(c + 2, sel);
        else CPA_COMMIT();
    }
    stageB(g_Wkh, g_Wkl, 0);

    // ---- LN from accumulators ----
    {
        float rs[4] = {0.f, 0.f, 0.f, 0.f}, rs2[4] = {0.f, 0.f, 0.f, 0.f};
#pragma unroll
        for (int nb = 0; nb < 2; nb++)
#pragma unroll
            for (int u = 0; u < 8; u++) {
                int dc = d0 + u * 8 + (lane & 3) * 2;
                float v0 = acc[nb][u][0] + bp_s[dc];
                float v1 = acc[nb][u][1] + bp_s[dc + 1];
                float v2 = acc[nb][u][2] + bp_s[dc];
                float v3 = acc[nb][u][3] + bp_s[dc + 1];
                rs[nb * 2] += v0 + v1;       rs2[nb * 2] += v0 * v0 + v1 * v1;
                rs[nb * 2 + 1] += v2 + v3;   rs2[nb * 2 + 1] += v2 * v2 + v3 * v3;
            }
#pragma unroll
        for (int off = 1; off <= 2; off <<= 1)
#pragma unroll
            for (int i = 0; i < 4; i++) {
                rs[i] += __shfl_xor_sync(0xffffffffu, rs[i], off);
                rs2[i] += __shfl_xor_sync(0xffffffffu, rs2[i], off);
            }
        if ((lane & 3) == 0) {
#pragma unroll
            for (int i = 0; i < 4; i++) {
                int row = nr + (i >> 1) * 16 + (i & 1) * 8 + (lane >> 2);
                ps[warpX][row] = rs[i];
                ps2[warpX][row] = rs2[i];
            }
        }
    }
    __syncthreads();
    if (t < 128) {
        float s = ps[0][t] + ps[1][t];
        float s2 = ps2[0][t] + ps2[1][t];
        float m = s * (1.0f / 128.0f);
        float var = s2 * (1.0f / 128.0f) - m * m;
        mean_s[t] = m;
        istd_s[t] = rsqrtf(var + 1e-5f);
    }
    __syncthreads();

    // ---- write LN output as bf16 hi/lo into A-full ----
#pragma unroll
    for (int nb = 0; nb < 2; nb++)
#pragma unroll
        for (int u = 0; u < 8; u++) {
            int dc = d0 + u * 8 + (lane & 3) * 2;
            int r0 = nr + nb * 16 + (lane >> 2), r1 = r0 + 8;
            float m0 = mean_s[r0], i0 = istd_s[r0];
            float m1 = mean_s[r1], i1 = istd_s[r1];
            float f0 = (acc[nb][u][0] + bp_s[dc] - m0) * i0 * gin_s[dc] + bin_s[dc];
            float f1 = (acc[nb][u][1] + bp_s[dc + 1] - m0) * i0 * gin_s[dc + 1] + bin_s[dc + 1];
            float f2 = (acc[nb][u][2] + bp_s[dc] - m1) * i1 * gin_s[dc] + bin_s[dc];
            float f3 = (acc[nb][u][3] + bp_s[dc + 1] - m1) * i1 * gin_s[dc + 1] + bin_s[dc + 1];
            unsigned vh, vl;
            unsigned o0 = swaddr<256>(r0, dc >> 3) + (dc & 7) * 2;
            split2(f0, f1, vh, vl);
            *(unsigned*)(sm + o0) = vh;
            *(unsigned*)(sm + AF_L + o0) = vl;
            unsigned o1 = swaddr<256>(r1, dc >> 3) + (dc & 7) * 2;
            split2(f2, f3, vh, vl);
            *(unsigned*)(sm + o1) = vh;
            *(unsigned*)(sm + AF_L + o1) = vl;
        }
    __syncthreads();

    // ---- phases 2/3 ----
    unsigned aH = smb, aL = smb + AF_L, bH = smb + BF_OFF, bL = smb + BF_OFF + BF_L;
    float acc2[2][8][4];
#pragma unroll
    for (int nb = 0; nb < 2; nb++)
#pragma unroll
        for (int u = 0; u < 8; u++)
#pragma unroll
            for (int j = 0; j < 4; j++) acc2[nb][u][j] = 0.f;
    CPA_WAIT(0); __syncthreads();
#pragma unroll
    for (int kk = 0; kk < 64; kk += 16)
        mma_k16t<256, 128>(acc2, aH, aL, bH, bL, nr, d0, lane, kk, kk);
    __syncthreads();
    stageB(g_Wkh, g_Wkl, 64);
    CPA_WAIT(0); __syncthreads();
#pragma unroll
    for (int kk = 0; kk < 64; kk += 16)
        mma_k16t<256, 128>(acc2, aH, aL, bH, bL, nr, d0, lane, 64 + kk, kk);
    __syncthreads();
    stageB(g_Wvh, g_Wvl, 0);
    writeout(acc2, g_k + ((size_t)b * NN + n0) * DD, bk_s, nr, d0, lane);
#pragma unroll
    for (int nb = 0; nb < 2; nb++)
#pragma unroll
        for (int u = 0; u < 8; u++)
#pragma unroll
            for (int j = 0; j < 4; j++) acc2[nb][u][j] = 0.f;
    CPA_WAIT(0); __syncthreads();
#pragma unroll
    for (int kk = 0; kk < 64; kk += 16)
        mma_k16t<256, 128>(acc2, aH, aL, bH, bL, nr, d0, lane, kk, kk);
    __syncthreads();
    stageB(g_Wvh, g_Wvl, 64);
    CPA_WAIT(0); __syncthreads();
#pragma unroll
    for (int kk = 0; kk < 64; kk += 16)
        mma_k16t<256, 128>(acc2, aH, aL, bH, bL, nr, d0, lane, 64 + kk, kk);
    writeout(acc2, g_v + ((size_t)b * NN + n0) * DD, bv_s, nr, d0, lane);
}

// ---------------- kernel 2: attention (k/v streamed with evict_first) ----------------
__global__ __launch_bounds__(256) void k_attn(float* __restrict__ attn_out, int write_attn) {
    __shared__ float updp[8][KK * DD];
    __shared__ float asums[8][KK];
    __shared__ float atile[8][KK][16];

    int b = blockIdx.y, split = blockIdx.x;
    int t = threadIdx.x, lane = t & 31, w = t >> 5;
    int n0 = split * (NN / NSPLIT);
    int nb = n0 + w * 16;
    const unsigned long long pol = mk_policy_ef();

    const float* qp = g_q + (size_t)b * KK * DD + lane * 4;
    float qreg[KK][4];
#pragma unroll
    for (int s = 0; s < KK; s++) {
        float4 qv = *(const float4*)(qp + s * DD);
        qreg[s][0] = qv.x; qreg[s][1] = qv.y; qreg[s][2] = qv.z; qreg[s][3] = qv.w;
    }
    float upd[KK][4];
    float asum[KK];
#pragma unroll
    for (int s = 0; s < KK; s++) {
        asum[s] = 0.f;
#pragma unroll
        for (int j = 0; j < 4; j++) upd[s][j] = 0.f;
    }

    const float* kb = g_k + ((size_t)b * NN + nb) * DD + lane * 4;
    const float* vb = g_v + ((size_t)b * NN + nb) * DD + lane * 4;
    float4 kc = ldg_ef4(kb, pol);
    float4 vc = ldg_ef4(vb, pol);

#pragma unroll 4
    for (int i = 0; i < 16; i++) {
        float4 kn = kc, vn = vc;
        if (i < 15) {
            kn = ldg_ef4(kb + (i + 1) * DD, pol);
            vn = ldg_ef4(vb + (i + 1) * DD, pol);
        }
        float lg[KK];
#pragma unroll
        for (int s = 0; s < KK; s++)
            lg[s] = qreg[s][0] * kc.x + qreg[s][1] * kc.y + qreg[s][2] * kc.z + qreg[s][3] * kc.w;
#pragma unroll
        for (int off = 16; off; off >>= 1)
#pragma unroll
            for (int s = 0; s < KK; s++) lg[s] += __shfl_xor_sync(0xffffffffu, lg[s], off);
        float mx = lg[0];
#pragma unroll
        for (int s = 1; s < KK; s++) mx = fmaxf(mx, lg[s]);
        float ssum = 0.f;
#pragma unroll
        for (int s = 0; s < KK; s++) { lg[s] = __expf(lg[s] - mx); ssum += lg[s]; }
        float inv = 1.0f / ssum;
#pragma unroll
        for (int s = 0; s < KK; s++) {
            lg[s] *= inv;
            asum[s] += lg[s];
            upd[s][0] = fmaf(lg[s], vc.x, upd[s][0]);
            upd[s][1] = fmaf(lg[s], vc.y, upd[s][1]);
            upd[s][2] = fmaf(lg[s], vc.z, upd[s][2]);
            upd[s][3] = fmaf(lg[s], vc.w, upd[s][3]);
        }
        if (write_attn && lane < 8) {
            float av = lane == 0 ? lg[0] : lane == 1 ? lg[1] : lane == 2 ? lg[2] :
                       lane == 3 ? lg[3] : lane == 4 ? lg[4] : lane == 5 ? lg[5] :
                       lane == 6 ? lg[6] : lg[7];
            atile[w][lane][i] = av;
        }
        kc = kn; vc = vn;
    }
#pragma unroll
    for (int s = 0; s < KK; s++)
        *(float4*)&updp[w][s * DD + lane * 4] =
            make_float4(upd[s][0], upd[s][1], upd[s][2], upd[s][3]);
    if (lane == 0) {
#pragma unroll
        for (int s = 0; s < KK; s++) asums[w][s] = asum[s];
    }
    __syncthreads();
    for (int idx = t; idx < KK * DD; idx += 256) {
        float s = 0.f;
#pragma unroll
        for (int ww = 0; ww < 8; ww++) s += updp[ww][idx];
        g_upd[((size_t)b * NSPLIT + split) * KK * DD + idx] = s;
    }
    if (t < KK) {
        float s = 0.f;
#pragma unroll
        for (int ww = 0; ww < 8; ww++) s += asums[ww][t];
        g_asum[((size_t)b * NSPLIT + split) * KK + t] = s;
    }
    if (write_attn) {
        for (int idx = t; idx < KK * (NN / NSPLIT); idx += 256) {
            int s = idx >> 7, n = idx & 127;
            attn_out[((size_t)b * KK + s) * NN + n0 + n] = atile[n >> 4][s][n & 15];
        }
    }
}

// ---------------- kernel 3: updates + GRU + MLP + next-iter q (1024 thr, K-split) ----------------
// dynamic smem floats: us[1024] | hs[1024] | pgx[2*3072] | pgh[2*3072] | astot[8]
#define UPD_US 0
#define UPD_HS 1024
#define UPD_PGX 2048
#define UPD_PGH 8192
#define UPD_AST 14336
#define SMEM_UPD ((14336 + 16) * 4)
__global__ __launch_bounds__(1024) void k_update(
    const float* __restrict__ b_ih, const float* __restrict__ b_hh,
    const float* __restrict__ W1, const float* __restrict__ b1,
    const float* __restrict__ W2, const float* __restrict__ b2,
    const float* __restrict__ gm, const float* __restrict__ bm,
    const float* __restrict__ Wq, const float* __restrict__ bq,
    const float* __restrict__ gsl, const float* __restrict__ bsl,
    float* __restrict__ slots_out, int last) {
    extern __shared__ float su[];
    float* us = su + UPD_US;
    float* hs = su + UPD_HS;
    float* pgx = su + UPD_PGX;       // GRU x-partials, then h1s (2048) + q partials
    float* pgh = su + UPD_PGH;       // GRU h-partials, then W1 partials, W2 partials, lnq
    float* astot = su + UPD_AST;
    float* ns = us;
    float* lns = hs;
    float* h1s = pgx;                // [8*256]
    float* fs = hs;
    float* lnq = pgh;                // [8*128] (free after W2 combine)

    int b = blockIdx.x;
    int t = threadIdx.x;
    int wid = t >> 5, lane = t & 31;

    // ---- A: attn-sum totals, load slots, reduce split partials ----
    if (t < KK) {
        float s = 0.f;
        for (int sp = 0; sp < NSPLIT; sp++) s += g_asum[((size_t)b * NSPLIT + sp) * KK + t];
        astot[t] = s + 1e-8f;
    }
    hs[t] = g_slots[(size_t)b * KK * DD + t];
    __syncthreads();
    {
        float s = 0.f;
#pragma unroll
        for (int sp = 0; sp < NSPLIT; sp++)
            s += g_upd[((size_t)b * NSPLIT + sp) * KK * DD + t];
        us[t] = s / astot[t >> 7];
    }
    __syncthreads();

    // ---- B: GRU gate partials (768 threads = 384 o x 2 K-halves, 8 chains x 64) ----
    if (t < 768) {
        int o = t % 384, jh = t / 384;
        float accx[KK], acch[KK];
#pragma unroll
        for (int r = 0; r < KK; r++) { accx[r] = 0.f; acch[r] = 0.f; }
        const float* wi = g_wihT + (size_t)(jh * 64) * 384 + o;
        const float* wh = g_whhT + (size_t)(jh * 64) * 384 + o;
        int j0 = jh * 64;
#pragma unroll 8
        for (int j2 = 0; j2 < 64; j2++) {
            float wa = wi[(size_t)j2 * 384];
            float wb = wh[(size_t)j2 * 384];
            int j = j0 + j2;
#pragma unroll
            for (int r = 0; r < KK; r++) {
                accx[r] = fmaf(us[r * DD + j], wa, accx[r]);
                acch[r] = fmaf(hs[r * DD + j], wb, acch[r]);
            }
        }
#pragma unroll
        for (int r = 0; r < KK; r++) {
            pgx[jh * 3072 + r * 384 + o] = accx[r];
            pgh[jh * 3072 + r * 384 + o] = acch[r];
        }
    }
    __syncthreads();

    // ---- C: combine + gates -> ns ----
    {
        int r = t >> 7, d = t & 127;
        float xr = pgx[r * 384 + d] + pgx[3072 + r * 384 + d] + b_ih[d];
        float hr = pgh[r * 384 + d] + pgh[3072 + r * 384 + d] + b_hh[d];
        float xz = pgx[r * 384 + 128 + d] + pgx[3072 + r * 384 + 128 + d] + b_ih[128 + d];
        float hz = pgh[r * 384 + 128 + d] + pgh[3072 + r * 384 + 128 + d] + b_hh[128 + d];
        float xn = pgx[r * 384 + 256 + d] + pgx[3072 + r * 384 + 256 + d] + b_ih[256 + d];
        float hn = pgh[r * 384 + 256 + d] + pgh[3072 + r * 384 + 256 + d] + b_hh[256 + d];
        float rg = sigf(xr + hr);
        float zg = sigf(xz + hz);
        float ng = tanhf(xn + rg * hn);
        float nsv = (1.0f - zg) * ng + zg * hs[t];
        __syncthreads();                    // all pgx/pgh reads done before ns overwrites us
        ns[t] = nsv;
    }
    __syncthreads();

    // ---- D: LN(ns) -> lns (8 warps, one row each) ----
    if (wid < KK) {
        int row = wid;
        float s = 0.f, s2 = 0.f, vr[4];
#pragma unroll
        for (int i = 0; i < 4; i++) {
            float val = ns[row * DD + lane * 4 + i];
            vr[i] = val; s += val; s2 += val * val;
        }
#pragma unroll
        for (int off = 16; off; off >>= 1) {
            s += __shfl_xor_sync(0xffffffffu, s, off);
            s2 += __shfl_xor_sync(0xffffffffu, s2, off);
        }
        float m = s * (1.0f / 128.0f);
        float var = s2 * (1.0f / 128.0f) - m * m;
        float inv = rsqrtf(var + 1e-5f);
#pragma unroll
        for (int i = 0; i < 4; i++) {
            int d = lane * 4 + i;
            lns[row * DD + d] = (vr[i] - m) * inv * gm[d] + bm[d];
        }
    }
    __syncthreads();

    // ---- E: W1 partials (512 threads = 256 o x 2 K-halves, 8 chains x 64) ----
    if (t < 512) {
        int o = t & 255, jh = t >> 8;
        float acc[KK];
#pragma unroll
        for (int r = 0; r < KK; r++) acc[r] = 0.f;
        int j0 = jh * 64;
#pragma unroll 8
        for (int j2 = 0; j2 < 64; j2++) {
            float w = W1[(size_t)(j0 + j2) * 256 + o];
#pragma unroll
            for (int r = 0; r < KK; r++) acc[r] = fmaf(lns[r * DD + j0 + j2], w, acc[r]);
        }
#pragma unroll
        for (int r = 0; r < KK; r++) pgh[jh * 2048 + r * 256 + o] = acc[r];
    }
    __syncthreads();

    // ---- F: h1 = gelu(combine + b1) ----
#pragma unroll
    for (int i2 = t; i2 < 2048; i2 += 1024) {
        int o = i2 & 255;
        h1s[i2] = geluf(pgh[i2] + pgh[2048 + i2] + b1[o]);
    }
    __syncthreads();

    // ---- G: W2 partials (1024 threads = 128 d x 4 row-pairs x 2 K-halves) ----
    {
        int d = t & 127, seg = t >> 7;
        int rg = seg & 3, jh = seg >> 2;
        int j0 = jh * 128;
        float acc[2] = {0.f, 0.f};
#pragma unroll 8
        for (int j2 = 0; j2 < 128; j2++) {
            float w = W2[(size_t)(j0 + j2) * DD + d];
#pragma unroll
            for (int i = 0; i < 2; i++)
                acc[i] = fmaf(h1s[(rg * 2 + i) * 256 + j0 + j2], w, acc[i]);
        }
#pragma unroll
        for (int i = 0; i < 2; i++)
            pgh[jh * 1024 + (rg * 2 + i) * DD + d] = acc[i];
    }
    __syncthreads();

    // ---- H: combine + writeback slots ----
    {
        int d = t & 127;
        float val = ns[t] + pgh[t] + pgh[1024 + t] + b2[d];
        __syncthreads();        // pgh reads done before lnq aliases it
        g_slots[(size_t)b * KK * DD + t] = val;
        fs[t] = val;            // fs=hs; lns fully consumed in E
        if (last) slots_out[(size_t)b * KK * DD + t] = val;
    }
    __syncthreads();

    // ---- I: next-iteration q ----
    if (!last) {
        const float SCALE = 0.08838834764831845f;
        if (wid < KK) {
            int row = wid;
            float s = 0.f, s2 = 0.f, vr[4];
#pragma unroll
            for (int i = 0; i < 4; i++) {
                float val = fs[row * DD + lane * 4 + i];
                vr[i] = val; s += val; s2 += val * val;
            }
#pragma unroll
            for (int off = 16; off; off >>= 1) {
                s += __shfl_xor_sync(0xffffffffu, s, off);
                s2 += __shfl_xor_sync(0xffffffffu, s2, off);
            }
            float m = s * (1.0f / 128.0f);
            float var = s2 * (1.0f / 128.0f) - m * m;
            float inv = rsqrtf(var + 1e-5f);
#pragma unroll
            for (int i = 0; i < 4; i++) {
                int d = lane * 4 + i;
                lnq[row * DD + d] = (vr[i] - m) * inv * gsl[d] + bsl[d];
            }
        }
        __syncthreads();
        // q partials: 1024 = 128 d x 4 row-pairs x 2 K-halves (2 chains x 64)
        {
            int d = t & 127, seg = t >> 7;
            int rg = seg & 3, jh = seg >> 2;
            int j0 = jh * 64;
            float acc[2] = {0.f, 0.f};
#pragma unroll 8
            for (int j2 = 0; j2 < 64; j2++) {
                float w = Wq[(size_t)(j0 + j2) * DD + d];
#pragma unroll
                for (int i = 0; i < 2; i++)
                    acc[i] = fmaf(lnq[(rg * 2 + i) * DD + j0 + j2], w, acc[i]);
            }
#pragma unroll
            for (int i = 0; i < 2; i++)
                pgx[jh * 1024 + (rg * 2 + i) * DD + d] = acc[i];
        }
        __syncthreads();
        {
            int d = t & 127;
            g_q[(size_t)b * KK * DD + t] = (pgx[t] + pgx[1024 + t] + bq[d]) * SCALE;
        }
    }
}

// ---------------- launcher ----------------
extern "C" void kernel_launch(void* const* d_in, const int* in_sizes, int n_in,
                              void* d_out, int out_size) {
    const float* x       = (const float*)d_in[0];
    const float* noise   = (const float*)d_in[1];
    const float* slot_mu = (const float*)d_in[2];
    const float* slot_ls = (const float*)d_in[3];
    const float* Wp   = (const float*)d_in[4];
    const float* bp   = (const float*)d_in[5];
    const float* gin  = (const float*)d_in[6];
    const float* bin  = (const float*)d_in[7];
    const float* Wq   = (const float*)d_in[8];
    const float* bq   = (const float*)d_in[9];
    const float* Wk   = (const float*)d_in[10];
    const float* bk   = (const float*)d_in[11];
    const float* Wv   = (const float*)d_in[12];
    const float* bv   = (const float*)d_in[13];
    const float* W_ih = (const float*)d_in[14];
    const float* W_hh = (const float*)d_in[15];
    const float* b_ih = (const float*)d_in[16];
    const float* b_hh = (const float*)d_in[17];
    const float* W1   = (const float*)d_in[18];
    const float* b1   = (const float*)d_in[19];
    const float* W2   = (const float*)d_in[20];
    const float* b2   = (const float*)d_in[21];
    const float* gsl  = (const float*)d_in[22];
    const float* bsl  = (const float*)d_in[23];
    const float* gm   = (const float*)d_in[24];
    const float* bm   = (const float*)d_in[25];

    float* out_slots = (float*)d_out;
    float* out_attn  = out_slots + BB * KK * DD;

    cudaFuncSetAttribute(k_proj, cudaFuncAttributeMaxDynamicSharedMemorySize, SMEM_PROJ);
    cudaFuncSetAttribute(k_prep, cudaFuncAttributeMaxDynamicSharedMemorySize, SMEM_PREP);
    cudaFuncSetAttribute(k_update, cudaFuncAttributeMaxDynamicSharedMemorySize, SMEM_UPD);

    // launches: prep(0), proj(1), attn(2), update(3) -> ncu slot 3 = first k_update
    k_prep<<<304, 256, SMEM_PREP>>>(W_ih, W_hh, Wp, Wk, Wv,
                                    slot_mu, slot_ls, noise, Wq, bq, gsl, bsl);
    k_proj<<<dim3(NN / 128, BB), 256, SMEM_PROJ>>>(x, bp, gin, bin, bk, bv);

    for (int it = 0; it < N_ITERS; it++) {
        int last = (it == N_ITERS - 1);
        k_attn<<<dim3(NSPLIT, BB), 256>>>(out_attn, last);
        k_update<<<BB, 1024, SMEM_UPD>>>(b_ih, b_hh, W1, b1, W2, b2, gm, bm,
                                         Wq, bq, gsl, bsl, out_slots, last);
    }
}

// round 17
// speedup vs baseline: 1.1748x; 1.0104x over previous
#include <cuda_runtime.h>
#include <cuda_bf16.h>
#include <math.h>

#define BB 64
#define CC 512
#define NN 1024
#define KK 8
#define DD 128
#define NSPLIT 8
#define N_ITERS 3

// ---------------- scratch (static device globals; no allocation) ----------------
__device__ float g_k[BB * NN * DD];
__device__ float g_v[BB * NN * DD];
__device__ float g_slots[BB * KK * DD];
__device__ float g_q[BB * KK * DD];
__device__ float g_upd[BB * NSPLIT * KK * DD];
__device__ float g_asum[BB * NSPLIT * KK];
__device__ float g_wihT[DD * 384];
__device__ float g_whhT[DD * 384];
__device__ float g_sink;
__device__ __nv_bfloat16 g_Wph[DD * CC], g_Wpl[DD * CC];   // [d][c]
__device__ __nv_bfloat16 g_Wkh[DD * DD], g_Wkl[DD * DD];   // [d][j]
__device__ __nv_bfloat16 g_Wvh[DD * DD], g_Wvl[DD * DD];

__device__ __forceinline__ float sigf(float x) { return 1.0f / (1.0f + __expf(-x)); }
__device__ __forceinline__ float geluf(float x) { return 0.5f * x * (1.0f + erff(x * 0.70710678118654752f)); }

// ---------------- mma / ldmatrix / cp.async helpers ----------------
__device__ __forceinline__ unsigned smem_u32(const void* p) {
    unsigned a;
    asm("{ .reg .u64 tmp; cvta.to.shared.u64 tmp, %1; cvt.u32.u64 %0, tmp; }" : "=r"(a) : "l"(p));
    return a;
}
__device__ __forceinline__ void mma_bf16(float acc[4],
    unsigned a0, unsigned a1, unsigned a2, unsigned a3,
    unsigned b0, unsigned b1) {
    asm volatile(
        "mma.sync.aligned.m16n8k16.row.col.f32.bf16.bf16.f32 "
        "{%0,%1,%2,%3}, {%4,%5,%6,%7}, {%8,%9}, {%0,%1,%2,%3};"
        : "+f"(acc[0]), "+f"(acc[1]), "+f"(acc[2]), "+f"(acc[3])
        : "r"(a0), "r"(a1), "r"(a2), "r"(a3), "r"(b0), "r"(b1));
}
__device__ __forceinline__ void ldsm4(unsigned r[4], unsigned addr) {
    asm volatile("ldmatrix.sync.aligned.m8n8.x4.shared.b16 {%0,%1,%2,%3}, [%4];"
        : "=r"(r[0]), "=r"(r[1]), "=r"(r[2]), "=r"(r[3]) : "r"(addr));
}
#define CPA16(dst, src) asm volatile("cp.async.cg.shared.global [%0], [%1], 16;" :: "r"(dst), "l"(src))
#define CPA_COMMIT() asm volatile("cp.async.commit_group;" ::: "memory")
#define CPA_WAIT(n) asm volatile("cp.async.wait_group %0;" :: "n"(n) : "memory")

// streaming (evict_first) k/v loads
__device__ __forceinline__ unsigned long long mk_policy_ef() {
    unsigned long long pol;
    asm("createpolicy.fractional.L2::evict_first.b64 %0, 1.0;" : "=l"(pol));
    return pol;
}
// resident (evict_last) warming loads
__device__ __forceinline__ unsigned long long mk_policy_el() {
    unsigned long long pol;
    asm("createpolicy.fractional.L2::evict_last.b64 %0, 1.0;" : "=l"(pol));
    return pol;
}
__device__ __forceinline__ float4 ldg_pol4(const float* p, unsigned long long pol) {
    float4 v;
    asm volatile("ld.global.nc.L2::cache_hint.v4.f32 {%0,%1,%2,%3}, [%4], %5;"
        : "=f"(v.x), "=f"(v.y), "=f"(v.z), "=f"(v.w) : "l"(p), "l"(pol));
    return v;
}

__device__ __forceinline__ void split2(float f0, float f1, unsigned& vh, unsigned& vl) {
    __nv_bfloat162 h = __floats2bfloat162_rn(f0, f1);
    float r0 = f0 - __bfloat162float(h.x);
    float r1 = f1 - __bfloat162float(h.y);
    __nv_bfloat162 l = __floats2bfloat162_rn(r0, r1);
    vh = *(unsigned*)&h; vl = *(unsigned*)&l;
}

// swizzled byte address within a tile: row r, 16B-granule g.
template<int S> __device__ __forceinline__ unsigned swaddr(int r, int g) {
    if (S == 64)  return (unsigned)(r * 64  + ((g ^ ((r >> 1) & 3)) << 4));
    if (S == 128) return (unsigned)(r * 128 + ((g ^ (r & 7)) << 4));
    return (unsigned)(r * 256 + ((g ^ (r & 7)) << 4));
}

// one k16 step for 32n x 64d warp tile, 3-mma bf16 split; SA/SB = tile row bytes.
template<int SA, int SB>
__device__ __forceinline__ void mma_k16t(float (*acc)[8][4],
    unsigned aH, unsigned aL, unsigned bH, unsigned bL,
    int nr, int d0, int lane, int kkA, int kkB) {
    int lr = lane & 15;
    int half = lane >> 4;
    int gA = half + (kkA >> 3);
    int gB = half + (kkB >> 3);
    unsigned bh[4][4], bl[4][4];
#pragma unroll
    for (int db = 0; db < 4; db++) {
        unsigned ro = swaddr<SB>(d0 + db * 16 + lr, gB);
        ldsm4(bh[db], bH + ro);
        ldsm4(bl[db], bL + ro);
    }
#pragma unroll
    for (int nb = 0; nb < 2; nb++) {
        unsigned ra = swaddr<SA>(nr + nb * 16 + lr, gA);
        unsigned ah[4], al[4];
        ldsm4(ah, aH + ra);
        ldsm4(al, aL + ra);
#pragma unroll
        for (int db = 0; db < 4; db++) {
#pragma unroll
            for (int g = 0; g < 2; g++) {
                float* a4 = acc[nb][db * 2 + g];
                mma_bf16(a4, ah[0], ah[1], ah[2], ah[3], bh[db][g], bh[db][g + 2]);
                mma_bf16(a4, ah[0], ah[1], ah[2], ah[3], bl[db][g], bl[db][g + 2]);
                mma_bf16(a4, al[0], al[1], al[2], al[3], bh[db][g], bh[db][g + 2]);
            }
        }
    }
}

// ---------------- kernel 0: fused prep (transpose | cvt_w | init+q | L2 warm) ----------------
#define SMEM_PREP (DD * DD * 4 + KK * (DD + 1) * 4)
__global__ __launch_bounds__(256) void k_prep(
    const float* __restrict__ W_ih, const float* __restrict__ W_hh,
    const float* __restrict__ Wp, const float* __restrict__ Wk, const float* __restrict__ Wv,
    const float* __restrict__ mu, const float* __restrict__ lsig,
    const float* __restrict__ noise,
    const float* __restrict__ Wq, const float* __restrict__ bq,
    const float* __restrict__ gsl, const float* __restrict__ bsl,
    const float* __restrict__ W1, const float* __restrict__ W2) {
    extern __shared__ float smf[];
    __shared__ float ta[32][33];
    __shared__ float tb[32][33];
    int blk = blockIdx.x;
    int t = threadIdx.x;
    int tx = t & 31, ty = t >> 5;

    if (blk < 48) {
        int bx = blk % 12, by = blk / 12;
        int o0 = bx * 32, j0 = by * 32;
#pragma unroll
        for (int i = 0; i < 4; i++) {
            int o = o0 + ty + 8 * i;
            ta[ty + 8 * i][tx] = W_ih[(size_t)o * DD + j0 + tx];
            tb[ty + 8 * i][tx] = W_hh[(size_t)o * DD + j0 + tx];
        }
        __syncthreads();
#pragma unroll
        for (int i = 0; i < 4; i++) {
            int j = j0 + ty + 8 * i;
            g_wihT[(size_t)j * 384 + o0 + tx] = ta[tx][ty + 8 * i];
            g_whhT[(size_t)j * 384 + o0 + tx] = tb[tx][ty + 8 * i];
        }
    } else if (blk < 240) {
        int idx = blk - 48;
        int z = idx / 64, rem = idx % 64;
        int c0 = (rem % 16) * 32, d0 = (rem / 16) * 32;
        int Cdim = z == 0 ? CC : DD;
        if (c0 >= Cdim) return;
        const float* src = z == 0 ? Wp : (z == 1 ? Wk : Wv);
        __nv_bfloat16* dsth = z == 0 ? g_Wph : (z == 1 ? g_Wkh : g_Wvh);
        __nv_bfloat16* dstl = z == 0 ? g_Wpl : (z == 1 ? g_Wkl : g_Wvl);
#pragma unroll
        for (int i = 0; i < 4; i++)
            ta[ty + 8 * i][tx] = src[(size_t)(c0 + ty + 8 * i) * DD + d0 + tx];
        __syncthreads();
#pragma unroll
        for (int i = 0; i < 4; i++) {
            int d = d0 + ty + 8 * i;
            float f = ta[tx][ty + 8 * i];
            __nv_bfloat16 h = __float2bfloat16(f);
            __nv_bfloat16 l = __float2bfloat16(f - __bfloat162float(h));
            dsth[(size_t)d * Cdim + c0 + tx] = h;
            dstl[(size_t)d * Cdim + c0 + tx] = l;
        }
    } else if (blk < 304) {
        int b = blk - 240;
        float* Wqs = smf;
        float (*sl)[DD + 1] = (float (*)[DD + 1])(smf + DD * DD);
        const float SCALE = 0.08838834764831845f;
#pragma unroll
        for (int i = 0; i < 16; i++)
            ((float4*)Wqs)[t + i * 256] = ((const float4*)Wq)[t + i * 256];
        for (int i = t; i < KK * DD; i += 256) {
            float v = mu[i] + __expf(lsig[i]) * noise[(size_t)b * KK * DD + i];
            g_slots[(size_t)b * KK * DD + i] = v;
            sl[i >> 7][i & 127] = v;
        }
        __syncthreads();
        {
            int row = ty;
            float s = 0.f, s2 = 0.f, vr[4];
#pragma unroll
            for (int i = 0; i < 4; i++) {
                float val = sl[row][tx * 4 + i];
                vr[i] = val; s += val; s2 += val * val;
            }
#pragma unroll
            for (int off = 16; off; off >>= 1) {
                s += __shfl_xor_sync(0xffffffffu, s, off);
                s2 += __shfl_xor_sync(0xffffffffu, s2, off);
            }
            float m = s * (1.0f / 128.0f);
            float var = s2 * (1.0f / 128.0f) - m * m;
            float inv = rsqrtf(var + 1e-5f);
#pragma unroll
            for (int i = 0; i < 4; i++) {
                int d = tx * 4 + i;
                sl[row][d] = (vr[i] - m) * inv * gsl[d] + bsl[d];
            }
        }
        __syncthreads();
        int d = t & 127, rh = t >> 7;
        float acc[4] = {0.f, 0.f, 0.f, 0.f};
#pragma unroll 8
        for (int j = 0; j < DD; j++) {
            float w = Wqs[j * DD + d];
#pragma unroll
            for (int rr = 0; rr < 4; rr++) acc[rr] = fmaf(sl[rh * 4 + rr][j], w, acc[rr]);
        }
#pragma unroll
        for (int rr = 0; rr < 4; rr++)
            g_q[((size_t)b * KK + rh * 4 + rr) * DD + d] = (acc[rr] + bq[d]) * SCALE;
    } else {
        // ---- L2 warm: mark update weights evict_last before proj streams ----
        const unsigned long long pol = mk_policy_el();
        int wi = (blk - 304) * 256 + t;   // 0..16383, each handles stride-16384 float4s
        float acc = 0.f;
        // g_wihT + g_whhT: 49152 floats each = 12288 float4 each
        for (int i = wi; i < 12288; i += 16384) {
            float4 a = ldg_pol4((const float*)g_wihT + i * 4, pol);
            float4 c = ldg_pol4((const float*)g_whhT + i * 4, pol);
            acc += a.x + c.x;
        }
        // W1: 32768 floats = 8192 float4 ; W2 same ; Wq 16384 floats = 4096 float4
        for (int i = wi; i < 8192; i += 16384) {
            float4 a = ldg_pol4(W1 + i * 4, pol);
            float4 c = ldg_pol4(W2 + i * 4, pol);
            acc += a.x + c.x;
        }
        for (int i = wi; i < 4096; i += 16384) {
            float4 a = ldg_pol4(Wq + i * 4, pol);
            acc += a.x;
        }
        if (acc == -1.25e30f) g_sink = acc;   // never true; defeats DCE
    }
}

// ---------------- kernel 1: proj + LN + k/v (x converted in-kernel) ----------------
#define XS_SZ 16896
#define SL_AH 16896
#define SL_AL 25088
#define SL_BH 33280
#define SL_BL 41472
#define SLOT 49664
#define AF_L 32768
#define BF_OFF 65536
#define BF_L 16384
#define SMEM_PROJ 99328

__device__ __forceinline__ void writeout(float (*acc)[8][4], float* out, const float* bias,
                                         int nr, int d0, int lane) {
#pragma unroll
    for (int nb = 0; nb < 2; nb++)
#pragma unroll
        for (int u = 0; u < 8; u++) {
            int row = nr + nb * 16 + (lane >> 2);
            int dc = d0 + u * 8 + (lane & 3) * 2;
            *(float2*)(out + (size_t)row * DD + dc) =
                make_float2(acc[nb][u][0] + bias[dc], acc[nb][u][1] + bias[dc + 1]);
            *(float2*)(out + (size_t)(row + 8) * DD + dc) =
                make_float2(acc[nb][u][2] + bias[dc], acc[nb][u][3] + bias[dc + 1]);
        }
}

__global__ __launch_bounds__(256, 2) void k_proj(
    const float* __restrict__ x,
    const float* __restrict__ bp,
    const float* __restrict__ gin, const float* __restrict__ bin,
    const float* __restrict__ bk, const float* __restrict__ bv) {
    extern __shared__ char sm[];
    __shared__ float bp_s[DD], gin_s[DD], bin_s[DD], bk_s[DD], bv_s[DD];
    __shared__ float mean_s[128], istd_s[128];
    __shared__ float ps[2][128], ps2[2][128];

    const int t = threadIdx.x, lane = t & 31, wid = t >> 5;
    const int warpX = wid >> 2, warpY = wid & 3;
    const int d0 = warpX * 64, nr = warpY * 32;
    const int b = blockIdx.y, n0 = blockIdx.x * 128;
    const unsigned smb = smem_u32(sm);

    if (t < DD) {
        bp_s[t] = bp[t]; gin_s[t] = gin[t]; bin_s[t] = bin[t];
        bk_s[t] = bk[t]; bv_s[t] = bv[t];
    }

    const float* xb = x + (size_t)b * CC * NN + n0;

    float acc[2][8][4];
#pragma unroll
    for (int nb = 0; nb < 2; nb++)
#pragma unroll
        for (int u = 0; u < 8; u++)
#pragma unroll
            for (int j = 0; j < 4; j++) acc[nb][u][j] = 0.f;

    auto stage1 = [&](int c, int sel) {
        unsigned base = smb + sel * SLOT;
        int c0 = c * 32;
#pragma unroll
        for (int it = 0; it < 4; it++) {
            int idx = t + it * 256;
            int row = idx >> 5, g = idx & 31;
            CPA16(base + row * 528 + g * 16, xb + (size_t)(c0 + row) * NN + g * 4);
        }
#pragma unroll
        for (int it = 0; it < 2; it++) {
            int idx = t + it * 256;
            int row = idx >> 2, g = idx & 3;
            unsigned so = swaddr<64>(row, g);
            size_t go = (size_t)row * CC + c0 + g * 8;
            CPA16(base + SL_BH + so, g_Wph + go);
            CPA16(base + SL_BL + so, g_Wpl + go);
        }
        CPA_COMMIT();
    };
    auto convert1 = [&](int sel) {
        char* sb = sm + sel * SLOT;
#pragma unroll
        for (int it = 0; it < 8; it++) {
            int idx = t + it * 256;
            int n = idx & 127, p = idx >> 7;
            float f0 = *(const float*)(sb + (2 * p) * 528 + n * 4);
            float f1 = *(const float*)(sb + (2 * p + 1) * 528 + n * 4);
            unsigned vh, vl; split2(f0, f1, vh, vl);
            unsigned off = swaddr<64>(n, p >> 2) + (p & 3) * 4;
            *(unsigned*)(sb + SL_AH + off) = vh;
            *(unsigned*)(sb + SL_AL + off) = vl;
        }
    };
    auto stageB = [&](const __nv_bfloat16* Wh, const __nv_bfloat16* Wl, int j0) {
#pragma unroll
        for (int it = 0; it < 4; it++) {
            int idx = t + it * 256;
            int row = idx >> 3, g = idx & 7;
            unsigned so = swaddr<128>(row, g);
            size_t go = (size_t)row * DD + j0 + g * 8;
            CPA16(smb + BF_OFF + so, Wh + go);
            CPA16(smb + BF_OFF + BF_L + so, Wl + go);
        }
        CPA_COMMIT();
    };

    // ---- phase 1 ----
    stage1(0, 0);
    stage1(1, 1);
#pragma unroll 1
    for (int c = 0; c < 16; c++) {
        CPA_WAIT(1);
        __syncthreads();
        int sel = c & 1;
        convert1(sel);
        __syncthreads();
        unsigned base = smb + sel * SLOT;
        mma_k16t<64, 64>(acc, base + SL_AH, base + SL_AL, base + SL_BH, base + SL_BL,
                         nr, d0, lane, 0, 0);
        mma_k16t<64, 64>(acc, base + SL_AH, base + SL_AL, base + SL_BH, base + SL_BL,
                         nr, d0, lane, 16, 16);
        __syncthreads();
        if (c + 2 < 16) stage1(c + 2, sel);
        else CPA_COMMIT();
    }
    stageB(g_Wkh, g_Wkl, 0);

    // ---- LN from accumulators ----
    {
        float rs[4] = {0.f, 0.f, 0.f, 0.f}, rs2[4] = {0.f, 0.f, 0.f, 0.f};
#pragma unroll
        for (int nb = 0; nb < 2; nb++)
#pragma unroll
            for (int u = 0; u < 8; u++) {
                int dc = d0 + u * 8 + (lane & 3) * 2;
                float v0 = acc[nb][u][0] + bp_s[dc];
                float v1 = acc[nb][u][1] + bp_s[dc + 1];
                float v2 = acc[nb][u][2] + bp_s[dc];
                float v3 = acc[nb][u][3] + bp_s[dc + 1];
                rs[nb * 2] += v0 + v1;       rs2[nb * 2] += v0 * v0 + v1 * v1;
                rs[nb * 2 + 1] += v2 + v3;   rs2[nb * 2 + 1] += v2 * v2 + v3 * v3;
            }
#pragma unroll
        for (int off = 1; off <= 2; off <<= 1)
#pragma unroll
            for (int i = 0; i < 4; i++) {
                rs[i] += __shfl_xor_sync(0xffffffffu, rs[i], off);
                rs2[i] += __shfl_xor_sync(0xffffffffu, rs2[i], off);
            }
        if ((lane & 3) == 0) {
#pragma unroll
            for (int i = 0; i < 4; i++) {
                int row = nr + (i >> 1) * 16 + (i & 1) * 8 + (lane >> 2);
                ps[warpX][row] = rs[i];
                ps2[warpX][row] = rs2[i];
            }
        }
    }
    __syncthreads();
    if (t < 128) {
        float s = ps[0][t] + ps[1][t];
        float s2 = ps2[0][t] + ps2[1][t];
        float m = s * (1.0f / 128.0f);
        float var = s2 * (1.0f / 128.0f) - m * m;
        mean_s[t] = m;
        istd_s[t] = rsqrtf(var + 1e-5f);
    }
    __syncthreads();

    // ---- write LN output as bf16 hi/lo into A-full ----
#pragma unroll
    for (int nb = 0; nb < 2; nb++)
#pragma unroll
        for (int u = 0; u < 8; u++) {
            int dc = d0 + u * 8 + (lane & 3) * 2;
            int r0 = nr + nb * 16 + (lane >> 2), r1 = r0 + 8;
            float m0 = mean_s[r0], i0 = istd_s[r0];
            float m1 = mean_s[r1], i1 = istd_s[r1];
            float f0 = (acc[nb][u][0] + bp_s[dc] - m0) * i0 * gin_s[dc] + bin_s[dc];
            float f1 = (acc[nb][u][1] + bp_s[dc + 1] - m0) * i0 * gin_s[dc + 1] + bin_s[dc + 1];
            float f2 = (acc[nb][u][2] + bp_s[dc] - m1) * i1 * gin_s[dc] + bin_s[dc];
            float f3 = (acc[nb][u][3] + bp_s[dc + 1] - m1) * i1 * gin_s[dc + 1] + bin_s[dc + 1];
            unsigned vh, vl;
            unsigned o0 = swaddr<256>(r0, dc >> 3) + (dc & 7) * 2;
            split2(f0, f1, vh, vl);
            *(unsigned*)(sm + o0) = vh;
            *(unsigned*)(sm + AF_L + o0) = vl;
            unsigned o1 = swaddr<256>(r1, dc >> 3) + (dc & 7) * 2;
            split2(f2, f3, vh, vl);
            *(unsigned*)(sm + o1) = vh;
            *(unsigned*)(sm + AF_L + o1) = vl;
        }
    __syncthreads();

    // ---- phases 2/3 ----
    unsigned aH = smb, aL = smb + AF_L, bH = smb + BF_OFF, bL = smb + BF_OFF + BF_L;
    float acc2[2][8][4];
#pragma unroll
    for (int nb = 0; nb < 2; nb++)
#pragma unroll
        for (int u = 0; u < 8; u++)
#pragma unroll
            for (int j = 0; j < 4; j++) acc2[nb][u][j] = 0.f;
    CPA_WAIT(0); __syncthreads();
#pragma unroll
    for (int kk = 0; kk < 64; kk += 16)
        mma_k16t<256, 128>(acc2, aH, aL, bH, bL, nr, d0, lane, kk, kk);
    __syncthreads();
    stageB(g_Wkh, g_Wkl, 64);
    CPA_WAIT(0); __syncthreads();
#pragma unroll
    for (int kk = 0; kk < 64; kk += 16)
        mma_k16t<256, 128>(acc2, aH, aL, bH, bL, nr, d0, lane, 64 + kk, kk);
    __syncthreads();
    stageB(g_Wvh, g_Wvl, 0);
    writeout(acc2, g_k + ((size_t)b * NN + n0) * DD, bk_s, nr, d0, lane);
#pragma unroll
    for (int nb = 0; nb < 2; nb++)
#pragma unroll
        for (int u = 0; u < 8; u++)
#pragma unroll
            for (int j = 0; j < 4; j++) acc2[nb][u][j] = 0.f;
    CPA_WAIT(0); __syncthreads();
#pragma unroll
    for (int kk = 0; kk < 64; kk += 16)
        mma_k16t<256, 128>(acc2, aH, aL, bH, bL, nr, d0, lane, kk, kk);
    __syncthreads();
    stageB(g_Wvh, g_Wvl, 64);
    CPA_WAIT(0); __syncthreads();
#pragma unroll
    for (int kk = 0; kk < 64; kk += 16)
        mma_k16t<256, 128>(acc2, aH, aL, bH, bL, nr, d0, lane, 64 + kk, kk);
    writeout(acc2, g_v + ((size_t)b * NN + n0) * DD, bv_s, nr, d0, lane);
}

// ---------------- kernel 2: attention (k/v streamed with evict_first) ----------------
__global__ __launch_bounds__(256) void k_attn(float* __restrict__ attn_out, int write_attn) {
    __shared__ float updp[8][KK * DD];
    __shared__ float asums[8][KK];
    __shared__ float atile[8][KK][16];

    int b = blockIdx.y, split = blockIdx.x;
    int t = threadIdx.x, lane = t & 31, w = t >> 5;
    int n0 = split * (NN / NSPLIT);
    int nb = n0 + w * 16;
    const unsigned long long pol = mk_policy_ef();

    const float* qp = g_q + (size_t)b * KK * DD + lane * 4;
    float qreg[KK][4];
#pragma unroll
    for (int s = 0; s < KK; s++) {
        float4 qv = *(const float4*)(qp + s * DD);
        qreg[s][0] = qv.x; qreg[s][1] = qv.y; qreg[s][2] = qv.z; qreg[s][3] = qv.w;
    }
    float upd[KK][4];
    float asum[KK];
#pragma unroll
    for (int s = 0; s < KK; s++) {
        asum[s] = 0.f;
#pragma unroll
        for (int j = 0; j < 4; j++) upd[s][j] = 0.f;
    }

    const float* kb = g_k + ((size_t)b * NN + nb) * DD + lane * 4;
    const float* vb = g_v + ((size_t)b * NN + nb) * DD + lane * 4;
    float4 kc = ldg_pol4(kb, pol);
    float4 vc = ldg_pol4(vb, pol);

#pragma unroll 4
    for (int i = 0; i < 16; i++) {
        float4 kn = kc, vn = vc;
        if (i < 15) {
            kn = ldg_pol4(kb + (i + 1) * DD, pol);
            vn = ldg_pol4(vb + (i + 1) * DD, pol);
        }
        float lg[KK];
#pragma unroll
        for (int s = 0; s < KK; s++)
            lg[s] = qreg[s][0] * kc.x + qreg[s][1] * kc.y + qreg[s][2] * kc.z + qreg[s][3] * kc.w;
#pragma unroll
        for (int off = 16; off; off >>= 1)
#pragma unroll
            for (int s = 0; s < KK; s++) lg[s] += __shfl_xor_sync(0xffffffffu, lg[s], off);
        float mx = lg[0];
#pragma unroll
        for (int s = 1; s < KK; s++) mx = fmaxf(mx, lg[s]);
        float ssum = 0.f;
#pragma unroll
        for (int s = 0; s < KK; s++) { lg[s] = __expf(lg[s] - mx); ssum += lg[s]; }
        float inv = 1.0f / ssum;
#pragma unroll
        for (int s = 0; s < KK; s++) {
            lg[s] *= inv;
            asum[s] += lg[s];
            upd[s][0] = fmaf(lg[s], vc.x, upd[s][0]);
            upd[s][1] = fmaf(lg[s], vc.y, upd[s][1]);
            upd[s][2] = fmaf(lg[s], vc.z, upd[s][2]);
            upd[s][3] = fmaf(lg[s], vc.w, upd[s][3]);
        }
        if (write_attn && lane < 8) {
            float av = lane == 0 ? lg[0] : lane == 1 ? lg[1] : lane == 2 ? lg[2] :
                       lane == 3 ? lg[3] : lane == 4 ? lg[4] : lane == 5 ? lg[5] :
                       lane == 6 ? lg[6] : lg[7];
            atile[w][lane][i] = av;
        }
        kc = kn; vc = vn;
    }
#pragma unroll
    for (int s = 0; s < KK; s++)
        *(float4*)&updp[w][s * DD + lane * 4] =
            make_float4(upd[s][0], upd[s][1], upd[s][2], upd[s][3]);
    if (lane == 0) {
#pragma unroll
        for (int s = 0; s < KK; s++) asums[w][s] = asum[s];
    }
    __syncthreads();
    for (int idx = t; idx < KK * DD; idx += 256) {
        float s = 0.f;
#pragma unroll
        for (int ww = 0; ww < 8; ww++) s += updp[ww][idx];
        g_upd[((size_t)b * NSPLIT + split) * KK * DD + idx] = s;
    }
    if (t < KK) {
        float s = 0.f;
#pragma unroll
        for (int ww = 0; ww < 8; ww++) s += asums[ww][t];
        g_asum[((size_t)b * NSPLIT + split) * KK + t] = s;
    }
    if (write_attn) {
        for (int idx = t; idx < KK * (NN / NSPLIT); idx += 256) {
            int s = idx >> 7, n = idx & 127;
            attn_out[((size_t)b * KK + s) * NN + n0 + n] = atile[n >> 4][s][n & 15];
        }
    }
}

// ---------------- kernel 3: updates + GRU + MLP + next-iter q (1024 thr, K-split) ----------------
#define UPD_US 0
#define UPD_HS 1024
#define UPD_PGX 2048
#define UPD_PGH 8192
#define UPD_AST 14336
#define SMEM_UPD ((14336 + 16) * 4)
__global__ __launch_bounds__(1024) void k_update(
    const float* __restrict__ b_ih, const float* __restrict__ b_hh,
    const float* __restrict__ W1, const float* __restrict__ b1,
    const float* __restrict__ W2, const float* __restrict__ b2,
    const float* __restrict__ gm, const float* __restrict__ bm,
    const float* __restrict__ Wq, const float* __restrict__ bq,
    const float* __restrict__ gsl, const float* __restrict__ bsl,
    float* __restrict__ slots_out, int last) {
    extern __shared__ float su[];
    float* us = su + UPD_US;
    float* hs = su + UPD_HS;
    float* pgx = su + UPD_PGX;
    float* pgh = su + UPD_PGH;
    float* astot = su + UPD_AST;
    float* ns = us;
    float* lns = hs;
    float* h1s = pgx;
    float* fs = hs;
    float* lnq = pgh;

    int b = blockIdx.x;
    int t = threadIdx.x;
    int wid = t >> 5, lane = t & 31;

    if (t < KK) {
        float s = 0.f;
        for (int sp = 0; sp < NSPLIT; sp++) s += g_asum[((size_t)b * NSPLIT + sp) * KK + t];
        astot[t] = s + 1e-8f;
    }
    hs[t] = g_slots[(size_t)b * KK * DD + t];
    __syncthreads();
    {
        float s = 0.f;
#pragma unroll
        for (int sp = 0; sp < NSPLIT; sp++)
            s += g_upd[((size_t)b * NSPLIT + sp) * KK * DD + t];
        us[t] = s / astot[t >> 7];
    }
    __syncthreads();

    if (t < 768) {
        int o = t % 384, jh = t / 384;
        float accx[KK], acch[KK];
#pragma unroll
        for (int r = 0; r < KK; r++) { accx[r] = 0.f; acch[r] = 0.f; }
        const float* wi = g_wihT + (size_t)(jh * 64) * 384 + o;
        const float* wh = g_whhT + (size_t)(jh * 64) * 384 + o;
        int j0 = jh * 64;
#pragma unroll 8
        for (int j2 = 0; j2 < 64; j2++) {
            float wa = wi[(size_t)j2 * 384];
            float wb = wh[(size_t)j2 * 384];
            int j = j0 + j2;
#pragma unroll
            for (int r = 0; r < KK; r++) {
                accx[r] = fmaf(us[r * DD + j], wa, accx[r]);
                acch[r] = fmaf(hs[r * DD + j], wb, acch[r]);
            }
        }
#pragma unroll
        for (int r = 0; r < KK; r++) {
            pgx[jh * 3072 + r * 384 + o] = accx[r];
            pgh[jh * 3072 + r * 384 + o] = acch[r];
        }
    }
    __syncthreads();

    {
        int r = t >> 7, d = t & 127;
        float xr = pgx[r * 384 + d] + pgx[3072 + r * 384 + d] + b_ih[d];
        float hr = pgh[r * 384 + d] + pgh[3072 + r * 384 + d] + b_hh[d];
        float xz = pgx[r * 384 + 128 + d] + pgx[3072 + r * 384 + 128 + d] + b_ih[128 + d];
        float hz = pgh[r * 384 + 128 + d] + pgh[3072 + r * 384 + 128 + d] + b_hh[128 + d];
        float xn = pgx[r * 384 + 256 + d] + pgx[3072 + r * 384 + 256 + d] + b_ih[256 + d];
        float hn = pgh[r * 384 + 256 + d] + pgh[3072 + r * 384 + 256 + d] + b_hh[256 + d];
        float rg = sigf(xr + hr);
        float zg = sigf(xz + hz);
        float ng = tanhf(xn + rg * hn);
        float nsv = (1.0f - zg) * ng + zg * hs[t];
        __syncthreads();
        ns[t] = nsv;
    }
    __syncthreads();

    if (wid < KK) {
        int row = wid;
        float s = 0.f, s2 = 0.f, vr[4];
#pragma unroll
        for (int i = 0; i < 4; i++) {
            float val = ns[row * DD + lane * 4 + i];
            vr[i] = val; s += val; s2 += val * val;
        }
#pragma unroll
        for (int off = 16; off; off >>= 1) {
            s += __shfl_xor_sync(0xffffffffu, s, off);
            s2 += __shfl_xor_sync(0xffffffffu, s2, off);
        }
        float m = s * (1.0f / 128.0f);
        float var = s2 * (1.0f / 128.0f) - m * m;
        float inv = rsqrtf(var + 1e-5f);
#pragma unroll
        for (int i = 0; i < 4; i++) {
            int d = lane * 4 + i;
            lns[row * DD + d] = (vr[i] - m) * inv * gm[d] + bm[d];
        }
    }
    __syncthreads();

    if (t < 512) {
        int o = t & 255, jh = t >> 8;
        float acc[KK];
#pragma unroll
        for (int r = 0; r < KK; r++) acc[r] = 0.f;
        int j0 = jh * 64;
#pragma unroll 8
        for (int j2 = 0; j2 < 64; j2++) {
            float w = W1[(size_t)(j0 + j2) * 256 + o];
#pragma unroll
            for (int r = 0; r < KK; r++) acc[r] = fmaf(lns[r * DD + j0 + j2], w, acc[r]);
        }
#pragma unroll
        for (int r = 0; r < KK; r++) pgh[jh * 2048 + r * 256 + o] = acc[r];
    }
    __syncthreads();

#pragma unroll
    for (int i2 = t; i2 < 2048; i2 += 1024) {
        int o = i2 & 255;
        h1s[i2] = geluf(pgh[i2] + pgh[2048 + i2] + b1[o]);
    }
    __syncthreads();

    {
        int d = t & 127, seg = t >> 7;
        int rg = seg & 3, jh = seg >> 2;
        int j0 = jh * 128;
        float acc[2] = {0.f, 0.f};
#pragma unroll 8
        for (int j2 = 0; j2 < 128; j2++) {
            float w = W2[(size_t)(j0 + j2) * DD + d];
#pragma unroll
            for (int i = 0; i < 2; i++)
                acc[i] = fmaf(h1s[(rg * 2 + i) * 256 + j0 + j2], w, acc[i]);
        }
#pragma unroll
        for (int i = 0; i < 2; i++)
            pgh[jh * 1024 + (rg * 2 + i) * DD + d] = acc[i];
    }
    __syncthreads();

    {
        int d = t & 127;
        float val = ns[t] + pgh[t] + pgh[1024 + t] + b2[d];
        __syncthreads();
        g_slots[(size_t)b * KK * DD + t] = val;
        fs[t] = val;
        if (last) slots_out[(size_t)b * KK * DD + t] = val;
    }
    __syncthreads();

    if (!last) {
        const float SCALE = 0.08838834764831845f;
        if (wid < KK) {
            int row = wid;
            float s = 0.f, s2 = 0.f, vr[4];
#pragma unroll
            for (int i = 0; i < 4; i++) {
                float val = fs[row * DD + lane * 4 + i];
                vr[i] = val; s += val; s2 += val * val;
            }
#pragma unroll
            for (int off = 16; off; off >>= 1) {
                s += __shfl_xor_sync(0xffffffffu, s, off);
                s2 += __shfl_xor_sync(0xffffffffu, s2, off);
            }
            float m = s * (1.0f / 128.0f);
            float var = s2 * (1.0f / 128.0f) - m * m;
            float inv = rsqrtf(var + 1e-5f);
#pragma unroll
            for (int i = 0; i < 4; i++) {
                int d = lane * 4 + i;
                lnq[row * DD + d] = (vr[i] - m) * inv * gsl[d] + bsl[d];
            }
        }
        __syncthreads();
        {
            int d = t & 127, seg = t >> 7;
            int rg = seg & 3, jh = seg >> 2;
            int j0 = jh * 64;
            float acc[2] = {0.f, 0.f};
#pragma unroll 8
            for (int j2 = 0; j2 < 64; j2++) {
                float w = Wq[(size_t)(j0 + j2) * DD + d];
#pragma unroll
                for (int i = 0; i < 2; i++)
                    acc[i] = fmaf(lnq[(rg * 2 + i) * DD + j0 + j2], w, acc[i]);
            }
#pragma unroll
            for (int i = 0; i < 2; i++)
                pgx[jh * 1024 + (rg * 2 + i) * DD + d] = acc[i];
        }
        __syncthreads();
        {
            int d = t & 127;
            g_q[(size_t)b * KK * DD + t] = (pgx[t] + pgx[1024 + t] + bq[d]) * SCALE;
        }
    }
}

// ---------------- launcher ----------------
extern "C" void kernel_launch(void* const* d_in, const int* in_sizes, int n_in,
                              void* d_out, int out_size) {
    const float* x       = (const float*)d_in[0];
    const float* noise   = (const float*)d_in[1];
    const float* slot_mu = (const float*)d_in[2];
    const float* slot_ls = (const float*)d_in[3];
    const float* Wp   = (const float*)d_in[4];
    const float* bp   = (const float*)d_in[5];
    const float* gin  = (const float*)d_in[6];
    const float* bin  = (const float*)d_in[7];
    const float* Wq   = (const float*)d_in[8];
    const float* bq   = (const float*)d_in[9];
    const float* Wk   = (const float*)d_in[10];
    const float* bk   = (const float*)d_in[11];
    const float* Wv   = (const float*)d_in[12];
    const float* bv   = (const float*)d_in[13];
    const float* W_ih = (const float*)d_in[14];
    const float* W_hh = (const float*)d_in[15];
    const float* b_ih = (const float*)d_in[16];
    const float* b_hh = (const float*)d_in[17];
    const float* W1   = (const float*)d_in[18];
    const float* b1   = (const float*)d_in[19];
    const float* W2   = (const float*)d_in[20];
    const float* b2   = (const float*)d_in[21];
    const float* gsl  = (const float*)d_in[22];
    const float* bsl  = (const float*)d_in[23];
    const float* gm   = (const float*)d_in[24];
    const float* bm   = (const float*)d_in[25];

    float* out_slots = (float*)d_out;
    float* out_attn  = out_slots + BB * KK * DD;

    cudaFuncSetAttribute(k_proj, cudaFuncAttributeMaxDynamicSharedMemorySize, SMEM_PROJ);
    cudaFuncSetAttribute(k_prep, cudaFuncAttributeMaxDynamicSharedMemorySize, SMEM_PREP);
    cudaFuncSetAttribute(k_update, cudaFuncAttributeMaxDynamicSharedMemorySize, SMEM_UPD);

    // launches: prep(0), proj(1), attn(2), update(3) -> ncu slot 3 = first k_update
    k_prep<<<368, 256, SMEM_PREP>>>(W_ih, W_hh, Wp, Wk, Wv,
                                    slot_mu, slot_ls, noise, Wq, bq, gsl, bsl, W1, W2);
    k_proj<<<dim3(NN / 128, BB), 256, SMEM_PROJ>>>(x, bp, gin, bin, bk, bv);

    for (int it = 0; it < N_ITERS; it++) {
        int last = (it == N_ITERS - 1);
        k_attn<<<dim3(NSPLIT, BB), 256>>>(out_attn, last);
        k_update<<<BB, 1024, SMEM_UPD>>>(b_ih, b_hh, W1, b1, W2, b2, gm, bm,
                                         Wq, bq, gsl, bsl, out_slots, last);
    }
}